// round 1
// baseline (speedup 1.0000x reference)
#include <cuda_runtime.h>

#define EMBED 256
#define HEADS 8
#define HD    32
#define NTOK  2304
#define BATCH 4
#define HH    48
#define WW    48
#define KSCALE 0.17677669529663687f  /* 32^-0.5 */

#define GEMM_BM 64
#define GEMM_BN 64
#define GEMM_BK 16

// Scratch buffers (allocation-free rule: __device__ globals)
__device__ float g_q[BATCH * NTOK * EMBED];
__device__ float g_k[BATCH * NTOK * EMBED];
__device__ float g_v[BATCH * NTOK * EMBED];
__device__ float g_lepe[BATCH * NTOK * EMBED];
__device__ float g_att[BATCH * NTOK * EMBED];

// ---------------------------------------------------------------------------
// Generic fp32 GEMM body: C[m0:m0+64, n0:n0+64] = (A (+A2)) @ B + bias
// A: [M,256] row-major, B: [256,256] row-major, C stride 256.
// 256 threads, 4x4 microtile per thread, columns strided by 16 (conflict-free
// Bs reads + coalesced epilogue).
// ---------------------------------------------------------------------------
__device__ __forceinline__ void gemm_body(
    const float* __restrict__ A, const float* __restrict__ A2,
    const float* __restrict__ B, const float* __restrict__ bias,
    float* __restrict__ C, int m0, int n0)
{
    __shared__ float As[GEMM_BK][65];        // padded: reduce store conflicts
    __shared__ float Bs[GEMM_BK][GEMM_BN];

    const int tid = threadIdx.x;
    const int am  = tid >> 2;                // 0..63 : A row within tile
    const int ak  = (tid & 3) << 2;          // 0,4,8,12 : A k within tile
    const int bk  = tid >> 4;                // 0..15 : B row within tile
    const int bn  = (tid & 15) << 2;         // 0..60 : B col (float4)
    const int tm  = (tid >> 4) << 2;         // thread row base
    const int tc  = tid & 15;                // thread col lane (cols tc+16j)

    float acc[4][4] = {};

    for (int k0 = 0; k0 < EMBED; k0 += GEMM_BK) {
        float4 av = *(const float4*)&A[(size_t)(m0 + am) * EMBED + k0 + ak];
        if (A2) {
            float4 a2 = *(const float4*)&A2[(size_t)(m0 + am) * EMBED + k0 + ak];
            av.x += a2.x; av.y += a2.y; av.z += a2.z; av.w += a2.w;
        }
        float4 bv = *(const float4*)&B[(size_t)(k0 + bk) * EMBED + n0 + bn];

        As[ak + 0][am] = av.x;
        As[ak + 1][am] = av.y;
        As[ak + 2][am] = av.z;
        As[ak + 3][am] = av.w;
        *(float4*)&Bs[bk][bn] = bv;
        __syncthreads();

        #pragma unroll
        for (int kk = 0; kk < GEMM_BK; kk++) {
            float a[4], b[4];
            #pragma unroll
            for (int i = 0; i < 4; i++) a[i] = As[kk][tm + i];
            #pragma unroll
            for (int j = 0; j < 4; j++) b[j] = Bs[kk][tc + 16 * j];
            #pragma unroll
            for (int i = 0; i < 4; i++)
                #pragma unroll
                for (int j = 0; j < 4; j++)
                    acc[i][j] = fmaf(a[i], b[j], acc[i][j]);
        }
        __syncthreads();
    }

    #pragma unroll
    for (int i = 0; i < 4; i++)
        #pragma unroll
        for (int j = 0; j < 4; j++) {
            int col = n0 + tc + 16 * j;
            C[(size_t)(m0 + tm + i) * EMBED + col] = acc[i][j] + bias[col];
        }
}

// ---------------------------------------------------------------------------
// Fused QKV projection: one grid covering N=768 output columns (3 matrices).
// ---------------------------------------------------------------------------
__global__ void __launch_bounds__(256)
qkv_gemm(const float* __restrict__ x,
         const float* __restrict__ Wq, const float* __restrict__ bq,
         const float* __restrict__ Wk, const float* __restrict__ bk,
         const float* __restrict__ Wv, const float* __restrict__ bv)
{
    const int m0  = blockIdx.y * GEMM_BM;
    const int nb  = blockIdx.x;            // 0..11  (768 / 64)
    const int mat = nb >> 2;               // 0:q 1:k 2:v
    const int n0  = (nb & 3) * GEMM_BN;

    const float* W;
    const float* bias;
    float* out;
    if (mat == 0)      { W = Wq; bias = bq; out = g_q; }
    else if (mat == 1) { W = Wk; bias = bk; out = g_k; }
    else               { W = Wv; bias = bv; out = g_v; }

    gemm_body(x, nullptr, W, bias, out, m0, n0);
}

// ---------------------------------------------------------------------------
// RoPE on q and k (in place); k also gets the 1/sqrt(HD) scale (linear op, so
// order vs. rotation is irrelevant).
// ---------------------------------------------------------------------------
__global__ void __launch_bounds__(256)
rope_kernel(const float* __restrict__ sin_t, const float* __restrict__ cos_t)
{
    const int idx = blockIdx.x * blockDim.x + threadIdx.x;   // pair index
    if (idx >= BATCH * NTOK * (EMBED / 2)) return;
    const int row = idx >> 7;        // b*NTOK + pos
    const int c   = (idx & 127) << 1;
    const int dd  = c & (HD - 1);    // index within head
    const int pos = row % NTOK;      // y*48+x

    const float cs0 = cos_t[pos * HD + dd];
    const float sn0 = sin_t[pos * HD + dd];
    const float cs1 = cos_t[pos * HD + dd + 1];
    const float sn1 = sin_t[pos * HD + dd + 1];

    float2* qp = (float2*)&g_q[(size_t)row * EMBED + c];
    float2 qv = *qp;
    float2 qo;
    qo.x = qv.x * cs0 - qv.y * sn0;
    qo.y = qv.y * cs1 + qv.x * sn1;
    *qp = qo;

    float2* kp = (float2*)&g_k[(size_t)row * EMBED + c];
    float2 kv = *kp;
    float2 ko;
    ko.x = (kv.x * cs0 - kv.y * sn0) * KSCALE;
    ko.y = (kv.y * cs1 + kv.x * sn1) * KSCALE;
    *kp = ko;
}

// ---------------------------------------------------------------------------
// LePE: 5x5 depthwise conv over v (NHWC, pad 2). One block per (y, b) row;
// thread = channel; weights held in registers; x swept serially.
// ---------------------------------------------------------------------------
__global__ void __launch_bounds__(256)
lepe_kernel(const float* __restrict__ w, const float* __restrict__ bias)
{
    const int c = threadIdx.x;
    const int y = blockIdx.x;    // 0..47
    const int b = blockIdx.y;    // 0..3

    float wr[25];
    #pragma unroll
    for (int t = 0; t < 25; t++) wr[t] = w[t * EMBED + c];
    const float bv = bias[c];

    const float* vb = g_v + (size_t)b * NTOK * EMBED;
    float* ob = g_lepe + (size_t)(b * NTOK + y * WW) * EMBED;

    for (int x = 0; x < WW; x++) {
        float sum = bv;
        #pragma unroll
        for (int dy = 0; dy < 5; dy++) {
            const int yy = y + dy - 2;
            if (yy < 0 || yy >= HH) continue;
            #pragma unroll
            for (int dx = 0; dx < 5; dx++) {
                const int xx = x + dx - 2;
                if (xx < 0 || xx >= WW) continue;
                sum = fmaf(vb[(size_t)(yy * WW + xx) * EMBED + c],
                           wr[dy * 5 + dx], sum);
            }
        }
        ob[(size_t)x * EMBED + c] = sum;
    }
}

// ---------------------------------------------------------------------------
// Flash-style attention with additive mask bias + online softmax.
// Block = 32 queries (8 lanes each); loop over 72 key tiles of 32.
// Writes directly to [B, N, 256] layout (head-interleaved) for the out-proj.
// ---------------------------------------------------------------------------
__global__ void __launch_bounds__(256)
attn_kernel(const float* __restrict__ mask)
{
    __shared__ float q_s[32][40];   // stride 40: float4-aligned, bank-spread
    __shared__ float k_s[32][40];
    __shared__ float v_s[32][40];
    __shared__ float p_s[32][33];

    const int tid = threadIdx.x;
    const int b   = blockIdx.z;
    const int h   = blockIdx.y;
    const int q0  = blockIdx.x * 32;
    const int qi  = tid >> 3;       // query within tile (0..31)
    const int l8  = tid & 7;        // lane within query group
    const int d0  = l8 << 2;        // this lane's 4 dims / 4 key cols

    const float* Q  = g_q + ((size_t)(b * NTOK + q0)) * EMBED + h * HD;
    const float* K  = g_k + (size_t)b * NTOK * EMBED + h * HD;
    const float* V  = g_v + (size_t)b * NTOK * EMBED + h * HD;
    const float* Mp = mask + ((size_t)h * NTOK + q0) * NTOK;

    {
        float4 t = *(const float4*)&Q[(size_t)qi * EMBED + d0];
        q_s[qi][d0 + 0] = t.x; q_s[qi][d0 + 1] = t.y;
        q_s[qi][d0 + 2] = t.z; q_s[qi][d0 + 3] = t.w;
    }

    float m_run = -1e30f, l_run = 0.f;
    float4 acc = make_float4(0.f, 0.f, 0.f, 0.f);

    for (int k0 = 0; k0 < NTOK; k0 += 32) {
        // issue global loads early (row qi of the incoming K/V tile)
        float4 kt   = *(const float4*)&K[(size_t)(k0 + qi) * EMBED + d0];
        float4 vt   = *(const float4*)&V[(size_t)(k0 + qi) * EMBED + d0];
        float4 mrow = *(const float4*)&Mp[(size_t)qi * NTOK + k0 + d0];

        __syncthreads();   // previous tile's consumers done
        k_s[qi][d0 + 0] = kt.x; k_s[qi][d0 + 1] = kt.y;
        k_s[qi][d0 + 2] = kt.z; k_s[qi][d0 + 3] = kt.w;
        v_s[qi][d0 + 0] = vt.x; v_s[qi][d0 + 1] = vt.y;
        v_s[qi][d0 + 2] = vt.z; v_s[qi][d0 + 3] = vt.w;
        __syncthreads();

        // scores for keys kj = d0..d0+3 (mask bias folded in as init)
        float s0 = mrow.x, s1 = mrow.y, s2 = mrow.z, s3 = mrow.w;
        #pragma unroll
        for (int d4 = 0; d4 < HD; d4 += 4) {
            float4 qv  = *(const float4*)&q_s[qi][d4];
            float4 k0v = *(const float4*)&k_s[d0 + 0][d4];
            float4 k1v = *(const float4*)&k_s[d0 + 1][d4];
            float4 k2v = *(const float4*)&k_s[d0 + 2][d4];
            float4 k3v = *(const float4*)&k_s[d0 + 3][d4];
            s0 += qv.x * k0v.x + qv.y * k0v.y + qv.z * k0v.z + qv.w * k0v.w;
            s1 += qv.x * k1v.x + qv.y * k1v.y + qv.z * k1v.z + qv.w * k1v.w;
            s2 += qv.x * k2v.x + qv.y * k2v.y + qv.z * k2v.z + qv.w * k2v.w;
            s3 += qv.x * k3v.x + qv.y * k3v.y + qv.z * k3v.z + qv.w * k3v.w;
        }

        // online softmax update (8-lane query group reductions)
        float tmax = fmaxf(fmaxf(s0, s1), fmaxf(s2, s3));
        tmax = fmaxf(tmax, __shfl_xor_sync(0xffffffffu, tmax, 1));
        tmax = fmaxf(tmax, __shfl_xor_sync(0xffffffffu, tmax, 2));
        tmax = fmaxf(tmax, __shfl_xor_sync(0xffffffffu, tmax, 4));
        const float m_new = fmaxf(m_run, tmax);

        const float p0 = __expf(s0 - m_new);
        const float p1 = __expf(s1 - m_new);
        const float p2 = __expf(s2 - m_new);
        const float p3 = __expf(s3 - m_new);
        float ps = p0 + p1 + p2 + p3;
        ps += __shfl_xor_sync(0xffffffffu, ps, 1);
        ps += __shfl_xor_sync(0xffffffffu, ps, 2);
        ps += __shfl_xor_sync(0xffffffffu, ps, 4);

        const float alpha = __expf(m_run - m_new);
        l_run = l_run * alpha + ps;
        m_run = m_new;

        p_s[qi][d0 + 0] = p0; p_s[qi][d0 + 1] = p1;
        p_s[qi][d0 + 2] = p2; p_s[qi][d0 + 3] = p3;
        acc.x *= alpha; acc.y *= alpha; acc.z *= alpha; acc.w *= alpha;
        __syncwarp();

        #pragma unroll 8
        for (int kj = 0; kj < 32; kj++) {
            const float pv = p_s[qi][kj];
            float4 vv = *(const float4*)&v_s[kj][d0];
            acc.x = fmaf(pv, vv.x, acc.x);
            acc.y = fmaf(pv, vv.y, acc.y);
            acc.z = fmaf(pv, vv.z, acc.z);
            acc.w = fmaf(pv, vv.w, acc.w);
        }
        // p_s re-written only after the next block-wide __syncthreads
    }

    const float inv = 1.0f / l_run;
    float4 o = make_float4(acc.x * inv, acc.y * inv, acc.z * inv, acc.w * inv);
    *(float4*)&g_att[((size_t)(b * NTOK + q0 + qi)) * EMBED + h * HD + d0] = o;
}

// ---------------------------------------------------------------------------
// Output projection: out = (att + lepe) @ Wout + bout
// ---------------------------------------------------------------------------
__global__ void __launch_bounds__(256)
out_gemm(const float* __restrict__ Wout, const float* __restrict__ bout,
         float* __restrict__ out)
{
    gemm_body(g_att, g_lepe, Wout, bout, out,
              blockIdx.y * GEMM_BM, blockIdx.x * GEMM_BN);
}

// ---------------------------------------------------------------------------
extern "C" void kernel_launch(void* const* d_in, const int* in_sizes, int n_in,
                              void* d_out, int out_size)
{
    const float* x      = (const float*)d_in[0];
    const float* sin_t  = (const float*)d_in[1];
    const float* cos_t  = (const float*)d_in[2];
    const float* mask   = (const float*)d_in[3];
    const float* Wq     = (const float*)d_in[4];
    const float* bq     = (const float*)d_in[5];
    const float* Wk     = (const float*)d_in[6];
    const float* bk     = (const float*)d_in[7];
    const float* Wv     = (const float*)d_in[8];
    const float* bv     = (const float*)d_in[9];
    const float* lepe_w = (const float*)d_in[10];
    const float* lepe_b = (const float*)d_in[11];
    const float* Wout   = (const float*)d_in[12];
    const float* bout   = (const float*)d_in[13];
    float* out = (float*)d_out;

    const int M = BATCH * NTOK;   // 9216

    qkv_gemm<<<dim3(768 / GEMM_BN, M / GEMM_BM), 256>>>(x, Wq, bq, Wk, bk, Wv, bv);
    rope_kernel<<<(BATCH * NTOK * (EMBED / 2)) / 256, 256>>>(sin_t, cos_t);
    lepe_kernel<<<dim3(HH, BATCH), 256>>>(lepe_w, lepe_b);
    attn_kernel<<<dim3(NTOK / 32, HEADS, BATCH), 256>>>(mask);
    out_gemm<<<dim3(EMBED / GEMM_BN, M / GEMM_BM), 256>>>(Wout, bout, out);
}

// round 2
// speedup vs baseline: 6.5219x; 6.5219x over previous
#include <cuda_runtime.h>

#define EMBED 256
#define HEADS 8
#define HD    32
#define NTOK  2304
#define BATCH 4
#define HH    48
#define WW    48
#define KSCALE 0.17677669529663687f  /* 32^-0.5 */

#define GEMM_BM 64
#define GEMM_BN 64
#define GEMM_BK 16

// Attention tiling
#define TQ 64
#define TK 64
#define KSTR 68           // q_s/k_s row stride (words), d-major
#define VSTR 36           // v_s row stride (words)
#define PSTR 76           // p_s row stride (words), half-offset 36

// Scratch buffers (allocation-free rule: __device__ globals)
__device__ float g_q[BATCH * NTOK * EMBED];
__device__ float g_k[BATCH * NTOK * EMBED];
__device__ float g_v[BATCH * NTOK * EMBED];
__device__ float g_lepe[BATCH * NTOK * EMBED];
__device__ float g_att[BATCH * NTOK * EMBED];

// ---------------------------------------------------------------------------
// Generic fp32 GEMM body (unchanged from R1)
// ---------------------------------------------------------------------------
__device__ __forceinline__ void gemm_body(
    const float* __restrict__ A, const float* __restrict__ A2,
    const float* __restrict__ B, const float* __restrict__ bias,
    float* __restrict__ C, int m0, int n0)
{
    __shared__ float As[GEMM_BK][65];
    __shared__ float Bs[GEMM_BK][GEMM_BN];

    const int tid = threadIdx.x;
    const int am  = tid >> 2;
    const int ak  = (tid & 3) << 2;
    const int bk  = tid >> 4;
    const int bn  = (tid & 15) << 2;
    const int tm  = (tid >> 4) << 2;
    const int tc  = tid & 15;

    float acc[4][4] = {};

    for (int k0 = 0; k0 < EMBED; k0 += GEMM_BK) {
        float4 av = *(const float4*)&A[(size_t)(m0 + am) * EMBED + k0 + ak];
        if (A2) {
            float4 a2 = *(const float4*)&A2[(size_t)(m0 + am) * EMBED + k0 + ak];
            av.x += a2.x; av.y += a2.y; av.z += a2.z; av.w += a2.w;
        }
        float4 bv = *(const float4*)&B[(size_t)(k0 + bk) * EMBED + n0 + bn];

        As[ak + 0][am] = av.x;
        As[ak + 1][am] = av.y;
        As[ak + 2][am] = av.z;
        As[ak + 3][am] = av.w;
        *(float4*)&Bs[bk][bn] = bv;
        __syncthreads();

        #pragma unroll
        for (int kk = 0; kk < GEMM_BK; kk++) {
            float a[4], b[4];
            #pragma unroll
            for (int i = 0; i < 4; i++) a[i] = As[kk][tm + i];
            #pragma unroll
            for (int j = 0; j < 4; j++) b[j] = Bs[kk][tc + 16 * j];
            #pragma unroll
            for (int i = 0; i < 4; i++)
                #pragma unroll
                for (int j = 0; j < 4; j++)
                    acc[i][j] = fmaf(a[i], b[j], acc[i][j]);
        }
        __syncthreads();
    }

    #pragma unroll
    for (int i = 0; i < 4; i++)
        #pragma unroll
        for (int j = 0; j < 4; j++) {
            int col = n0 + tc + 16 * j;
            C[(size_t)(m0 + tm + i) * EMBED + col] = acc[i][j] + bias[col];
        }
}

__global__ void __launch_bounds__(256)
qkv_gemm(const float* __restrict__ x,
         const float* __restrict__ Wq, const float* __restrict__ bq,
         const float* __restrict__ Wk, const float* __restrict__ bk,
         const float* __restrict__ Wv, const float* __restrict__ bv)
{
    const int m0  = blockIdx.y * GEMM_BM;
    const int nb  = blockIdx.x;
    const int mat = nb >> 2;
    const int n0  = (nb & 3) * GEMM_BN;

    const float* W;
    const float* bias;
    float* out;
    if (mat == 0)      { W = Wq; bias = bq; out = g_q; }
    else if (mat == 1) { W = Wk; bias = bk; out = g_k; }
    else               { W = Wv; bias = bv; out = g_v; }

    gemm_body(x, nullptr, W, bias, out, m0, n0);
}

__global__ void __launch_bounds__(256)
rope_kernel(const float* __restrict__ sin_t, const float* __restrict__ cos_t)
{
    const int idx = blockIdx.x * blockDim.x + threadIdx.x;
    if (idx >= BATCH * NTOK * (EMBED / 2)) return;
    const int row = idx >> 7;
    const int c   = (idx & 127) << 1;
    const int dd  = c & (HD - 1);
    const int pos = row % NTOK;

    const float cs0 = cos_t[pos * HD + dd];
    const float sn0 = sin_t[pos * HD + dd];
    const float cs1 = cos_t[pos * HD + dd + 1];
    const float sn1 = sin_t[pos * HD + dd + 1];

    float2* qp = (float2*)&g_q[(size_t)row * EMBED + c];
    float2 qv = *qp;
    float2 qo;
    qo.x = qv.x * cs0 - qv.y * sn0;
    qo.y = qv.y * cs1 + qv.x * sn1;
    *qp = qo;

    float2* kp = (float2*)&g_k[(size_t)row * EMBED + c];
    float2 kv = *kp;
    float2 ko;
    ko.x = (kv.x * cs0 - kv.y * sn0) * KSCALE;
    ko.y = (kv.y * cs1 + kv.x * sn1) * KSCALE;
    *kp = ko;
}

__global__ void __launch_bounds__(256)
lepe_kernel(const float* __restrict__ w, const float* __restrict__ bias)
{
    const int c = threadIdx.x;
    const int y = blockIdx.x;
    const int b = blockIdx.y;

    float wr[25];
    #pragma unroll
    for (int t = 0; t < 25; t++) wr[t] = w[t * EMBED + c];
    const float bv = bias[c];

    const float* vb = g_v + (size_t)b * NTOK * EMBED;
    float* ob = g_lepe + (size_t)(b * NTOK + y * WW) * EMBED;

    for (int x = 0; x < WW; x++) {
        float sum = bv;
        #pragma unroll
        for (int dy = 0; dy < 5; dy++) {
            const int yy = y + dy - 2;
            if (yy < 0 || yy >= HH) continue;
            #pragma unroll
            for (int dx = 0; dx < 5; dx++) {
                const int xx = x + dx - 2;
                if (xx < 0 || xx >= WW) continue;
                sum = fmaf(vb[(size_t)(yy * WW + xx) * EMBED + c],
                           wr[dy * 5 + dx], sum);
            }
        }
        ob[(size_t)x * EMBED + c] = sum;
    }
}

// ---------------------------------------------------------------------------
// Attention v2: 64q x 64k tiles, 4x4 register microtiles, d-major K/Q in
// shared, key-split PV with shfl combine. All shared float4 accesses laid out
// conflict-free (strides 68/36+halfpad/76+36).
// ---------------------------------------------------------------------------
__global__ void __launch_bounds__(256)
attn_kernel(const float* __restrict__ mask)
{
    __shared__ float q_s[32 * KSTR];          // [d][query]
    __shared__ float k_s[32 * KSTR];          // [d][key]
    __shared__ float v_s[64 * VSTR + 8];      // [key][d], +4w pad after key 31
    __shared__ float p_s[64 * PSTR];          // [query][key], half offset 36

    const int tid = threadIdx.x;
    const int b   = blockIdx.z;
    const int h   = blockIdx.y;
    const int q0  = blockIdx.x * TQ;

    const int ty   = tid >> 4;       // query group: queries ty*4 .. ty*4+3
    const int tx   = tid & 15;       // QK key group: keys tx*4 .. tx*4+3
    const int half = (tid >> 3) & 1; // PV key half
    const int dg   = tid & 7;        // PV dim group: dims dg*4 .. dg*4+3

    const int lr = tid >> 2;         // loader: row 0..63
    const int lc = (tid & 3) * 8;    // loader: d chunk base (0,8,16,24)

    const float* Qg = g_q + (size_t)(b * NTOK + q0) * EMBED + h * HD;
    const float* Kg = g_k + (size_t)b * NTOK * EMBED + h * HD;
    const float* Vg = g_v + (size_t)b * NTOK * EMBED + h * HD;
    const float* Mg = mask + ((size_t)h * NTOK + q0) * NTOK;

    // Load Q tile, transpose to [d][query]
    {
        float4 a = *(const float4*)&Qg[(size_t)lr * EMBED + lc];
        float4 c = *(const float4*)&Qg[(size_t)lr * EMBED + lc + 4];
        q_s[(lc + 0) * KSTR + lr] = a.x;
        q_s[(lc + 1) * KSTR + lr] = a.y;
        q_s[(lc + 2) * KSTR + lr] = a.z;
        q_s[(lc + 3) * KSTR + lr] = a.w;
        q_s[(lc + 4) * KSTR + lr] = c.x;
        q_s[(lc + 5) * KSTR + lr] = c.y;
        q_s[(lc + 6) * KSTR + lr] = c.z;
        q_s[(lc + 7) * KSTR + lr] = c.w;
    }

    float m_run[4], l_run[4];
    float acc[4][4] = {};
    #pragma unroll
    for (int i = 0; i < 4; i++) { m_run[i] = -1e30f; l_run[i] = 0.f; }

    for (int k0 = 0; k0 < NTOK; k0 += TK) {
        // ---- global loads to registers (before sync) ----
        float4 ka = *(const float4*)&Kg[(size_t)(k0 + lr) * EMBED + lc];
        float4 kb = *(const float4*)&Kg[(size_t)(k0 + lr) * EMBED + lc + 4];
        float4 va = *(const float4*)&Vg[(size_t)(k0 + lr) * EMBED + lc];
        float4 vb = *(const float4*)&Vg[(size_t)(k0 + lr) * EMBED + lc + 4];
        float4 m4[4];
        #pragma unroll
        for (int i = 0; i < 4; i++)
            m4[i] = *(const float4*)&Mg[(size_t)(ty * 4 + i) * NTOK + k0 + tx * 4];

        __syncthreads();   // prior tile fully consumed

        // K transposed to [d][key]
        k_s[(lc + 0) * KSTR + lr] = ka.x;
        k_s[(lc + 1) * KSTR + lr] = ka.y;
        k_s[(lc + 2) * KSTR + lr] = ka.z;
        k_s[(lc + 3) * KSTR + lr] = ka.w;
        k_s[(lc + 4) * KSTR + lr] = kb.x;
        k_s[(lc + 5) * KSTR + lr] = kb.y;
        k_s[(lc + 6) * KSTR + lr] = kb.z;
        k_s[(lc + 7) * KSTR + lr] = kb.w;
        // V row-major with half pad
        {
            const int vo = lr * VSTR + (lr >> 5) * 4;
            *(float4*)&v_s[vo + lc]     = va;
            *(float4*)&v_s[vo + lc + 4] = vb;
        }
        __syncthreads();

        // ---- QK^T: s[i][j], mask bias as init ----
        float s[4][4];
        #pragma unroll
        for (int i = 0; i < 4; i++) {
            s[i][0] = m4[i].x; s[i][1] = m4[i].y;
            s[i][2] = m4[i].z; s[i][3] = m4[i].w;
        }
        #pragma unroll 8
        for (int d = 0; d < HD; d++) {
            float4 qv = *(const float4*)&q_s[d * KSTR + ty * 4];
            float4 kv = *(const float4*)&k_s[d * KSTR + tx * 4];
            s[0][0] = fmaf(qv.x, kv.x, s[0][0]);
            s[0][1] = fmaf(qv.x, kv.y, s[0][1]);
            s[0][2] = fmaf(qv.x, kv.z, s[0][2]);
            s[0][3] = fmaf(qv.x, kv.w, s[0][3]);
            s[1][0] = fmaf(qv.y, kv.x, s[1][0]);
            s[1][1] = fmaf(qv.y, kv.y, s[1][1]);
            s[1][2] = fmaf(qv.y, kv.z, s[1][2]);
            s[1][3] = fmaf(qv.y, kv.w, s[1][3]);
            s[2][0] = fmaf(qv.z, kv.x, s[2][0]);
            s[2][1] = fmaf(qv.z, kv.y, s[2][1]);
            s[2][2] = fmaf(qv.z, kv.z, s[2][2]);
            s[2][3] = fmaf(qv.z, kv.w, s[2][3]);
            s[3][0] = fmaf(qv.w, kv.x, s[3][0]);
            s[3][1] = fmaf(qv.w, kv.y, s[3][1]);
            s[3][2] = fmaf(qv.w, kv.z, s[3][2]);
            s[3][3] = fmaf(qv.w, kv.w, s[3][3]);
        }

        // ---- online softmax (row reductions over 16 tx lanes) ----
        float alpha[4];
        #pragma unroll
        for (int i = 0; i < 4; i++) {
            float t = fmaxf(fmaxf(s[i][0], s[i][1]), fmaxf(s[i][2], s[i][3]));
            t = fmaxf(t, __shfl_xor_sync(0xffffffffu, t, 1));
            t = fmaxf(t, __shfl_xor_sync(0xffffffffu, t, 2));
            t = fmaxf(t, __shfl_xor_sync(0xffffffffu, t, 4));
            t = fmaxf(t, __shfl_xor_sync(0xffffffffu, t, 8));
            const float mn = fmaxf(m_run[i], t);
            alpha[i] = __expf(m_run[i] - mn);
            m_run[i] = mn;
            s[i][0] = __expf(s[i][0] - mn);
            s[i][1] = __expf(s[i][1] - mn);
            s[i][2] = __expf(s[i][2] - mn);
            s[i][3] = __expf(s[i][3] - mn);
            float ps = s[i][0] + s[i][1] + s[i][2] + s[i][3];
            ps += __shfl_xor_sync(0xffffffffu, ps, 1);
            ps += __shfl_xor_sync(0xffffffffu, ps, 2);
            ps += __shfl_xor_sync(0xffffffffu, ps, 4);
            ps += __shfl_xor_sync(0xffffffffu, ps, 8);
            l_run[i] = l_run[i] * alpha[i] + ps;
            // p store: [query][key], key col = half*36 + dg*4 (tx*4 remapped)
            *(float4*)&p_s[(ty * 4 + i) * PSTR + half * 36 + dg * 4] =
                make_float4(s[i][0], s[i][1], s[i][2], s[i][3]);
            acc[i][0] *= alpha[i]; acc[i][1] *= alpha[i];
            acc[i][2] *= alpha[i]; acc[i][3] *= alpha[i];
        }
        __syncwarp();   // p producers == consumers' half-warp

        // ---- PV: this thread: queries ty*4.., dims dg*4.., keys half*32.. ----
        #pragma unroll
        for (int kc = 0; kc < 8; kc++) {
            float4 p0 = *(const float4*)&p_s[(ty * 4 + 0) * PSTR + half * 36 + kc * 4];
            float4 p1 = *(const float4*)&p_s[(ty * 4 + 1) * PSTR + half * 36 + kc * 4];
            float4 p2 = *(const float4*)&p_s[(ty * 4 + 2) * PSTR + half * 36 + kc * 4];
            float4 p3 = *(const float4*)&p_s[(ty * 4 + 3) * PSTR + half * 36 + kc * 4];
            const int kr = half * 32 + kc * 4;
            const int vbase = kr * VSTR + half * 4 + dg * 4;
            float4 v0 = *(const float4*)&v_s[vbase];
            float4 v1 = *(const float4*)&v_s[vbase + VSTR];
            float4 v2 = *(const float4*)&v_s[vbase + 2 * VSTR];
            float4 v3 = *(const float4*)&v_s[vbase + 3 * VSTR];
            #define PV_ROW(i, pv)                                   \
                acc[i][0] = fmaf(pv.x, v0.x, acc[i][0]);            \
                acc[i][1] = fmaf(pv.x, v0.y, acc[i][1]);            \
                acc[i][2] = fmaf(pv.x, v0.z, acc[i][2]);            \
                acc[i][3] = fmaf(pv.x, v0.w, acc[i][3]);            \
                acc[i][0] = fmaf(pv.y, v1.x, acc[i][0]);            \
                acc[i][1] = fmaf(pv.y, v1.y, acc[i][1]);            \
                acc[i][2] = fmaf(pv.y, v1.z, acc[i][2]);            \
                acc[i][3] = fmaf(pv.y, v1.w, acc[i][3]);            \
                acc[i][0] = fmaf(pv.z, v2.x, acc[i][0]);            \
                acc[i][1] = fmaf(pv.z, v2.y, acc[i][1]);            \
                acc[i][2] = fmaf(pv.z, v2.z, acc[i][2]);            \
                acc[i][3] = fmaf(pv.z, v2.w, acc[i][3]);            \
                acc[i][0] = fmaf(pv.w, v3.x, acc[i][0]);            \
                acc[i][1] = fmaf(pv.w, v3.y, acc[i][1]);            \
                acc[i][2] = fmaf(pv.w, v3.z, acc[i][2]);            \
                acc[i][3] = fmaf(pv.w, v3.w, acc[i][3]);
            PV_ROW(0, p0)
            PV_ROW(1, p1)
            PV_ROW(2, p2)
            PV_ROW(3, p3)
            #undef PV_ROW
        }
    }

    // combine key halves (lane bit 3) and write
    #pragma unroll
    for (int i = 0; i < 4; i++) {
        acc[i][0] += __shfl_xor_sync(0xffffffffu, acc[i][0], 8);
        acc[i][1] += __shfl_xor_sync(0xffffffffu, acc[i][1], 8);
        acc[i][2] += __shfl_xor_sync(0xffffffffu, acc[i][2], 8);
        acc[i][3] += __shfl_xor_sync(0xffffffffu, acc[i][3], 8);
    }
    if (half == 0) {
        #pragma unroll
        for (int i = 0; i < 4; i++) {
            const float inv = 1.0f / l_run[i];
            float4 o = make_float4(acc[i][0] * inv, acc[i][1] * inv,
                                   acc[i][2] * inv, acc[i][3] * inv);
            *(float4*)&g_att[(size_t)(b * NTOK + q0 + ty * 4 + i) * EMBED
                             + h * HD + dg * 4] = o;
        }
    }
}

__global__ void __launch_bounds__(256)
out_gemm(const float* __restrict__ Wout, const float* __restrict__ bout,
         float* __restrict__ out)
{
    gemm_body(g_att, g_lepe, Wout, bout, out,
              blockIdx.y * GEMM_BM, blockIdx.x * GEMM_BN);
}

// ---------------------------------------------------------------------------
extern "C" void kernel_launch(void* const* d_in, const int* in_sizes, int n_in,
                              void* d_out, int out_size)
{
    const float* x      = (const float*)d_in[0];
    const float* sin_t  = (const float*)d_in[1];
    const float* cos_t  = (const float*)d_in[2];
    const float* mask   = (const float*)d_in[3];
    const float* Wq     = (const float*)d_in[4];
    const float* bq     = (const float*)d_in[5];
    const float* Wk     = (const float*)d_in[6];
    const float* bk     = (const float*)d_in[7];
    const float* Wv     = (const float*)d_in[8];
    const float* bv     = (const float*)d_in[9];
    const float* lepe_w = (const float*)d_in[10];
    const float* lepe_b = (const float*)d_in[11];
    const float* Wout   = (const float*)d_in[12];
    const float* bout   = (const float*)d_in[13];
    float* out = (float*)d_out;

    const int M = BATCH * NTOK;   // 9216

    qkv_gemm<<<dim3(768 / GEMM_BN, M / GEMM_BM), 256>>>(x, Wq, bq, Wk, bk, Wv, bv);
    rope_kernel<<<(BATCH * NTOK * (EMBED / 2)) / 256, 256>>>(sin_t, cos_t);
    lepe_kernel<<<dim3(HH, BATCH), 256>>>(lepe_w, lepe_b);
    attn_kernel<<<dim3(NTOK / TQ, HEADS, BATCH), 256>>>(mask);
    out_gemm<<<dim3(EMBED / GEMM_BN, M / GEMM_BM), 256>>>(Wout, bout, out);
}

// round 3
// speedup vs baseline: 8.6194x; 1.3216x over previous
#include <cuda_runtime.h>
#include <cstdint>

#define EMBED 256
#define HEADS 8
#define HD    32
#define NTOK  2304
#define BATCH 4
#define HH    48
#define WW    48
#define KSCALE 0.17677669529663687f  /* 32^-0.5 */

#define GEMM_BM 64
#define GEMM_BN 64
#define GEMM_BK 16

// Attention tiling (tensor-core version)
#define TQ 128            // 8 warps x 16 query rows
#define TK 64             // key tile
#define KVSTR 36          // k_s/v_s row stride in words

// Scratch buffers (allocation-free rule: __device__ globals)
__device__ float g_q[BATCH * NTOK * EMBED];
__device__ float g_k[BATCH * NTOK * EMBED];
__device__ float g_v[BATCH * NTOK * EMBED];
__device__ float g_lepe[BATCH * NTOK * EMBED];
__device__ float g_att[BATCH * NTOK * EMBED];

// ---------------------------------------------------------------------------
// TF32 helpers
// ---------------------------------------------------------------------------
__device__ __forceinline__ uint32_t f2tf32(float x) {
    uint32_t r;
    asm("cvt.rna.tf32.f32 %0, %1;" : "=r"(r) : "f"(x));
    return r;
}

__device__ __forceinline__ void mma_tf32(
    float& c0, float& c1, float& c2, float& c3,
    uint32_t a0, uint32_t a1, uint32_t a2, uint32_t a3,
    uint32_t b0, uint32_t b1)
{
    asm("mma.sync.aligned.m16n8k8.row.col.f32.tf32.tf32.f32 "
        "{%0,%1,%2,%3}, {%4,%5,%6,%7}, {%8,%9}, {%0,%1,%2,%3};"
        : "+f"(c0), "+f"(c1), "+f"(c2), "+f"(c3)
        : "r"(a0), "r"(a1), "r"(a2), "r"(a3), "r"(b0), "r"(b1));
}

// ---------------------------------------------------------------------------
// Generic fp32 GEMM body (unchanged)
// ---------------------------------------------------------------------------
__device__ __forceinline__ void gemm_body(
    const float* __restrict__ A, const float* __restrict__ A2,
    const float* __restrict__ B, const float* __restrict__ bias,
    float* __restrict__ C, int m0, int n0)
{
    __shared__ float As[GEMM_BK][65];
    __shared__ float Bs[GEMM_BK][GEMM_BN];

    const int tid = threadIdx.x;
    const int am  = tid >> 2;
    const int ak  = (tid & 3) << 2;
    const int bk  = tid >> 4;
    const int bn  = (tid & 15) << 2;
    const int tm  = (tid >> 4) << 2;
    const int tc  = tid & 15;

    float acc[4][4] = {};

    for (int k0 = 0; k0 < EMBED; k0 += GEMM_BK) {
        float4 av = *(const float4*)&A[(size_t)(m0 + am) * EMBED + k0 + ak];
        if (A2) {
            float4 a2 = *(const float4*)&A2[(size_t)(m0 + am) * EMBED + k0 + ak];
            av.x += a2.x; av.y += a2.y; av.z += a2.z; av.w += a2.w;
        }
        float4 bv = *(const float4*)&B[(size_t)(k0 + bk) * EMBED + n0 + bn];

        As[ak + 0][am] = av.x;
        As[ak + 1][am] = av.y;
        As[ak + 2][am] = av.z;
        As[ak + 3][am] = av.w;
        *(float4*)&Bs[bk][bn] = bv;
        __syncthreads();

        #pragma unroll
        for (int kk = 0; kk < GEMM_BK; kk++) {
            float a[4], b[4];
            #pragma unroll
            for (int i = 0; i < 4; i++) a[i] = As[kk][tm + i];
            #pragma unroll
            for (int j = 0; j < 4; j++) b[j] = Bs[kk][tc + 16 * j];
            #pragma unroll
            for (int i = 0; i < 4; i++)
                #pragma unroll
                for (int j = 0; j < 4; j++)
                    acc[i][j] = fmaf(a[i], b[j], acc[i][j]);
        }
        __syncthreads();
    }

    #pragma unroll
    for (int i = 0; i < 4; i++)
        #pragma unroll
        for (int j = 0; j < 4; j++) {
            int col = n0 + tc + 16 * j;
            C[(size_t)(m0 + tm + i) * EMBED + col] = acc[i][j] + bias[col];
        }
}

__global__ void __launch_bounds__(256)
qkv_gemm(const float* __restrict__ x,
         const float* __restrict__ Wq, const float* __restrict__ bq,
         const float* __restrict__ Wk, const float* __restrict__ bk,
         const float* __restrict__ Wv, const float* __restrict__ bv)
{
    const int m0  = blockIdx.y * GEMM_BM;
    const int nb  = blockIdx.x;
    const int mat = nb >> 2;
    const int n0  = (nb & 3) * GEMM_BN;

    const float* W;
    const float* bias;
    float* out;
    if (mat == 0)      { W = Wq; bias = bq; out = g_q; }
    else if (mat == 1) { W = Wk; bias = bk; out = g_k; }
    else               { W = Wv; bias = bv; out = g_v; }

    gemm_body(x, nullptr, W, bias, out, m0, n0);
}

__global__ void __launch_bounds__(256)
rope_kernel(const float* __restrict__ sin_t, const float* __restrict__ cos_t)
{
    const int idx = blockIdx.x * blockDim.x + threadIdx.x;
    if (idx >= BATCH * NTOK * (EMBED / 2)) return;
    const int row = idx >> 7;
    const int c   = (idx & 127) << 1;
    const int dd  = c & (HD - 1);
    const int pos = row % NTOK;

    const float cs0 = cos_t[pos * HD + dd];
    const float sn0 = sin_t[pos * HD + dd];
    const float cs1 = cos_t[pos * HD + dd + 1];
    const float sn1 = sin_t[pos * HD + dd + 1];

    float2* qp = (float2*)&g_q[(size_t)row * EMBED + c];
    float2 qv = *qp;
    float2 qo;
    qo.x = qv.x * cs0 - qv.y * sn0;
    qo.y = qv.y * cs1 + qv.x * sn1;
    *qp = qo;

    float2* kp = (float2*)&g_k[(size_t)row * EMBED + c];
    float2 kv = *kp;
    float2 ko;
    ko.x = (kv.x * cs0 - kv.y * sn0) * KSCALE;
    ko.y = (kv.y * cs1 + kv.x * sn1) * KSCALE;
    *kp = ko;
}

__global__ void __launch_bounds__(256)
lepe_kernel(const float* __restrict__ w, const float* __restrict__ bias)
{
    const int c = threadIdx.x;
    const int y = blockIdx.x;
    const int b = blockIdx.y;

    float wr[25];
    #pragma unroll
    for (int t = 0; t < 25; t++) wr[t] = w[t * EMBED + c];
    const float bv = bias[c];

    const float* vb = g_v + (size_t)b * NTOK * EMBED;
    float* ob = g_lepe + (size_t)(b * NTOK + y * WW) * EMBED;

    for (int x = 0; x < WW; x++) {
        float sum = bv;
        #pragma unroll
        for (int dy = 0; dy < 5; dy++) {
            const int yy = y + dy - 2;
            if (yy < 0 || yy >= HH) continue;
            #pragma unroll
            for (int dx = 0; dx < 5; dx++) {
                const int xx = x + dx - 2;
                if (xx < 0 || xx >= WW) continue;
                sum = fmaf(vb[(size_t)(yy * WW + xx) * EMBED + c],
                           wr[dy * 5 + dx], sum);
            }
        }
        ob[(size_t)x * EMBED + c] = sum;
    }
}

// ---------------------------------------------------------------------------
// Attention v3: mma.sync m16n8k8 TF32 tensor cores.
//   - 8 warps, each owns 16 query rows (TQ=128), key tiles of 64.
//   - QK^T in 3xTF32 (hi/lo split) for fp32-grade scores.
//   - PV in plain TF32; P moved C-frag -> A-frag via warp shuffles (no smem).
//   - K/V tiles staged in smem, stride 36 (conflict-free B-frag reads).
//   - Grid (b, qtile, h): b fastest so concurrent blocks share mask in L2.
// ---------------------------------------------------------------------------
__global__ void __launch_bounds__(256, 2)
attn_kernel(const float* __restrict__ mask)
{
    __shared__ float k_s[TK * KVSTR];
    __shared__ float v_s[TK * KVSTR];

    const int tid  = threadIdx.x;
    const int warp = tid >> 5;
    const int lane = tid & 31;
    const int g    = lane >> 2;      // fragment row group 0..7
    const int t4   = lane & 3;       // fragment quad lane 0..3

    const int b  = blockIdx.x;
    const int q0 = blockIdx.y * TQ;
    const int h  = blockIdx.z;
    const int qw = q0 + warp * 16;   // this warp's first query row

    const float* Qg = g_q + (size_t)(b * NTOK + qw) * EMBED + h * HD;
    const float* Kg = g_k + (size_t)b * NTOK * EMBED + h * HD;
    const float* Vg = g_v + (size_t)b * NTOK * EMBED + h * HD;
    const float* Mg = mask + ((size_t)h * NTOK + qw) * NTOK;

    // --- Q fragments (persist across all key tiles), hi/lo tf32 split ---
    uint32_t qhi[4][4], qlo[4][4];
    #pragma unroll
    for (int kc = 0; kc < 4; kc++) {
        float x0 = Qg[(size_t)g * EMBED + kc * 8 + t4];
        float x1 = Qg[(size_t)(g + 8) * EMBED + kc * 8 + t4];
        float x2 = Qg[(size_t)g * EMBED + kc * 8 + t4 + 4];
        float x3 = Qg[(size_t)(g + 8) * EMBED + kc * 8 + t4 + 4];
        qhi[kc][0] = f2tf32(x0);
        qhi[kc][1] = f2tf32(x1);
        qhi[kc][2] = f2tf32(x2);
        qhi[kc][3] = f2tf32(x3);
        qlo[kc][0] = f2tf32(x0 - __uint_as_float(qhi[kc][0]));
        qlo[kc][1] = f2tf32(x1 - __uint_as_float(qhi[kc][1]));
        qlo[kc][2] = f2tf32(x2 - __uint_as_float(qhi[kc][2]));
        qlo[kc][3] = f2tf32(x3 - __uint_as_float(qhi[kc][3]));
    }

    float m0r = -1e30f, m1r = -1e30f, l0r = 0.f, l1r = 0.f;
    float acc[4][4] = {};   // PV C-frags: n-tile (8 dims each) x 4 regs

    // loader mapping: 256 threads cover 64 rows x 32 d for both K and V
    const int lr  = tid >> 2;
    const int lcb = (tid & 3) * 8;

    for (int k0 = 0; k0 < NTOK; k0 += TK) {
        float4 ka = *(const float4*)&Kg[(size_t)(k0 + lr) * EMBED + lcb];
        float4 kb = *(const float4*)&Kg[(size_t)(k0 + lr) * EMBED + lcb + 4];
        float4 va = *(const float4*)&Vg[(size_t)(k0 + lr) * EMBED + lcb];
        float4 vb = *(const float4*)&Vg[(size_t)(k0 + lr) * EMBED + lcb + 4];

        __syncthreads();
        *(float4*)&k_s[lr * KVSTR + lcb]     = ka;
        *(float4*)&k_s[lr * KVSTR + lcb + 4] = kb;
        *(float4*)&v_s[lr * KVSTR + lcb]     = va;
        *(float4*)&v_s[lr * KVSTR + lcb + 4] = vb;
        __syncthreads();

        // ---- scores: init with mask bias, then 3xTF32 QK^T ----
        float c[8][4];
        #pragma unroll
        for (int n0 = 0; n0 < 8; n0++) {
            const float* mrow = Mg + (size_t)g * NTOK + k0 + n0 * 8 + 2 * t4;
            float2 mA = *(const float2*)mrow;
            float2 mB = *(const float2*)(mrow + 8 * NTOK);
            c[n0][0] = mA.x; c[n0][1] = mA.y;
            c[n0][2] = mB.x; c[n0][3] = mB.y;
        }

        #pragma unroll
        for (int kc = 0; kc < 4; kc++) {
            #pragma unroll
            for (int n0 = 0; n0 < 8; n0++) {
                const int krow = n0 * 8 + g;
                float kf0 = k_s[krow * KVSTR + kc * 8 + t4];
                float kf1 = k_s[krow * KVSTR + kc * 8 + t4 + 4];
                uint32_t bh0 = f2tf32(kf0);
                uint32_t bh1 = f2tf32(kf1);
                uint32_t bl0 = f2tf32(kf0 - __uint_as_float(bh0));
                uint32_t bl1 = f2tf32(kf1 - __uint_as_float(bh1));
                // small terms first, then the dominant hi*hi
                mma_tf32(c[n0][0], c[n0][1], c[n0][2], c[n0][3],
                         qhi[kc][0], qhi[kc][1], qhi[kc][2], qhi[kc][3],
                         bl0, bl1);
                mma_tf32(c[n0][0], c[n0][1], c[n0][2], c[n0][3],
                         qlo[kc][0], qlo[kc][1], qlo[kc][2], qlo[kc][3],
                         bh0, bh1);
                mma_tf32(c[n0][0], c[n0][1], c[n0][2], c[n0][3],
                         qhi[kc][0], qhi[kc][1], qhi[kc][2], qhi[kc][3],
                         bh0, bh1);
            }
        }

        // ---- online softmax (rows g and g+8) ----
        float mx0 = -1e30f, mx1 = -1e30f;
        #pragma unroll
        for (int n0 = 0; n0 < 8; n0++) {
            mx0 = fmaxf(mx0, fmaxf(c[n0][0], c[n0][1]));
            mx1 = fmaxf(mx1, fmaxf(c[n0][2], c[n0][3]));
        }
        mx0 = fmaxf(mx0, __shfl_xor_sync(0xffffffffu, mx0, 1));
        mx0 = fmaxf(mx0, __shfl_xor_sync(0xffffffffu, mx0, 2));
        mx1 = fmaxf(mx1, __shfl_xor_sync(0xffffffffu, mx1, 1));
        mx1 = fmaxf(mx1, __shfl_xor_sync(0xffffffffu, mx1, 2));

        const float mn0 = fmaxf(m0r, mx0);
        const float mn1 = fmaxf(m1r, mx1);
        const float al0 = __expf(m0r - mn0);
        const float al1 = __expf(m1r - mn1);
        m0r = mn0; m1r = mn1;

        float s0 = 0.f, s1 = 0.f;
        #pragma unroll
        for (int n0 = 0; n0 < 8; n0++) {
            c[n0][0] = __expf(c[n0][0] - mn0);
            c[n0][1] = __expf(c[n0][1] - mn0);
            c[n0][2] = __expf(c[n0][2] - mn1);
            c[n0][3] = __expf(c[n0][3] - mn1);
            s0 += c[n0][0] + c[n0][1];
            s1 += c[n0][2] + c[n0][3];
        }
        s0 += __shfl_xor_sync(0xffffffffu, s0, 1);
        s0 += __shfl_xor_sync(0xffffffffu, s0, 2);
        s1 += __shfl_xor_sync(0xffffffffu, s1, 1);
        s1 += __shfl_xor_sync(0xffffffffu, s1, 2);
        l0r = l0r * al0 + s0;
        l1r = l1r * al1 + s1;

        #pragma unroll
        for (int n = 0; n < 4; n++) {
            acc[n][0] *= al0; acc[n][1] *= al0;
            acc[n][2] *= al1; acc[n][3] *= al1;
        }

        // ---- PV: P C-frag -> A-frag via shuffles, plain TF32 mma ----
        const int src0 = (g << 2) + (t4 >> 1);
        const int src1 = src0 + 2;
        const bool odd = (t4 & 1);
        #pragma unroll
        for (int kc = 0; kc < 8; kc++) {
            float e00 = __shfl_sync(0xffffffffu, c[kc][0], src0);
            float e01 = __shfl_sync(0xffffffffu, c[kc][1], src0);
            float e10 = __shfl_sync(0xffffffffu, c[kc][2], src0);
            float e11 = __shfl_sync(0xffffffffu, c[kc][3], src0);
            float e20 = __shfl_sync(0xffffffffu, c[kc][0], src1);
            float e21 = __shfl_sync(0xffffffffu, c[kc][1], src1);
            float e30 = __shfl_sync(0xffffffffu, c[kc][2], src1);
            float e31 = __shfl_sync(0xffffffffu, c[kc][3], src1);
            uint32_t pa0 = f2tf32(odd ? e01 : e00);
            uint32_t pa1 = f2tf32(odd ? e11 : e10);
            uint32_t pa2 = f2tf32(odd ? e21 : e20);
            uint32_t pa3 = f2tf32(odd ? e31 : e30);

            const int vr0 = (kc * 8 + t4) * KVSTR;
            const int vr1 = (kc * 8 + t4 + 4) * KVSTR;
            #pragma unroll
            for (int n = 0; n < 4; n++) {
                uint32_t vb0 = f2tf32(v_s[vr0 + n * 8 + g]);
                uint32_t vb1 = f2tf32(v_s[vr1 + n * 8 + g]);
                mma_tf32(acc[n][0], acc[n][1], acc[n][2], acc[n][3],
                         pa0, pa1, pa2, pa3, vb0, vb1);
            }
        }
    }

    // ---- epilogue ----
    const float inv0 = 1.0f / l0r;
    const float inv1 = 1.0f / l1r;
    float* Og = g_att + (size_t)(b * NTOK + qw) * EMBED + h * HD;
    #pragma unroll
    for (int n = 0; n < 4; n++) {
        *(float2*)&Og[(size_t)g * EMBED + n * 8 + 2 * t4] =
            make_float2(acc[n][0] * inv0, acc[n][1] * inv0);
        *(float2*)&Og[(size_t)(g + 8) * EMBED + n * 8 + 2 * t4] =
            make_float2(acc[n][2] * inv1, acc[n][3] * inv1);
    }
}

__global__ void __launch_bounds__(256)
out_gemm(const float* __restrict__ Wout, const float* __restrict__ bout,
         float* __restrict__ out)
{
    gemm_body(g_att, g_lepe, Wout, bout, out,
              blockIdx.y * GEMM_BM, blockIdx.x * GEMM_BN);
}

// ---------------------------------------------------------------------------
extern "C" void kernel_launch(void* const* d_in, const int* in_sizes, int n_in,
                              void* d_out, int out_size)
{
    const float* x      = (const float*)d_in[0];
    const float* sin_t  = (const float*)d_in[1];
    const float* cos_t  = (const float*)d_in[2];
    const float* mask   = (const float*)d_in[3];
    const float* Wq     = (const float*)d_in[4];
    const float* bq     = (const float*)d_in[5];
    const float* Wk     = (const float*)d_in[6];
    const float* bk     = (const float*)d_in[7];
    const float* Wv     = (const float*)d_in[8];
    const float* bv     = (const float*)d_in[9];
    const float* lepe_w = (const float*)d_in[10];
    const float* lepe_b = (const float*)d_in[11];
    const float* Wout   = (const float*)d_in[12];
    const float* bout   = (const float*)d_in[13];
    float* out = (float*)d_out;

    const int M = BATCH * NTOK;   // 9216

    qkv_gemm<<<dim3(768 / GEMM_BN, M / GEMM_BM), 256>>>(x, Wq, bq, Wk, bk, Wv, bv);
    rope_kernel<<<(BATCH * NTOK * (EMBED / 2)) / 256, 256>>>(sin_t, cos_t);
    lepe_kernel<<<dim3(HH, BATCH), 256>>>(lepe_w, lepe_b);
    attn_kernel<<<dim3(BATCH, NTOK / TQ, HEADS), 256>>>(mask);
    out_gemm<<<dim3(EMBED / GEMM_BN, M / GEMM_BM), 256>>>(Wout, bout, out);
}

// round 4
// speedup vs baseline: 9.7863x; 1.1354x over previous
#include <cuda_runtime.h>
#include <cstdint>

#define EMBED 256
#define HEADS 8
#define HD    32
#define NTOK  2304
#define BATCH 4
#define HH    48
#define WW    48
#define KSCALE 0.17677669529663687f  /* 32^-0.5 */

#define GEMM_BM 64
#define GEMM_BN 64
#define GEMM_BK 16

// Attention tiling (tensor-core version)
#define TQ 128            // 8 warps x 16 query rows
#define TK 64             // key tile
#define KVSTR 36          // k_s/v_s row stride in words

// Scratch buffers (allocation-free rule: __device__ globals)
__device__ float g_q[BATCH * NTOK * EMBED];
__device__ float g_k[BATCH * NTOK * EMBED];
__device__ float g_v[BATCH * NTOK * EMBED];
__device__ float g_lepe[BATCH * NTOK * EMBED];
__device__ float g_att[BATCH * NTOK * EMBED];

// ---------------------------------------------------------------------------
// TF32 helpers
// ---------------------------------------------------------------------------
__device__ __forceinline__ uint32_t f2tf32(float x) {
    uint32_t r;
    asm("cvt.rna.tf32.f32 %0, %1;" : "=r"(r) : "f"(x));
    return r;
}

__device__ __forceinline__ void mma_tf32(
    float& c0, float& c1, float& c2, float& c3,
    uint32_t a0, uint32_t a1, uint32_t a2, uint32_t a3,
    uint32_t b0, uint32_t b1)
{
    asm("mma.sync.aligned.m16n8k8.row.col.f32.tf32.tf32.f32 "
        "{%0,%1,%2,%3}, {%4,%5,%6,%7}, {%8,%9}, {%0,%1,%2,%3};"
        : "+f"(c0), "+f"(c1), "+f"(c2), "+f"(c3)
        : "r"(a0), "r"(a1), "r"(a2), "r"(a3), "r"(b0), "r"(b1));
}

// ---------------------------------------------------------------------------
// Generic fp32 GEMM body (unchanged)
// ---------------------------------------------------------------------------
__device__ __forceinline__ void gemm_body(
    const float* __restrict__ A, const float* __restrict__ A2,
    const float* __restrict__ B, const float* __restrict__ bias,
    float* __restrict__ C, int m0, int n0)
{
    __shared__ float As[GEMM_BK][65];
    __shared__ float Bs[GEMM_BK][GEMM_BN];

    const int tid = threadIdx.x;
    const int am  = tid >> 2;
    const int ak  = (tid & 3) << 2;
    const int bk  = tid >> 4;
    const int bn  = (tid & 15) << 2;
    const int tm  = (tid >> 4) << 2;
    const int tc  = tid & 15;

    float acc[4][4] = {};

    for (int k0 = 0; k0 < EMBED; k0 += GEMM_BK) {
        float4 av = *(const float4*)&A[(size_t)(m0 + am) * EMBED + k0 + ak];
        if (A2) {
            float4 a2 = *(const float4*)&A2[(size_t)(m0 + am) * EMBED + k0 + ak];
            av.x += a2.x; av.y += a2.y; av.z += a2.z; av.w += a2.w;
        }
        float4 bv = *(const float4*)&B[(size_t)(k0 + bk) * EMBED + n0 + bn];

        As[ak + 0][am] = av.x;
        As[ak + 1][am] = av.y;
        As[ak + 2][am] = av.z;
        As[ak + 3][am] = av.w;
        *(float4*)&Bs[bk][bn] = bv;
        __syncthreads();

        #pragma unroll
        for (int kk = 0; kk < GEMM_BK; kk++) {
            float a[4], b[4];
            #pragma unroll
            for (int i = 0; i < 4; i++) a[i] = As[kk][tm + i];
            #pragma unroll
            for (int j = 0; j < 4; j++) b[j] = Bs[kk][tc + 16 * j];
            #pragma unroll
            for (int i = 0; i < 4; i++)
                #pragma unroll
                for (int j = 0; j < 4; j++)
                    acc[i][j] = fmaf(a[i], b[j], acc[i][j]);
        }
        __syncthreads();
    }

    #pragma unroll
    for (int i = 0; i < 4; i++)
        #pragma unroll
        for (int j = 0; j < 4; j++) {
            int col = n0 + tc + 16 * j;
            C[(size_t)(m0 + tm + i) * EMBED + col] = acc[i][j] + bias[col];
        }
}

__global__ void __launch_bounds__(256)
qkv_gemm(const float* __restrict__ x,
         const float* __restrict__ Wq, const float* __restrict__ bq,
         const float* __restrict__ Wk, const float* __restrict__ bk,
         const float* __restrict__ Wv, const float* __restrict__ bv)
{
    const int m0  = blockIdx.y * GEMM_BM;
    const int nb  = blockIdx.x;
    const int mat = nb >> 2;
    const int n0  = (nb & 3) * GEMM_BN;

    const float* W;
    const float* bias;
    float* out;
    if (mat == 0)      { W = Wq; bias = bq; out = g_q; }
    else if (mat == 1) { W = Wk; bias = bk; out = g_k; }
    else               { W = Wv; bias = bv; out = g_v; }

    gemm_body(x, nullptr, W, bias, out, m0, n0);
}

__global__ void __launch_bounds__(256)
rope_kernel(const float* __restrict__ sin_t, const float* __restrict__ cos_t)
{
    const int idx = blockIdx.x * blockDim.x + threadIdx.x;
    if (idx >= BATCH * NTOK * (EMBED / 2)) return;
    const int row = idx >> 7;
    const int c   = (idx & 127) << 1;
    const int dd  = c & (HD - 1);
    const int pos = row % NTOK;

    const float cs0 = cos_t[pos * HD + dd];
    const float sn0 = sin_t[pos * HD + dd];
    const float cs1 = cos_t[pos * HD + dd + 1];
    const float sn1 = sin_t[pos * HD + dd + 1];

    float2* qp = (float2*)&g_q[(size_t)row * EMBED + c];
    float2 qv = *qp;
    float2 qo;
    qo.x = qv.x * cs0 - qv.y * sn0;
    qo.y = qv.y * cs1 + qv.x * sn1;
    *qp = qo;

    float2* kp = (float2*)&g_k[(size_t)row * EMBED + c];
    float2 kv = *kp;
    float2 ko;
    ko.x = (kv.x * cs0 - kv.y * sn0) * KSCALE;
    ko.y = (kv.y * cs1 + kv.x * sn1) * KSCALE;
    *kp = ko;
}

__global__ void __launch_bounds__(256)
lepe_kernel(const float* __restrict__ w, const float* __restrict__ bias)
{
    const int c = threadIdx.x;
    const int y = blockIdx.x;
    const int b = blockIdx.y;

    float wr[25];
    #pragma unroll
    for (int t = 0; t < 25; t++) wr[t] = w[t * EMBED + c];
    const float bv = bias[c];

    const float* vb = g_v + (size_t)b * NTOK * EMBED;
    float* ob = g_lepe + (size_t)(b * NTOK + y * WW) * EMBED;

    for (int x = 0; x < WW; x++) {
        float sum = bv;
        #pragma unroll
        for (int dy = 0; dy < 5; dy++) {
            const int yy = y + dy - 2;
            if (yy < 0 || yy >= HH) continue;
            #pragma unroll
            for (int dx = 0; dx < 5; dx++) {
                const int xx = x + dx - 2;
                if (xx < 0 || xx >= WW) continue;
                sum = fmaf(vb[(size_t)(yy * WW + xx) * EMBED + c],
                           wr[dy * 5 + dx], sum);
            }
        }
        ob[(size_t)x * EMBED + c] = sum;
    }
}

// ---------------------------------------------------------------------------
// Attention v4: mma.sync m16n8k8 TF32.
//   - K and V are converted to TF32 ONCE by the tile loaders and stored in
//     smem as ready mma operands: the QK/PV mainloops contain zero CVT/FSUB.
//   - QK in 2xTF32 (qhi + qlo vs rounded K): fp32-grade minus ~1.4e-4 abs.
//   - PV in plain TF32; P goes C-frag -> A-frag via shuffles (no smem).
//   - Grid (b, qtile, h): b fastest so concurrent blocks share mask in L2.
// ---------------------------------------------------------------------------
__global__ void __launch_bounds__(256, 2)
attn_kernel(const float* __restrict__ mask)
{
    __shared__ uint32_t k_s[TK * KVSTR];   // tf32(K) [key][d]
    __shared__ uint32_t v_s[TK * KVSTR];   // tf32(V) [key][d]

    const int tid  = threadIdx.x;
    const int warp = tid >> 5;
    const int lane = tid & 31;
    const int g    = lane >> 2;      // fragment row group 0..7
    const int t4   = lane & 3;       // fragment quad lane 0..3

    const int b  = blockIdx.x;
    const int q0 = blockIdx.y * TQ;
    const int h  = blockIdx.z;
    const int qw = q0 + warp * 16;   // this warp's first query row

    const float* Qg = g_q + (size_t)(b * NTOK + qw) * EMBED + h * HD;
    const float* Kg = g_k + (size_t)b * NTOK * EMBED + h * HD;
    const float* Vg = g_v + (size_t)b * NTOK * EMBED + h * HD;
    const float* Mg = mask + ((size_t)h * NTOK + qw) * NTOK;

    // --- Q fragments (persist across all key tiles), hi/lo tf32 split ---
    uint32_t qhi[4][4], qlo[4][4];
    #pragma unroll
    for (int kc = 0; kc < 4; kc++) {
        float x0 = Qg[(size_t)g * EMBED + kc * 8 + t4];
        float x1 = Qg[(size_t)(g + 8) * EMBED + kc * 8 + t4];
        float x2 = Qg[(size_t)g * EMBED + kc * 8 + t4 + 4];
        float x3 = Qg[(size_t)(g + 8) * EMBED + kc * 8 + t4 + 4];
        qhi[kc][0] = f2tf32(x0);
        qhi[kc][1] = f2tf32(x1);
        qhi[kc][2] = f2tf32(x2);
        qhi[kc][3] = f2tf32(x3);
        qlo[kc][0] = f2tf32(x0 - __uint_as_float(qhi[kc][0]));
        qlo[kc][1] = f2tf32(x1 - __uint_as_float(qhi[kc][1]));
        qlo[kc][2] = f2tf32(x2 - __uint_as_float(qhi[kc][2]));
        qlo[kc][3] = f2tf32(x3 - __uint_as_float(qhi[kc][3]));
    }

    float m0r = -1e30f, m1r = -1e30f, l0r = 0.f, l1r = 0.f;
    float acc[4][4] = {};   // PV C-frags: n-tile (8 dims each) x 4 regs

    // loader mapping: 256 threads cover 64 rows x 32 d for both K and V
    const int lr  = tid >> 2;
    const int lcb = (tid & 3) * 8;

    for (int k0 = 0; k0 < NTOK; k0 += TK) {
        float4 ka = *(const float4*)&Kg[(size_t)(k0 + lr) * EMBED + lcb];
        float4 kb = *(const float4*)&Kg[(size_t)(k0 + lr) * EMBED + lcb + 4];
        float4 va = *(const float4*)&Vg[(size_t)(k0 + lr) * EMBED + lcb];
        float4 vb = *(const float4*)&Vg[(size_t)(k0 + lr) * EMBED + lcb + 4];

        __syncthreads();
        {
            uint32_t* kp = &k_s[lr * KVSTR + lcb];
            kp[0] = f2tf32(ka.x); kp[1] = f2tf32(ka.y);
            kp[2] = f2tf32(ka.z); kp[3] = f2tf32(ka.w);
            kp[4] = f2tf32(kb.x); kp[5] = f2tf32(kb.y);
            kp[6] = f2tf32(kb.z); kp[7] = f2tf32(kb.w);
            uint32_t* vp = &v_s[lr * KVSTR + lcb];
            vp[0] = f2tf32(va.x); vp[1] = f2tf32(va.y);
            vp[2] = f2tf32(va.z); vp[3] = f2tf32(va.w);
            vp[4] = f2tf32(vb.x); vp[5] = f2tf32(vb.y);
            vp[6] = f2tf32(vb.z); vp[7] = f2tf32(vb.w);
        }
        __syncthreads();

        // ---- scores: init with mask bias, then 2xTF32 QK^T ----
        float c[8][4];
        #pragma unroll
        for (int n0 = 0; n0 < 8; n0++) {
            const float* mrow = Mg + (size_t)g * NTOK + k0 + n0 * 8 + 2 * t4;
            float2 mA = *(const float2*)mrow;
            float2 mB = *(const float2*)(mrow + 8 * NTOK);
            c[n0][0] = mA.x; c[n0][1] = mA.y;
            c[n0][2] = mB.x; c[n0][3] = mB.y;
        }

        #pragma unroll
        for (int kc = 0; kc < 4; kc++) {
            #pragma unroll
            for (int n0 = 0; n0 < 8; n0++) {
                const int krow = n0 * 8 + g;
                uint32_t bh0 = k_s[krow * KVSTR + kc * 8 + t4];
                uint32_t bh1 = k_s[krow * KVSTR + kc * 8 + t4 + 4];
                // small term first, then the dominant hi term
                mma_tf32(c[n0][0], c[n0][1], c[n0][2], c[n0][3],
                         qlo[kc][0], qlo[kc][1], qlo[kc][2], qlo[kc][3],
                         bh0, bh1);
                mma_tf32(c[n0][0], c[n0][1], c[n0][2], c[n0][3],
                         qhi[kc][0], qhi[kc][1], qhi[kc][2], qhi[kc][3],
                         bh0, bh1);
            }
        }

        // ---- online softmax (rows g and g+8) ----
        float mx0 = -1e30f, mx1 = -1e30f;
        #pragma unroll
        for (int n0 = 0; n0 < 8; n0++) {
            mx0 = fmaxf(mx0, fmaxf(c[n0][0], c[n0][1]));
            mx1 = fmaxf(mx1, fmaxf(c[n0][2], c[n0][3]));
        }
        mx0 = fmaxf(mx0, __shfl_xor_sync(0xffffffffu, mx0, 1));
        mx0 = fmaxf(mx0, __shfl_xor_sync(0xffffffffu, mx0, 2));
        mx1 = fmaxf(mx1, __shfl_xor_sync(0xffffffffu, mx1, 1));
        mx1 = fmaxf(mx1, __shfl_xor_sync(0xffffffffu, mx1, 2));

        const float mn0 = fmaxf(m0r, mx0);
        const float mn1 = fmaxf(m1r, mx1);
        const float al0 = __expf(m0r - mn0);
        const float al1 = __expf(m1r - mn1);
        m0r = mn0; m1r = mn1;

        float s0 = 0.f, s1 = 0.f;
        #pragma unroll
        for (int n0 = 0; n0 < 8; n0++) {
            c[n0][0] = __expf(c[n0][0] - mn0);
            c[n0][1] = __expf(c[n0][1] - mn0);
            c[n0][2] = __expf(c[n0][2] - mn1);
            c[n0][3] = __expf(c[n0][3] - mn1);
            s0 += c[n0][0] + c[n0][1];
            s1 += c[n0][2] + c[n0][3];
        }
        s0 += __shfl_xor_sync(0xffffffffu, s0, 1);
        s0 += __shfl_xor_sync(0xffffffffu, s0, 2);
        s1 += __shfl_xor_sync(0xffffffffu, s1, 1);
        s1 += __shfl_xor_sync(0xffffffffu, s1, 2);
        l0r = l0r * al0 + s0;
        l1r = l1r * al1 + s1;

        #pragma unroll
        for (int n = 0; n < 4; n++) {
            acc[n][0] *= al0; acc[n][1] *= al0;
            acc[n][2] *= al1; acc[n][3] *= al1;
        }

        // ---- PV: P C-frag -> A-frag via shuffles, plain TF32 mma ----
        const int src0 = (g << 2) + (t4 >> 1);
        const int src1 = src0 + 2;
        const bool odd = (t4 & 1);
        #pragma unroll
        for (int kc = 0; kc < 8; kc++) {
            float e00 = __shfl_sync(0xffffffffu, c[kc][0], src0);
            float e01 = __shfl_sync(0xffffffffu, c[kc][1], src0);
            float e10 = __shfl_sync(0xffffffffu, c[kc][2], src0);
            float e11 = __shfl_sync(0xffffffffu, c[kc][3], src0);
            float e20 = __shfl_sync(0xffffffffu, c[kc][0], src1);
            float e21 = __shfl_sync(0xffffffffu, c[kc][1], src1);
            float e30 = __shfl_sync(0xffffffffu, c[kc][2], src1);
            float e31 = __shfl_sync(0xffffffffu, c[kc][3], src1);
            uint32_t pa0 = f2tf32(odd ? e01 : e00);
            uint32_t pa1 = f2tf32(odd ? e11 : e10);
            uint32_t pa2 = f2tf32(odd ? e21 : e20);
            uint32_t pa3 = f2tf32(odd ? e31 : e30);

            const int vr0 = (kc * 8 + t4) * KVSTR;
            const int vr1 = (kc * 8 + t4 + 4) * KVSTR;
            #pragma unroll
            for (int n = 0; n < 4; n++) {
                uint32_t vb0 = v_s[vr0 + n * 8 + g];
                uint32_t vb1 = v_s[vr1 + n * 8 + g];
                mma_tf32(acc[n][0], acc[n][1], acc[n][2], acc[n][3],
                         pa0, pa1, pa2, pa3, vb0, vb1);
            }
        }
    }

    // ---- epilogue ----
    const float inv0 = 1.0f / l0r;
    const float inv1 = 1.0f / l1r;
    float* Og = g_att + (size_t)(b * NTOK + qw) * EMBED + h * HD;
    #pragma unroll
    for (int n = 0; n < 4; n++) {
        *(float2*)&Og[(size_t)g * EMBED + n * 8 + 2 * t4] =
            make_float2(acc[n][0] * inv0, acc[n][1] * inv0);
        *(float2*)&Og[(size_t)(g + 8) * EMBED + n * 8 + 2 * t4] =
            make_float2(acc[n][2] * inv1, acc[n][3] * inv1);
    }
}

__global__ void __launch_bounds__(256)
out_gemm(const float* __restrict__ Wout, const float* __restrict__ bout,
         float* __restrict__ out)
{
    gemm_body(g_att, g_lepe, Wout, bout, out,
              blockIdx.y * GEMM_BM, blockIdx.x * GEMM_BN);
}

// ---------------------------------------------------------------------------
extern "C" void kernel_launch(void* const* d_in, const int* in_sizes, int n_in,
                              void* d_out, int out_size)
{
    const float* x      = (const float*)d_in[0];
    const float* sin_t  = (const float*)d_in[1];
    const float* cos_t  = (const float*)d_in[2];
    const float* mask   = (const float*)d_in[3];
    const float* Wq     = (const float*)d_in[4];
    const float* bq     = (const float*)d_in[5];
    const float* Wk     = (const float*)d_in[6];
    const float* bk     = (const float*)d_in[7];
    const float* Wv     = (const float*)d_in[8];
    const float* bv     = (const float*)d_in[9];
    const float* lepe_w = (const float*)d_in[10];
    const float* lepe_b = (const float*)d_in[11];
    const float* Wout   = (const float*)d_in[12];
    const float* bout   = (const float*)d_in[13];
    float* out = (float*)d_out;

    const int M = BATCH * NTOK;   // 9216

    qkv_gemm<<<dim3(768 / GEMM_BN, M / GEMM_BM), 256>>>(x, Wq, bq, Wk, bk, Wv, bv);
    rope_kernel<<<(BATCH * NTOK * (EMBED / 2)) / 256, 256>>>(sin_t, cos_t);
    lepe_kernel<<<dim3(HH, BATCH), 256>>>(lepe_w, lepe_b);
    attn_kernel<<<dim3(BATCH, NTOK / TQ, HEADS), 256>>>(mask);
    out_gemm<<<dim3(EMBED / GEMM_BN, M / GEMM_BM), 256>>>(Wout, bout, out);
}

// round 5
// speedup vs baseline: 10.2198x; 1.0443x over previous
#include <cuda_runtime.h>
#include <cstdint>

#define EMBED 256
#define HEADS 8
#define HD    32
#define NTOK  2304
#define BATCH 4
#define HH    48
#define WW    48
#define KSCALE 0.17677669529663687f  /* 32^-0.5 */

#define GEMM_BM 64
#define GEMM_BN 64
#define GEMM_BK 16

// Attention tiling (tensor-core version)
#define TQ 128            // 8 warps x 16 query rows
#define TK 64             // key tile
#define KVSTR 36          // k_s/v_s row stride in words
#define NKT (NTOK / TK)   // 36 key tiles

// Scratch buffers (allocation-free rule: __device__ globals)
__device__ float g_q[BATCH * NTOK * EMBED];
__device__ float g_k[BATCH * NTOK * EMBED];    // tf32-rounded by rope
__device__ float g_v[BATCH * NTOK * EMBED];    // exact (for lepe)
__device__ float g_vt[BATCH * NTOK * EMBED];   // tf32-rounded copy for attn
__device__ float g_lepe[BATCH * NTOK * EMBED];
__device__ float g_att[BATCH * NTOK * EMBED];

// ---------------------------------------------------------------------------
// TF32 / cp.async helpers
// ---------------------------------------------------------------------------
__device__ __forceinline__ uint32_t f2tf32(float x) {
    uint32_t r;
    asm("cvt.rna.tf32.f32 %0, %1;" : "=r"(r) : "f"(x));
    return r;
}

__device__ __forceinline__ void mma_tf32(
    float& c0, float& c1, float& c2, float& c3,
    uint32_t a0, uint32_t a1, uint32_t a2, uint32_t a3,
    uint32_t b0, uint32_t b1)
{
    asm("mma.sync.aligned.m16n8k8.row.col.f32.tf32.tf32.f32 "
        "{%0,%1,%2,%3}, {%4,%5,%6,%7}, {%8,%9}, {%0,%1,%2,%3};"
        : "+f"(c0), "+f"(c1), "+f"(c2), "+f"(c3)
        : "r"(a0), "r"(a1), "r"(a2), "r"(a3), "r"(b0), "r"(b1));
}

__device__ __forceinline__ void cp16(uint32_t s_addr, const void* g_ptr) {
    asm volatile("cp.async.ca.shared.global [%0], [%1], 16;"
                 :: "r"(s_addr), "l"(g_ptr));
}

// ---------------------------------------------------------------------------
// Generic fp32 GEMM body (unchanged)
// ---------------------------------------------------------------------------
__device__ __forceinline__ void gemm_body(
    const float* __restrict__ A, const float* __restrict__ A2,
    const float* __restrict__ B, const float* __restrict__ bias,
    float* __restrict__ C, int m0, int n0)
{
    __shared__ float As[GEMM_BK][65];
    __shared__ float Bs[GEMM_BK][GEMM_BN];

    const int tid = threadIdx.x;
    const int am  = tid >> 2;
    const int ak  = (tid & 3) << 2;
    const int bk  = tid >> 4;
    const int bn  = (tid & 15) << 2;
    const int tm  = (tid >> 4) << 2;
    const int tc  = tid & 15;

    float acc[4][4] = {};

    for (int k0 = 0; k0 < EMBED; k0 += GEMM_BK) {
        float4 av = *(const float4*)&A[(size_t)(m0 + am) * EMBED + k0 + ak];
        if (A2) {
            float4 a2 = *(const float4*)&A2[(size_t)(m0 + am) * EMBED + k0 + ak];
            av.x += a2.x; av.y += a2.y; av.z += a2.z; av.w += a2.w;
        }
        float4 bv = *(const float4*)&B[(size_t)(k0 + bk) * EMBED + n0 + bn];

        As[ak + 0][am] = av.x;
        As[ak + 1][am] = av.y;
        As[ak + 2][am] = av.z;
        As[ak + 3][am] = av.w;
        *(float4*)&Bs[bk][bn] = bv;
        __syncthreads();

        #pragma unroll
        for (int kk = 0; kk < GEMM_BK; kk++) {
            float a[4], b[4];
            #pragma unroll
            for (int i = 0; i < 4; i++) a[i] = As[kk][tm + i];
            #pragma unroll
            for (int j = 0; j < 4; j++) b[j] = Bs[kk][tc + 16 * j];
            #pragma unroll
            for (int i = 0; i < 4; i++)
                #pragma unroll
                for (int j = 0; j < 4; j++)
                    acc[i][j] = fmaf(a[i], b[j], acc[i][j]);
        }
        __syncthreads();
    }

    #pragma unroll
    for (int i = 0; i < 4; i++)
        #pragma unroll
        for (int j = 0; j < 4; j++) {
            int col = n0 + tc + 16 * j;
            C[(size_t)(m0 + tm + i) * EMBED + col] = acc[i][j] + bias[col];
        }
}

__global__ void __launch_bounds__(256)
qkv_gemm(const float* __restrict__ x,
         const float* __restrict__ Wq, const float* __restrict__ bq,
         const float* __restrict__ Wk, const float* __restrict__ bk,
         const float* __restrict__ Wv, const float* __restrict__ bv)
{
    const int m0  = blockIdx.y * GEMM_BM;
    const int nb  = blockIdx.x;
    const int mat = nb >> 2;
    const int n0  = (nb & 3) * GEMM_BN;

    const float* W;
    const float* bias;
    float* out;
    if (mat == 0)      { W = Wq; bias = bq; out = g_q; }
    else if (mat == 1) { W = Wk; bias = bk; out = g_k; }
    else               { W = Wv; bias = bv; out = g_v; }

    gemm_body(x, nullptr, W, bias, out, m0, n0);
}

// RoPE; K output additionally rounded to tf32 (only attn consumes g_k).
__global__ void __launch_bounds__(256)
rope_kernel(const float* __restrict__ sin_t, const float* __restrict__ cos_t)
{
    const int idx = blockIdx.x * blockDim.x + threadIdx.x;
    if (idx >= BATCH * NTOK * (EMBED / 2)) return;
    const int row = idx >> 7;
    const int c   = (idx & 127) << 1;
    const int dd  = c & (HD - 1);
    const int pos = row % NTOK;

    const float cs0 = cos_t[pos * HD + dd];
    const float sn0 = sin_t[pos * HD + dd];
    const float cs1 = cos_t[pos * HD + dd + 1];
    const float sn1 = sin_t[pos * HD + dd + 1];

    float2* qp = (float2*)&g_q[(size_t)row * EMBED + c];
    float2 qv = *qp;
    float2 qo;
    qo.x = qv.x * cs0 - qv.y * sn0;
    qo.y = qv.y * cs1 + qv.x * sn1;
    *qp = qo;

    float2* kp = (float2*)&g_k[(size_t)row * EMBED + c];
    float2 kv = *kp;
    float2 ko;
    ko.x = __uint_as_float(f2tf32((kv.x * cs0 - kv.y * sn0) * KSCALE));
    ko.y = __uint_as_float(f2tf32((kv.y * cs1 + kv.x * sn1) * KSCALE));
    *kp = ko;
}

// tf32-rounded copy of V for attention (lepe keeps exact g_v)
__global__ void __launch_bounds__(256)
vt_kernel()
{
    const int i = blockIdx.x * blockDim.x + threadIdx.x;
    float4 v = ((const float4*)g_v)[i];
    float4 o;
    o.x = __uint_as_float(f2tf32(v.x));
    o.y = __uint_as_float(f2tf32(v.y));
    o.z = __uint_as_float(f2tf32(v.z));
    o.w = __uint_as_float(f2tf32(v.w));
    ((float4*)g_vt)[i] = o;
}

__global__ void __launch_bounds__(256)
lepe_kernel(const float* __restrict__ w, const float* __restrict__ bias)
{
    const int c = threadIdx.x;
    const int y = blockIdx.x;
    const int b = blockIdx.y;

    float wr[25];
    #pragma unroll
    for (int t = 0; t < 25; t++) wr[t] = w[t * EMBED + c];
    const float bv = bias[c];

    const float* vb = g_v + (size_t)b * NTOK * EMBED;
    float* ob = g_lepe + (size_t)(b * NTOK + y * WW) * EMBED;

    for (int x = 0; x < WW; x++) {
        float sum = bv;
        #pragma unroll
        for (int dy = 0; dy < 5; dy++) {
            const int yy = y + dy - 2;
            if (yy < 0 || yy >= HH) continue;
            #pragma unroll
            for (int dx = 0; dx < 5; dx++) {
                const int xx = x + dx - 2;
                if (xx < 0 || xx >= WW) continue;
                sum = fmaf(vb[(size_t)(yy * WW + xx) * EMBED + c],
                           wr[dy * 5 + dx], sum);
            }
        }
        ob[(size_t)x * EMBED + c] = sum;
    }
}

// ---------------------------------------------------------------------------
// Attention v5: mma.sync m16n8k8 TF32.
//   - 1xTF32 QK (K/Q single-rounded): 32 QK mmas/warp-tile, 4-deep chains.
//   - K/V pre-rounded to tf32 in gmem; tiles fetched via cp.async into a
//     double-buffered smem ring (full compute-phase of load overlap).
//   - Mask staged in regs and ADDED AFTER the QK mma block (loads overlap mma).
//   - PV in TF32; P moved C-frag -> A-frag via shuffles (no smem).
// ---------------------------------------------------------------------------
__global__ void __launch_bounds__(256, 2)
attn_kernel(const float* __restrict__ mask)
{
    __shared__ uint32_t k_s[2][TK * KVSTR];
    __shared__ uint32_t v_s[2][TK * KVSTR];

    const int tid  = threadIdx.x;
    const int warp = tid >> 5;
    const int lane = tid & 31;
    const int g    = lane >> 2;      // fragment row group 0..7
    const int t4   = lane & 3;       // fragment quad lane 0..3

    const int b  = blockIdx.x;
    const int q0 = blockIdx.y * TQ;
    const int h  = blockIdx.z;
    const int qw = q0 + warp * 16;   // this warp's first query row

    const float* Qg = g_q + (size_t)(b * NTOK + qw) * EMBED + h * HD;
    const float* Kg = g_k + (size_t)b * NTOK * EMBED + h * HD;
    const float* Vg = g_vt + (size_t)b * NTOK * EMBED + h * HD;
    const float* Mg = mask + ((size_t)h * NTOK + qw) * NTOK;

    // loader mapping: 256 threads cover 64 rows x 32 d for both K and V
    const int lr  = tid >> 2;
    const int lcb = (tid & 3) * 8;

    const uint32_t ks0 = (uint32_t)__cvta_generic_to_shared(&k_s[0][lr * KVSTR + lcb]);
    const uint32_t vs0 = (uint32_t)__cvta_generic_to_shared(&v_s[0][lr * KVSTR + lcb]);
    const uint32_t bufstep = (uint32_t)(TK * KVSTR * 4);

    // prologue: issue tile 0
    cp16(ks0,     &Kg[(size_t)lr * EMBED + lcb]);
    cp16(ks0 + 16, &Kg[(size_t)lr * EMBED + lcb + 4]);
    cp16(vs0,     &Vg[(size_t)lr * EMBED + lcb]);
    cp16(vs0 + 16, &Vg[(size_t)lr * EMBED + lcb + 4]);
    asm volatile("cp.async.commit_group;");

    // Q fragments (persist across all key tiles), single tf32 rounding
    uint32_t qa[4][4];
    #pragma unroll
    for (int kc = 0; kc < 4; kc++) {
        qa[kc][0] = f2tf32(Qg[(size_t)g * EMBED + kc * 8 + t4]);
        qa[kc][1] = f2tf32(Qg[(size_t)(g + 8) * EMBED + kc * 8 + t4]);
        qa[kc][2] = f2tf32(Qg[(size_t)g * EMBED + kc * 8 + t4 + 4]);
        qa[kc][3] = f2tf32(Qg[(size_t)(g + 8) * EMBED + kc * 8 + t4 + 4]);
    }

    float m0r = -1e30f, m1r = -1e30f, l0r = 0.f, l1r = 0.f;
    float acc[4][4] = {};   // PV C-frags

    for (int it = 0; it < NKT; it++) {
        const int cur = it & 1;
        asm volatile("cp.async.wait_group 0;");
        __syncthreads();   // tile it visible to all; prior buffer free

        // issue tile it+1 into the other buffer
        if (it + 1 < NKT) {
            const size_t go = (size_t)((it + 1) * TK + lr) * EMBED + lcb;
            const uint32_t ks = ks0 + (cur ^ 1) * bufstep;
            const uint32_t vs = vs0 + (cur ^ 1) * bufstep;
            cp16(ks,      &Kg[go]);
            cp16(ks + 16, &Kg[go + 4]);
            cp16(vs,      &Vg[go]);
            cp16(vs + 16, &Vg[go + 4]);
            asm volatile("cp.async.commit_group;");
        } else {
            asm volatile("cp.async.commit_group;");  // keep group count uniform
        }

        const int k0 = it * TK;

        // stage mask (overlaps the QK mma block below)
        float2 mA[8], mB[8];
        #pragma unroll
        for (int n0 = 0; n0 < 8; n0++) {
            const float* mrow = Mg + (size_t)g * NTOK + k0 + n0 * 8 + 2 * t4;
            mA[n0] = *(const float2*)mrow;
            mB[n0] = *(const float2*)(mrow + 8 * NTOK);
        }

        // ---- QK^T (1xTF32), c starts at 0 ----
        float c[8][4] = {};
        const uint32_t* ks = k_s[cur];
        #pragma unroll
        for (int kc = 0; kc < 4; kc++) {
            #pragma unroll
            for (int n0 = 0; n0 < 8; n0++) {
                const int krow = n0 * 8 + g;
                uint32_t bh0 = ks[krow * KVSTR + kc * 8 + t4];
                uint32_t bh1 = ks[krow * KVSTR + kc * 8 + t4 + 4];
                mma_tf32(c[n0][0], c[n0][1], c[n0][2], c[n0][3],
                         qa[kc][0], qa[kc][1], qa[kc][2], qa[kc][3],
                         bh0, bh1);
            }
        }
        // add mask bias
        #pragma unroll
        for (int n0 = 0; n0 < 8; n0++) {
            c[n0][0] += mA[n0].x; c[n0][1] += mA[n0].y;
            c[n0][2] += mB[n0].x; c[n0][3] += mB[n0].y;
        }

        // ---- online softmax (rows g and g+8) ----
        float mx0 = -1e30f, mx1 = -1e30f;
        #pragma unroll
        for (int n0 = 0; n0 < 8; n0++) {
            mx0 = fmaxf(mx0, fmaxf(c[n0][0], c[n0][1]));
            mx1 = fmaxf(mx1, fmaxf(c[n0][2], c[n0][3]));
        }
        mx0 = fmaxf(mx0, __shfl_xor_sync(0xffffffffu, mx0, 1));
        mx0 = fmaxf(mx0, __shfl_xor_sync(0xffffffffu, mx0, 2));
        mx1 = fmaxf(mx1, __shfl_xor_sync(0xffffffffu, mx1, 1));
        mx1 = fmaxf(mx1, __shfl_xor_sync(0xffffffffu, mx1, 2));

        const float mn0 = fmaxf(m0r, mx0);
        const float mn1 = fmaxf(m1r, mx1);
        const float al0 = __expf(m0r - mn0);
        const float al1 = __expf(m1r - mn1);
        m0r = mn0; m1r = mn1;

        float s0 = 0.f, s1 = 0.f;
        #pragma unroll
        for (int n0 = 0; n0 < 8; n0++) {
            c[n0][0] = __expf(c[n0][0] - mn0);
            c[n0][1] = __expf(c[n0][1] - mn0);
            c[n0][2] = __expf(c[n0][2] - mn1);
            c[n0][3] = __expf(c[n0][3] - mn1);
            s0 += c[n0][0] + c[n0][1];
            s1 += c[n0][2] + c[n0][3];
        }
        s0 += __shfl_xor_sync(0xffffffffu, s0, 1);
        s0 += __shfl_xor_sync(0xffffffffu, s0, 2);
        s1 += __shfl_xor_sync(0xffffffffu, s1, 1);
        s1 += __shfl_xor_sync(0xffffffffu, s1, 2);
        l0r = l0r * al0 + s0;
        l1r = l1r * al1 + s1;

        #pragma unroll
        for (int n = 0; n < 4; n++) {
            acc[n][0] *= al0; acc[n][1] *= al0;
            acc[n][2] *= al1; acc[n][3] *= al1;
        }

        // ---- PV: P C-frag -> A-frag via shuffles, plain TF32 mma ----
        const int src0 = (g << 2) + (t4 >> 1);
        const int src1 = src0 + 2;
        const bool odd = (t4 & 1);
        const uint32_t* vs = v_s[cur];
        #pragma unroll
        for (int kc = 0; kc < 8; kc++) {
            float e00 = __shfl_sync(0xffffffffu, c[kc][0], src0);
            float e01 = __shfl_sync(0xffffffffu, c[kc][1], src0);
            float e10 = __shfl_sync(0xffffffffu, c[kc][2], src0);
            float e11 = __shfl_sync(0xffffffffu, c[kc][3], src0);
            float e20 = __shfl_sync(0xffffffffu, c[kc][0], src1);
            float e21 = __shfl_sync(0xffffffffu, c[kc][1], src1);
            float e30 = __shfl_sync(0xffffffffu, c[kc][2], src1);
            float e31 = __shfl_sync(0xffffffffu, c[kc][3], src1);
            uint32_t pa0 = f2tf32(odd ? e01 : e00);
            uint32_t pa1 = f2tf32(odd ? e11 : e10);
            uint32_t pa2 = f2tf32(odd ? e21 : e20);
            uint32_t pa3 = f2tf32(odd ? e31 : e30);

            const int vr0 = (kc * 8 + t4) * KVSTR;
            const int vr1 = (kc * 8 + t4 + 4) * KVSTR;
            #pragma unroll
            for (int n = 0; n < 4; n++) {
                uint32_t vb0 = vs[vr0 + n * 8 + g];
                uint32_t vb1 = vs[vr1 + n * 8 + g];
                mma_tf32(acc[n][0], acc[n][1], acc[n][2], acc[n][3],
                         pa0, pa1, pa2, pa3, vb0, vb1);
            }
        }
    }

    // ---- epilogue ----
    const float inv0 = 1.0f / l0r;
    const float inv1 = 1.0f / l1r;
    float* Og = g_att + (size_t)(b * NTOK + qw) * EMBED + h * HD;
    #pragma unroll
    for (int n = 0; n < 4; n++) {
        *(float2*)&Og[(size_t)g * EMBED + n * 8 + 2 * t4] =
            make_float2(acc[n][0] * inv0, acc[n][1] * inv0);
        *(float2*)&Og[(size_t)(g + 8) * EMBED + n * 8 + 2 * t4] =
            make_float2(acc[n][2] * inv1, acc[n][3] * inv1);
    }
}

__global__ void __launch_bounds__(256)
out_gemm(const float* __restrict__ Wout, const float* __restrict__ bout,
         float* __restrict__ out)
{
    gemm_body(g_att, g_lepe, Wout, bout, out,
              blockIdx.y * GEMM_BM, blockIdx.x * GEMM_BN);
}

// ---------------------------------------------------------------------------
extern "C" void kernel_launch(void* const* d_in, const int* in_sizes, int n_in,
                              void* d_out, int out_size)
{
    const float* x      = (const float*)d_in[0];
    const float* sin_t  = (const float*)d_in[1];
    const float* cos_t  = (const float*)d_in[2];
    const float* mask   = (const float*)d_in[3];
    const float* Wq     = (const float*)d_in[4];
    const float* bq     = (const float*)d_in[5];
    const float* Wk     = (const float*)d_in[6];
    const float* bk     = (const float*)d_in[7];
    const float* Wv     = (const float*)d_in[8];
    const float* bv     = (const float*)d_in[9];
    const float* lepe_w = (const float*)d_in[10];
    const float* lepe_b = (const float*)d_in[11];
    const float* Wout   = (const float*)d_in[12];
    const float* bout   = (const float*)d_in[13];
    float* out = (float*)d_out;

    const int M = BATCH * NTOK;   // 9216

    qkv_gemm<<<dim3(768 / GEMM_BN, M / GEMM_BM), 256>>>(x, Wq, bq, Wk, bk, Wv, bv);
    rope_kernel<<<(BATCH * NTOK * (EMBED / 2)) / 256, 256>>>(sin_t, cos_t);
    vt_kernel<<<(BATCH * NTOK * EMBED / 4) / 256, 256>>>();
    lepe_kernel<<<dim3(HH, BATCH), 256>>>(lepe_w, lepe_b);
    attn_kernel<<<dim3(BATCH, NTOK / TQ, HEADS), 256>>>(mask);
    out_gemm<<<dim3(EMBED / GEMM_BN, M / GEMM_BM), 256>>>(Wout, bout, out);
}

// round 7
// speedup vs baseline: 14.5090x; 1.4197x over previous
#include <cuda_runtime.h>
#include <cstdint>

#define EMBED 256
#define HEADS 8
#define HD    32
#define NTOK  2304
#define BATCH 4
#define HH    48
#define WW    48
#define KSCALE 0.17677669529663687f  /* 32^-0.5 */

// Tensor GEMM tiling
#define GBM 128
#define GBN 64
#define GBK 16
#define ASTR 20          // 16 k-words + 4 pad (conflict-free A frag reads)
#define WSTR 72          // 64 n-words + 8 pad (72 mod 32 == 8 -> conflict-free)

// Attention tiling
#define TQ 128
#define TK 64
#define KVSTR 36
#define NKT (NTOK / TK)

// Scratch buffers (allocation-free rule: __device__ globals)
__device__ float g_xt[BATCH * NTOK * EMBED];   // tf32-rounded x
__device__ float g_wt[4 * EMBED * EMBED];      // tf32-rounded Wq,Wk,Wv,Wout
__device__ float g_q[BATCH * NTOK * EMBED];
__device__ float g_k[BATCH * NTOK * EMBED];    // tf32-rounded by rope
__device__ float g_v[BATCH * NTOK * EMBED];    // exact (for lepe)
__device__ float g_vt[BATCH * NTOK * EMBED];   // tf32-rounded for attn
__device__ float g_lepe[BATCH * NTOK * EMBED];
__device__ float g_att[BATCH * NTOK * EMBED];
__device__ float g_ao[BATCH * NTOK * EMBED];   // tf32(att + lepe)

// ---------------------------------------------------------------------------
// Helpers
// ---------------------------------------------------------------------------
__device__ __forceinline__ uint32_t f2tf32(float x) {
    uint32_t r;
    asm("cvt.rna.tf32.f32 %0, %1;" : "=r"(r) : "f"(x));
    return r;
}

__device__ __forceinline__ void mma_tf32(
    float& c0, float& c1, float& c2, float& c3,
    uint32_t a0, uint32_t a1, uint32_t a2, uint32_t a3,
    uint32_t b0, uint32_t b1)
{
    asm("mma.sync.aligned.m16n8k8.row.col.f32.tf32.tf32.f32 "
        "{%0,%1,%2,%3}, {%4,%5,%6,%7}, {%8,%9}, {%0,%1,%2,%3};"
        : "+f"(c0), "+f"(c1), "+f"(c2), "+f"(c3)
        : "r"(a0), "r"(a1), "r"(a2), "r"(a3), "r"(b0), "r"(b1));
}

__device__ __forceinline__ void cp16(uint32_t s_addr, const void* g_ptr) {
    asm volatile("cp.async.ca.shared.global [%0], [%1], 16;"
                 :: "r"(s_addr), "l"(g_ptr));
}

// ---------------------------------------------------------------------------
// Elementwise rounding kernels
// ---------------------------------------------------------------------------
__global__ void __launch_bounds__(256)
round_x(const float* __restrict__ x)
{
    const int i = blockIdx.x * blockDim.x + threadIdx.x;
    float4 v = ((const float4*)x)[i];
    float4 o;
    o.x = __uint_as_float(f2tf32(v.x));
    o.y = __uint_as_float(f2tf32(v.y));
    o.z = __uint_as_float(f2tf32(v.z));
    o.w = __uint_as_float(f2tf32(v.w));
    ((float4*)g_xt)[i] = o;
}

__global__ void __launch_bounds__(256)
round_w(const float* __restrict__ wq, const float* __restrict__ wk,
        const float* __restrict__ wv, const float* __restrict__ wo)
{
    const int mat = blockIdx.y;
    const float* src = (mat == 0) ? wq : (mat == 1) ? wk : (mat == 2) ? wv : wo;
    const int i = blockIdx.x * blockDim.x + threadIdx.x;
    float4 v = ((const float4*)src)[i];
    float4 o;
    o.x = __uint_as_float(f2tf32(v.x));
    o.y = __uint_as_float(f2tf32(v.y));
    o.z = __uint_as_float(f2tf32(v.z));
    o.w = __uint_as_float(f2tf32(v.w));
    ((float4*)(g_wt + (size_t)mat * EMBED * EMBED))[i] = o;
}

__global__ void __launch_bounds__(256)
addrnd_kernel()
{
    const int i = blockIdx.x * blockDim.x + threadIdx.x;
    float4 a = ((const float4*)g_att)[i];
    float4 l = ((const float4*)g_lepe)[i];
    float4 o;
    o.x = __uint_as_float(f2tf32(a.x + l.x));
    o.y = __uint_as_float(f2tf32(a.y + l.y));
    o.z = __uint_as_float(f2tf32(a.z + l.z));
    o.w = __uint_as_float(f2tf32(a.w + l.w));
    ((float4*)g_ao)[i] = o;
}

// tf32-rounded copy of V for attention (lepe keeps exact g_v)
__global__ void __launch_bounds__(256)
vt_kernel()
{
    const int i = blockIdx.x * blockDim.x + threadIdx.x;
    float4 v = ((const float4*)g_v)[i];
    float4 o;
    o.x = __uint_as_float(f2tf32(v.x));
    o.y = __uint_as_float(f2tf32(v.y));
    o.z = __uint_as_float(f2tf32(v.z));
    o.w = __uint_as_float(f2tf32(v.w));
    ((float4*)g_vt)[i] = o;
}

// ---------------------------------------------------------------------------
// TF32 tensor-core GEMM: C[m0:+128, n0:+64] = A @ W + bias
// A [M,256] tf32-rounded row-major, W [256,256] tf32-rounded row-major.
// 8 warps; warp = 16 rows x 64 cols; cp.async double-buffered K (16 steps).
// a_s: [128][20] (16+4 pad), w_s: [16][72] (64+8 pad) — both conflict-free.
// Static smem: 2*(128*20 + 16*72)*4 = 29,696 B.
// ---------------------------------------------------------------------------
__device__ __forceinline__ void gemm_t_body(
    const float* __restrict__ A, const float* __restrict__ W,
    const float* __restrict__ bias, float* __restrict__ C,
    int m0, int n0)
{
    __shared__ uint32_t a_s[2][GBM * ASTR];
    __shared__ uint32_t w_s[2][GBK * WSTR];

    const int tid  = threadIdx.x;
    const int warp = tid >> 5;
    const int lane = tid & 31;
    const int g    = lane >> 2;
    const int t4   = lane & 3;
    const int wrow = warp * 16;

    // loader indices
    const int ar0 = tid >> 2;               // A rows: tid/4 and +64
    const int ac  = (tid & 3) << 2;         // A col chunk (0,4,8,12)
    const int wr  = tid >> 4;               // W row 0..15
    const int wc  = (tid & 15) << 2;        // W col chunk 0..60

    float acc[8][4] = {};

    #define GEMM_ISSUE(kt, buf)                                               \
    {                                                                         \
        cp16((uint32_t)__cvta_generic_to_shared(                              \
                 &a_s[buf][ar0 * ASTR + ac]),                                 \
             &A[(size_t)(m0 + ar0) * EMBED + (kt) * GBK + ac]);               \
        cp16((uint32_t)__cvta_generic_to_shared(                              \
                 &a_s[buf][(ar0 + 64) * ASTR + ac]),                          \
             &A[(size_t)(m0 + ar0 + 64) * EMBED + (kt) * GBK + ac]);          \
        cp16((uint32_t)__cvta_generic_to_shared(                              \
                 &w_s[buf][wr * WSTR + wc]),                                  \
             &W[(size_t)((kt) * GBK + wr) * EMBED + n0 + wc]);                \
        asm volatile("cp.async.commit_group;");                               \
    }

    GEMM_ISSUE(0, 0)

    #pragma unroll 1
    for (int kt = 0; kt < EMBED / GBK; kt++) {
        const int cur = kt & 1;
        asm volatile("cp.async.wait_group 0;");
        __syncthreads();
        if (kt + 1 < EMBED / GBK) GEMM_ISSUE(kt + 1, cur ^ 1)

        uint32_t qa[2][4];
        #pragma unroll
        for (int kc = 0; kc < 2; kc++) {
            qa[kc][0] = a_s[cur][(wrow + g) * ASTR + kc * 8 + t4];
            qa[kc][1] = a_s[cur][(wrow + g + 8) * ASTR + kc * 8 + t4];
            qa[kc][2] = a_s[cur][(wrow + g) * ASTR + kc * 8 + t4 + 4];
            qa[kc][3] = a_s[cur][(wrow + g + 8) * ASTR + kc * 8 + t4 + 4];
        }
        #pragma unroll
        for (int kc = 0; kc < 2; kc++) {
            #pragma unroll
            for (int n = 0; n < 8; n++) {
                uint32_t b0 = w_s[cur][(kc * 8 + t4) * WSTR + n * 8 + g];
                uint32_t b1 = w_s[cur][(kc * 8 + t4 + 4) * WSTR + n * 8 + g];
                mma_tf32(acc[n][0], acc[n][1], acc[n][2], acc[n][3],
                         qa[kc][0], qa[kc][1], qa[kc][2], qa[kc][3], b0, b1);
            }
        }
    }
    #undef GEMM_ISSUE

    #pragma unroll
    for (int n = 0; n < 8; n++) {
        const int col = n0 + n * 8 + 2 * t4;
        const float b0 = bias[col], b1 = bias[col + 1];
        *(float2*)&C[(size_t)(m0 + wrow + g) * EMBED + col] =
            make_float2(acc[n][0] + b0, acc[n][1] + b1);
        *(float2*)&C[(size_t)(m0 + wrow + g + 8) * EMBED + col] =
            make_float2(acc[n][2] + b0, acc[n][3] + b1);
    }
}

__global__ void __launch_bounds__(256, 2)
qkv_gemm_t(const float* __restrict__ bq, const float* __restrict__ bk,
           const float* __restrict__ bv)
{
    const int m0  = blockIdx.y * GBM;
    const int nb  = blockIdx.x;           // 0..11
    const int mat = nb >> 2;
    const int n0  = (nb & 3) * GBN;

    const float* bias;
    float* out;
    if (mat == 0)      { bias = bq; out = g_q; }
    else if (mat == 1) { bias = bk; out = g_k; }
    else               { bias = bv; out = g_v; }

    gemm_t_body(g_xt, g_wt + (size_t)mat * EMBED * EMBED, bias, out, m0, n0);
}

__global__ void __launch_bounds__(256, 2)
out_gemm_t(const float* __restrict__ bout, float* __restrict__ out)
{
    gemm_t_body(g_ao, g_wt + (size_t)3 * EMBED * EMBED, bout, out,
                blockIdx.y * GBM, blockIdx.x * GBN);
}

// ---------------------------------------------------------------------------
// RoPE; K output additionally rounded to tf32 (only attn consumes g_k).
// ---------------------------------------------------------------------------
__global__ void __launch_bounds__(256)
rope_kernel(const float* __restrict__ sin_t, const float* __restrict__ cos_t)
{
    const int idx = blockIdx.x * blockDim.x + threadIdx.x;
    if (idx >= BATCH * NTOK * (EMBED / 2)) return;
    const int row = idx >> 7;
    const int c   = (idx & 127) << 1;
    const int dd  = c & (HD - 1);
    const int pos = row % NTOK;

    const float cs0 = cos_t[pos * HD + dd];
    const float sn0 = sin_t[pos * HD + dd];
    const float cs1 = cos_t[pos * HD + dd + 1];
    const float sn1 = sin_t[pos * HD + dd + 1];

    float2* qp = (float2*)&g_q[(size_t)row * EMBED + c];
    float2 qv = *qp;
    float2 qo;
    qo.x = qv.x * cs0 - qv.y * sn0;
    qo.y = qv.y * cs1 + qv.x * sn1;
    *qp = qo;

    float2* kp = (float2*)&g_k[(size_t)row * EMBED + c];
    float2 kv = *kp;
    float2 ko;
    ko.x = __uint_as_float(f2tf32((kv.x * cs0 - kv.y * sn0) * KSCALE));
    ko.y = __uint_as_float(f2tf32((kv.y * cs1 + kv.x * sn1) * KSCALE));
    *kp = ko;
}

// ---------------------------------------------------------------------------
// LePE: 5x5 depthwise conv, register sliding window; 768 blocks.
// ---------------------------------------------------------------------------
__global__ void __launch_bounds__(256)
lepe_kernel(const float* __restrict__ w, const float* __restrict__ bias)
{
    const int c  = threadIdx.x;
    const int y  = blockIdx.x;
    const int b  = blockIdx.y;
    const int x0 = blockIdx.z * 12;

    float wr[25];
    #pragma unroll
    for (int t = 0; t < 25; t++) wr[t] = w[t * EMBED + c];
    const float bv = bias[c];

    const float* vb = g_v + (size_t)b * NTOK * EMBED;
    float* ob = g_lepe + (size_t)(b * NTOK + y * WW) * EMBED;

    float win[5][5];
    #pragma unroll
    for (int j = 0; j < 4; j++) {
        const int xx = x0 - 2 + j;
        #pragma unroll
        for (int dy = 0; dy < 5; dy++) {
            const int yy = y + dy - 2;
            win[dy][j] = (xx >= 0 && xx < WW && yy >= 0 && yy < HH)
                       ? vb[(size_t)(yy * WW + xx) * EMBED + c] : 0.f;
        }
    }

    #pragma unroll
    for (int i = 0; i < 12; i++) {
        const int x  = x0 + i;
        const int xx = x + 2;
        #pragma unroll
        for (int dy = 0; dy < 5; dy++) {
            const int yy = y + dy - 2;
            win[dy][4] = (xx < WW && yy >= 0 && yy < HH)
                       ? vb[(size_t)(yy * WW + xx) * EMBED + c] : 0.f;
        }
        float sum = bv;
        #pragma unroll
        for (int dy = 0; dy < 5; dy++)
            #pragma unroll
            for (int j = 0; j < 5; j++)
                sum = fmaf(win[dy][j], wr[dy * 5 + j], sum);
        ob[(size_t)x * EMBED + c] = sum;
        #pragma unroll
        for (int dy = 0; dy < 5; dy++)
            #pragma unroll
            for (int j = 0; j < 4; j++)
                win[dy][j] = win[dy][j + 1];
    }
}

// ---------------------------------------------------------------------------
// Attention (unchanged, verified): 1xTF32 QK, cp.async double-buffered K/V,
// mask added after mma, PV via shuffle fragments.
// ---------------------------------------------------------------------------
__global__ void __launch_bounds__(256, 2)
attn_kernel(const float* __restrict__ mask)
{
    __shared__ uint32_t k_s[2][TK * KVSTR];
    __shared__ uint32_t v_s[2][TK * KVSTR];

    const int tid  = threadIdx.x;
    const int warp = tid >> 5;
    const int lane = tid & 31;
    const int g    = lane >> 2;
    const int t4   = lane & 3;

    const int b  = blockIdx.x;
    const int q0 = blockIdx.y * TQ;
    const int h  = blockIdx.z;
    const int qw = q0 + warp * 16;

    const float* Qg = g_q + (size_t)(b * NTOK + qw) * EMBED + h * HD;
    const float* Kg = g_k + (size_t)b * NTOK * EMBED + h * HD;
    const float* Vg = g_vt + (size_t)b * NTOK * EMBED + h * HD;
    const float* Mg = mask + ((size_t)h * NTOK + qw) * NTOK;

    const int lr  = tid >> 2;
    const int lcb = (tid & 3) * 8;

    const uint32_t ks0 = (uint32_t)__cvta_generic_to_shared(&k_s[0][lr * KVSTR + lcb]);
    const uint32_t vs0 = (uint32_t)__cvta_generic_to_shared(&v_s[0][lr * KVSTR + lcb]);
    const uint32_t bufstep = (uint32_t)(TK * KVSTR * 4);

    cp16(ks0,      &Kg[(size_t)lr * EMBED + lcb]);
    cp16(ks0 + 16, &Kg[(size_t)lr * EMBED + lcb + 4]);
    cp16(vs0,      &Vg[(size_t)lr * EMBED + lcb]);
    cp16(vs0 + 16, &Vg[(size_t)lr * EMBED + lcb + 4]);
    asm volatile("cp.async.commit_group;");

    uint32_t qa[4][4];
    #pragma unroll
    for (int kc = 0; kc < 4; kc++) {
        qa[kc][0] = f2tf32(Qg[(size_t)g * EMBED + kc * 8 + t4]);
        qa[kc][1] = f2tf32(Qg[(size_t)(g + 8) * EMBED + kc * 8 + t4]);
        qa[kc][2] = f2tf32(Qg[(size_t)g * EMBED + kc * 8 + t4 + 4]);
        qa[kc][3] = f2tf32(Qg[(size_t)(g + 8) * EMBED + kc * 8 + t4 + 4]);
    }

    float m0r = -1e30f, m1r = -1e30f, l0r = 0.f, l1r = 0.f;
    float acc[4][4] = {};

    for (int it = 0; it < NKT; it++) {
        const int cur = it & 1;
        asm volatile("cp.async.wait_group 0;");
        __syncthreads();

        if (it + 1 < NKT) {
            const size_t go = (size_t)((it + 1) * TK + lr) * EMBED + lcb;
            const uint32_t ks = ks0 + (cur ^ 1) * bufstep;
            const uint32_t vs = vs0 + (cur ^ 1) * bufstep;
            cp16(ks,      &Kg[go]);
            cp16(ks + 16, &Kg[go + 4]);
            cp16(vs,      &Vg[go]);
            cp16(vs + 16, &Vg[go + 4]);
            asm volatile("cp.async.commit_group;");
        } else {
            asm volatile("cp.async.commit_group;");
        }

        const int k0 = it * TK;

        float2 mA[8], mB[8];
        #pragma unroll
        for (int n0 = 0; n0 < 8; n0++) {
            const float* mrow = Mg + (size_t)g * NTOK + k0 + n0 * 8 + 2 * t4;
            mA[n0] = *(const float2*)mrow;
            mB[n0] = *(const float2*)(mrow + 8 * NTOK);
        }

        float c[8][4] = {};
        const uint32_t* ks = k_s[cur];
        #pragma unroll
        for (int kc = 0; kc < 4; kc++) {
            #pragma unroll
            for (int n0 = 0; n0 < 8; n0++) {
                const int krow = n0 * 8 + g;
                uint32_t bh0 = ks[krow * KVSTR + kc * 8 + t4];
                uint32_t bh1 = ks[krow * KVSTR + kc * 8 + t4 + 4];
                mma_tf32(c[n0][0], c[n0][1], c[n0][2], c[n0][3],
                         qa[kc][0], qa[kc][1], qa[kc][2], qa[kc][3],
                         bh0, bh1);
            }
        }
        #pragma unroll
        for (int n0 = 0; n0 < 8; n0++) {
            c[n0][0] += mA[n0].x; c[n0][1] += mA[n0].y;
            c[n0][2] += mB[n0].x; c[n0][3] += mB[n0].y;
        }

        float mx0 = -1e30f, mx1 = -1e30f;
        #pragma unroll
        for (int n0 = 0; n0 < 8; n0++) {
            mx0 = fmaxf(mx0, fmaxf(c[n0][0], c[n0][1]));
            mx1 = fmaxf(mx1, fmaxf(c[n0][2], c[n0][3]));
        }
        mx0 = fmaxf(mx0, __shfl_xor_sync(0xffffffffu, mx0, 1));
        mx0 = fmaxf(mx0, __shfl_xor_sync(0xffffffffu, mx0, 2));
        mx1 = fmaxf(mx1, __shfl_xor_sync(0xffffffffu, mx1, 1));
        mx1 = fmaxf(mx1, __shfl_xor_sync(0xffffffffu, mx1, 2));

        const float mn0 = fmaxf(m0r, mx0);
        const float mn1 = fmaxf(m1r, mx1);
        const float al0 = __expf(m0r - mn0);
        const float al1 = __expf(m1r - mn1);
        m0r = mn0; m1r = mn1;

        float s0 = 0.f, s1 = 0.f;
        #pragma unroll
        for (int n0 = 0; n0 < 8; n0++) {
            c[n0][0] = __expf(c[n0][0] - mn0);
            c[n0][1] = __expf(c[n0][1] - mn0);
            c[n0][2] = __expf(c[n0][2] - mn1);
            c[n0][3] = __expf(c[n0][3] - mn1);
            s0 += c[n0][0] + c[n0][1];
            s1 += c[n0][2] + c[n0][3];
        }
        s0 += __shfl_xor_sync(0xffffffffu, s0, 1);
        s0 += __shfl_xor_sync(0xffffffffu, s0, 2);
        s1 += __shfl_xor_sync(0xffffffffu, s1, 1);
        s1 += __shfl_xor_sync(0xffffffffu, s1, 2);
        l0r = l0r * al0 + s0;
        l1r = l1r * al1 + s1;

        #pragma unroll
        for (int n = 0; n < 4; n++) {
            acc[n][0] *= al0; acc[n][1] *= al0;
            acc[n][2] *= al1; acc[n][3] *= al1;
        }

        const int src0 = (g << 2) + (t4 >> 1);
        const int src1 = src0 + 2;
        const bool odd = (t4 & 1);
        const uint32_t* vs = v_s[cur];
        #pragma unroll
        for (int kc = 0; kc < 8; kc++) {
            float e00 = __shfl_sync(0xffffffffu, c[kc][0], src0);
            float e01 = __shfl_sync(0xffffffffu, c[kc][1], src0);
            float e10 = __shfl_sync(0xffffffffu, c[kc][2], src0);
            float e11 = __shfl_sync(0xffffffffu, c[kc][3], src0);
            float e20 = __shfl_sync(0xffffffffu, c[kc][0], src1);
            float e21 = __shfl_sync(0xffffffffu, c[kc][1], src1);
            float e30 = __shfl_sync(0xffffffffu, c[kc][2], src1);
            float e31 = __shfl_sync(0xffffffffu, c[kc][3], src1);
            uint32_t pa0 = f2tf32(odd ? e01 : e00);
            uint32_t pa1 = f2tf32(odd ? e11 : e10);
            uint32_t pa2 = f2tf32(odd ? e21 : e20);
            uint32_t pa3 = f2tf32(odd ? e31 : e30);

            const int vr0 = (kc * 8 + t4) * KVSTR;
            const int vr1 = (kc * 8 + t4 + 4) * KVSTR;
            #pragma unroll
            for (int n = 0; n < 4; n++) {
                uint32_t vb0 = vs[vr0 + n * 8 + g];
                uint32_t vb1 = vs[vr1 + n * 8 + g];
                mma_tf32(acc[n][0], acc[n][1], acc[n][2], acc[n][3],
                         pa0, pa1, pa2, pa3, vb0, vb1);
            }
        }
    }

    const float inv0 = 1.0f / l0r;
    const float inv1 = 1.0f / l1r;
    float* Og = g_att + (size_t)(b * NTOK + qw) * EMBED + h * HD;
    #pragma unroll
    for (int n = 0; n < 4; n++) {
        *(float2*)&Og[(size_t)g * EMBED + n * 8 + 2 * t4] =
            make_float2(acc[n][0] * inv0, acc[n][1] * inv0);
        *(float2*)&Og[(size_t)(g + 8) * EMBED + n * 8 + 2 * t4] =
            make_float2(acc[n][2] * inv1, acc[n][3] * inv1);
    }
}

// ---------------------------------------------------------------------------
extern "C" void kernel_launch(void* const* d_in, const int* in_sizes, int n_in,
                              void* d_out, int out_size)
{
    const float* x      = (const float*)d_in[0];
    const float* sin_t  = (const float*)d_in[1];
    const float* cos_t  = (const float*)d_in[2];
    const float* mask   = (const float*)d_in[3];
    const float* Wq     = (const float*)d_in[4];
    const float* bq     = (const float*)d_in[5];
    const float* Wk     = (const float*)d_in[6];
    const float* bk     = (const float*)d_in[7];
    const float* Wv     = (const float*)d_in[8];
    const float* bv     = (const float*)d_in[9];
    const float* lepe_w = (const float*)d_in[10];
    const float* lepe_b = (const float*)d_in[11];
    const float* Wout   = (const float*)d_in[12];
    const float* bout   = (const float*)d_in[13];
    float* out = (float*)d_out;

    const int M = BATCH * NTOK;   // 9216

    round_x<<<(M * EMBED / 4) / 256, 256>>>(x);
    round_w<<<dim3((EMBED * EMBED / 4) / 256, 4), 256>>>(Wq, Wk, Wv, Wout);
    qkv_gemm_t<<<dim3(12, M / GBM), 256>>>(bq, bk, bv);
    rope_kernel<<<(M * (EMBED / 2)) / 256, 256>>>(sin_t, cos_t);
    vt_kernel<<<(M * EMBED / 4) / 256, 256>>>();
    lepe_kernel<<<dim3(HH, BATCH, 4), 256>>>(lepe_w, lepe_b);
    attn_kernel<<<dim3(BATCH, NTOK / TQ, HEADS), 256>>>(mask);
    addrnd_kernel<<<(M * EMBED / 4) / 256, 256>>>();
    out_gemm_t<<<dim3(4, M / GBM), 256>>>(bout, out);
}

// round 8
// speedup vs baseline: 19.1897x; 1.3226x over previous
#include <cuda_runtime.h>
#include <cuda_fp16.h>
#include <cstdint>

#define EMBED 256
#define HEADS 8
#define HD    32
#define NTOK  2304
#define BATCH 4
#define HH    48
#define WW    48
#define KSCALE 0.17677669529663687f  /* 32^-0.5 */

// Tensor GEMM tiling
#define GBM 128
#define GBN 64
#define GBK 16
#define ASTR 20
#define WSTR 72

// Attention tiling
#define TQ 128
#define TK 64
#define KVSTR 36
#define VHS   40          // vh_s stride in half2 words
#define NKT (NTOK / TK)

// Scratch buffers (allocation-free rule: __device__ globals)
__device__ float  g_xt[BATCH * NTOK * EMBED];   // tf32-rounded x
__device__ float  g_wt[4 * EMBED * EMBED];      // tf32-rounded Wq,Wk,Wv,Wout
__device__ float  g_q[BATCH * NTOK * EMBED];    // rope'd q (fp32)
__device__ float  g_k[BATCH * NTOK * EMBED];    // rope'd+scaled k, tf32 bits
__device__ float  g_v[BATCH * NTOK * EMBED];    // exact v (for lepe)
__device__ __half g_vh[BATCH * NTOK * EMBED];   // fp16 v (for attn PV)
__device__ float  g_lepe[BATCH * NTOK * EMBED];
__device__ float  g_ao[BATCH * NTOK * EMBED];   // tf32(att + lepe)

// ---------------------------------------------------------------------------
// Helpers
// ---------------------------------------------------------------------------
__device__ __forceinline__ uint32_t f2tf32(float x) {
    uint32_t r;
    asm("cvt.rna.tf32.f32 %0, %1;" : "=r"(r) : "f"(x));
    return r;
}

__device__ __forceinline__ uint32_t pack_h2(float lo, float hi) {
    uint32_t r;   // f16x2: arg order (hi, lo) -> low half = lo
    asm("cvt.rn.f16x2.f32 %0, %1, %2;" : "=r"(r) : "f"(hi), "f"(lo));
    return r;
}

__device__ __forceinline__ void mma_tf32(
    float& c0, float& c1, float& c2, float& c3,
    uint32_t a0, uint32_t a1, uint32_t a2, uint32_t a3,
    uint32_t b0, uint32_t b1)
{
    asm("mma.sync.aligned.m16n8k8.row.col.f32.tf32.tf32.f32 "
        "{%0,%1,%2,%3}, {%4,%5,%6,%7}, {%8,%9}, {%0,%1,%2,%3};"
        : "+f"(c0), "+f"(c1), "+f"(c2), "+f"(c3)
        : "r"(a0), "r"(a1), "r"(a2), "r"(a3), "r"(b0), "r"(b1));
}

__device__ __forceinline__ void mma_f16(
    float& c0, float& c1, float& c2, float& c3,
    uint32_t a0, uint32_t a1, uint32_t a2, uint32_t a3,
    uint32_t b0, uint32_t b1)
{
    asm("mma.sync.aligned.m16n8k16.row.col.f32.f16.f16.f32 "
        "{%0,%1,%2,%3}, {%4,%5,%6,%7}, {%8,%9}, {%0,%1,%2,%3};"
        : "+f"(c0), "+f"(c1), "+f"(c2), "+f"(c3)
        : "r"(a0), "r"(a1), "r"(a2), "r"(a3), "r"(b0), "r"(b1));
}

__device__ __forceinline__ void cp16(uint32_t s_addr, const void* g_ptr) {
    asm volatile("cp.async.ca.shared.global [%0], [%1], 16;"
                 :: "r"(s_addr), "l"(g_ptr));
}

// ---------------------------------------------------------------------------
// Rounding kernels
// ---------------------------------------------------------------------------
__global__ void __launch_bounds__(256)
round_x(const float* __restrict__ x)
{
    const int i = blockIdx.x * blockDim.x + threadIdx.x;
    float4 v = ((const float4*)x)[i];
    float4 o;
    o.x = __uint_as_float(f2tf32(v.x));
    o.y = __uint_as_float(f2tf32(v.y));
    o.z = __uint_as_float(f2tf32(v.z));
    o.w = __uint_as_float(f2tf32(v.w));
    ((float4*)g_xt)[i] = o;
}

__global__ void __launch_bounds__(256)
round_w(const float* __restrict__ wq, const float* __restrict__ wk,
        const float* __restrict__ wv, const float* __restrict__ wo)
{
    const int mat = blockIdx.y;
    const float* src = (mat == 0) ? wq : (mat == 1) ? wk : (mat == 2) ? wv : wo;
    const int i = blockIdx.x * blockDim.x + threadIdx.x;
    float4 v = ((const float4*)src)[i];
    float4 o;
    o.x = __uint_as_float(f2tf32(v.x));
    o.y = __uint_as_float(f2tf32(v.y));
    o.z = __uint_as_float(f2tf32(v.z));
    o.w = __uint_as_float(f2tf32(v.w));
    ((float4*)(g_wt + (size_t)mat * EMBED * EMBED))[i] = o;
}

// ---------------------------------------------------------------------------
// TF32 tensor GEMM with fused epilogues.
// mode 0: plain bias add (out proj, writes to C)
// mode 1: q — bias + rope rotation
// mode 2: k — bias + rope + KSCALE + tf32 round
// mode 3: v — bias; writes exact fp32 to C AND fp16 to Ch
// ---------------------------------------------------------------------------
__device__ __forceinline__ void gemm_t_body(
    const float* __restrict__ A, const float* __restrict__ W,
    const float* __restrict__ bias, float* __restrict__ C,
    int m0, int n0, int mode,
    const float* __restrict__ sin_t, const float* __restrict__ cos_t,
    __half* __restrict__ Ch)
{
    __shared__ __align__(16) uint32_t a_s[2][GBM * ASTR];
    __shared__ __align__(16) uint32_t w_s[2][GBK * WSTR];

    const int tid  = threadIdx.x;
    const int warp = tid >> 5;
    const int lane = tid & 31;
    const int g    = lane >> 2;
    const int t4   = lane & 3;
    const int wrow = warp * 16;

    const int ar0 = tid >> 2;
    const int ac  = (tid & 3) << 2;
    const int wr  = tid >> 4;
    const int wc  = (tid & 15) << 2;

    float acc[8][4] = {};

    #define GEMM_ISSUE(kt, buf)                                               \
    {                                                                         \
        cp16((uint32_t)__cvta_generic_to_shared(                              \
                 &a_s[buf][ar0 * ASTR + ac]),                                 \
             &A[(size_t)(m0 + ar0) * EMBED + (kt) * GBK + ac]);               \
        cp16((uint32_t)__cvta_generic_to_shared(                              \
                 &a_s[buf][(ar0 + 64) * ASTR + ac]),                          \
             &A[(size_t)(m0 + ar0 + 64) * EMBED + (kt) * GBK + ac]);          \
        cp16((uint32_t)__cvta_generic_to_shared(                              \
                 &w_s[buf][wr * WSTR + wc]),                                  \
             &W[(size_t)((kt) * GBK + wr) * EMBED + n0 + wc]);                \
        asm volatile("cp.async.commit_group;");                               \
    }

    GEMM_ISSUE(0, 0)

    #pragma unroll 1
    for (int kt = 0; kt < EMBED / GBK; kt++) {
        const int cur = kt & 1;
        asm volatile("cp.async.wait_group 0;");
        __syncthreads();
        if (kt + 1 < EMBED / GBK) GEMM_ISSUE(kt + 1, cur ^ 1)

        uint32_t qa[2][4];
        #pragma unroll
        for (int kc = 0; kc < 2; kc++) {
            qa[kc][0] = a_s[cur][(wrow + g) * ASTR + kc * 8 + t4];
            qa[kc][1] = a_s[cur][(wrow + g + 8) * ASTR + kc * 8 + t4];
            qa[kc][2] = a_s[cur][(wrow + g) * ASTR + kc * 8 + t4 + 4];
            qa[kc][3] = a_s[cur][(wrow + g + 8) * ASTR + kc * 8 + t4 + 4];
        }
        #pragma unroll
        for (int kc = 0; kc < 2; kc++) {
            #pragma unroll
            for (int n = 0; n < 8; n++) {
                uint32_t b0 = w_s[cur][(kc * 8 + t4) * WSTR + n * 8 + g];
                uint32_t b1 = w_s[cur][(kc * 8 + t4 + 4) * WSTR + n * 8 + g];
                mma_tf32(acc[n][0], acc[n][1], acc[n][2], acc[n][3],
                         qa[kc][0], qa[kc][1], qa[kc][2], qa[kc][3], b0, b1);
            }
        }
    }
    #undef GEMM_ISSUE

    const int row0 = m0 + wrow + g;
    const int row1 = row0 + 8;
    const int pos0 = row0 % NTOK;
    const int pos1 = row1 % NTOK;

    #pragma unroll
    for (int n = 0; n < 8; n++) {
        const int col = n0 + n * 8 + 2 * t4;      // always even
        const float b0 = bias[col], b1 = bias[col + 1];
        float e0 = acc[n][0] + b0, o0 = acc[n][1] + b1;
        float e1 = acc[n][2] + b0, o1 = acc[n][3] + b1;

        if (mode == 1 || mode == 2) {
            const int dd = col & (HD - 1);
            float2 cs0 = *(const float2*)&cos_t[pos0 * HD + dd];
            float2 sn0 = *(const float2*)&sin_t[pos0 * HD + dd];
            float2 cs1 = *(const float2*)&cos_t[pos1 * HD + dd];
            float2 sn1 = *(const float2*)&sin_t[pos1 * HD + dd];
            float r0e = e0 * cs0.x - o0 * sn0.x;
            float r0o = o0 * cs0.y + e0 * sn0.y;
            float r1e = e1 * cs1.x - o1 * sn1.x;
            float r1o = o1 * cs1.y + e1 * sn1.y;
            if (mode == 2) {
                r0e = __uint_as_float(f2tf32(r0e * KSCALE));
                r0o = __uint_as_float(f2tf32(r0o * KSCALE));
                r1e = __uint_as_float(f2tf32(r1e * KSCALE));
                r1o = __uint_as_float(f2tf32(r1o * KSCALE));
            }
            e0 = r0e; o0 = r0o; e1 = r1e; o1 = r1o;
        }

        *(float2*)&C[(size_t)row0 * EMBED + col] = make_float2(e0, o0);
        *(float2*)&C[(size_t)row1 * EMBED + col] = make_float2(e1, o1);
        if (mode == 3) {
            *(uint32_t*)&Ch[(size_t)row0 * EMBED + col] = pack_h2(e0, o0);
            *(uint32_t*)&Ch[(size_t)row1 * EMBED + col] = pack_h2(e1, o1);
        }
    }
}

__global__ void __launch_bounds__(256, 2)
qkv_gemm_t(const float* __restrict__ bq, const float* __restrict__ bk,
           const float* __restrict__ bv,
           const float* __restrict__ sin_t, const float* __restrict__ cos_t)
{
    const int m0  = blockIdx.y * GBM;
    const int nb  = blockIdx.x;
    const int mat = nb >> 2;
    const int n0  = (nb & 3) * GBN;

    if (mat == 0)
        gemm_t_body(g_xt, g_wt, bq, g_q, m0, n0, 1, sin_t, cos_t, nullptr);
    else if (mat == 1)
        gemm_t_body(g_xt, g_wt + (size_t)EMBED * EMBED, bk, g_k,
                    m0, n0, 2, sin_t, cos_t, nullptr);
    else
        gemm_t_body(g_xt, g_wt + (size_t)2 * EMBED * EMBED, bv, g_v,
                    m0, n0, 3, nullptr, nullptr, g_vh);
}

__global__ void __launch_bounds__(256, 2)
out_gemm_t(const float* __restrict__ bout, float* __restrict__ out)
{
    gemm_t_body(g_ao, g_wt + (size_t)3 * EMBED * EMBED, bout, out,
                blockIdx.y * GBM, blockIdx.x * GBN, 0,
                nullptr, nullptr, nullptr);
}

// ---------------------------------------------------------------------------
// LePE: 5x5 depthwise conv, register sliding window; 768 blocks.
// ---------------------------------------------------------------------------
__global__ void __launch_bounds__(256)
lepe_kernel(const float* __restrict__ w, const float* __restrict__ bias)
{
    const int c  = threadIdx.x;
    const int y  = blockIdx.x;
    const int b  = blockIdx.y;
    const int x0 = blockIdx.z * 12;

    float wr[25];
    #pragma unroll
    for (int t = 0; t < 25; t++) wr[t] = w[t * EMBED + c];
    const float bv = bias[c];

    const float* vb = g_v + (size_t)b * NTOK * EMBED;
    float* ob = g_lepe + (size_t)(b * NTOK + y * WW) * EMBED;

    float win[5][5];
    #pragma unroll
    for (int j = 0; j < 4; j++) {
        const int xx = x0 - 2 + j;
        #pragma unroll
        for (int dy = 0; dy < 5; dy++) {
            const int yy = y + dy - 2;
            win[dy][j] = (xx >= 0 && xx < WW && yy >= 0 && yy < HH)
                       ? vb[(size_t)(yy * WW + xx) * EMBED + c] : 0.f;
        }
    }

    #pragma unroll
    for (int i = 0; i < 12; i++) {
        const int x  = x0 + i;
        const int xx = x + 2;
        #pragma unroll
        for (int dy = 0; dy < 5; dy++) {
            const int yy = y + dy - 2;
            win[dy][4] = (xx < WW && yy >= 0 && yy < HH)
                       ? vb[(size_t)(yy * WW + xx) * EMBED + c] : 0.f;
        }
        float sum = bv;
        #pragma unroll
        for (int dy = 0; dy < 5; dy++)
            #pragma unroll
            for (int j = 0; j < 5; j++)
                sum = fmaf(win[dy][j], wr[dy * 5 + j], sum);
        ob[(size_t)x * EMBED + c] = sum;
        #pragma unroll
        for (int dy = 0; dy < 5; dy++)
            #pragma unroll
            for (int j = 0; j < 4; j++)
                win[dy][j] = win[dy][j + 1];
    }
}

// ---------------------------------------------------------------------------
// Attention v6: 1xTF32 QK + fp16 m16n8k16 PV (flash-attn fragment trick:
// QK C-frags pack directly into PV A-frags — zero shuffles). V staged as
// key-paired half2 in smem (PRMT interleave, stride 40 conflict-free).
// Epilogue fuses +lepe and tf32 rounding into g_ao.
// ---------------------------------------------------------------------------
__global__ void __launch_bounds__(256, 2)
attn_kernel(const float* __restrict__ mask)
{
    __shared__ __align__(16) uint32_t k_s[2][TK * KVSTR];
    __shared__ __align__(16) uint32_t vh_s[2][32 * VHS];

    const int tid  = threadIdx.x;
    const int warp = tid >> 5;
    const int lane = tid & 31;
    const int g    = lane >> 2;
    const int t4   = lane & 3;

    const int b  = blockIdx.x;
    const int q0 = blockIdx.y * TQ;
    const int h  = blockIdx.z;
    const int qw = q0 + warp * 16;

    const float*  Qg = g_q + (size_t)(b * NTOK + qw) * EMBED + h * HD;
    const float*  Kg = g_k + (size_t)b * NTOK * EMBED + h * HD;
    const __half* Vg = g_vh + (size_t)b * NTOK * EMBED + h * HD;
    const float*  Mg = mask + ((size_t)h * NTOK + qw) * NTOK;

    // K loader: 64 rows x 32 dims via cp.async
    const int lr  = tid >> 2;
    const int lcb = (tid & 3) * 8;
    // V loader: pair vr (rows 2vr,2vr+1), dims vdc..vdc+3
    const int vr  = tid >> 3;
    const int vdc = (tid & 7) * 4;

    const uint32_t ks0 = (uint32_t)__cvta_generic_to_shared(&k_s[0][lr * KVSTR + lcb]);
    const uint32_t kbufstep = (uint32_t)(TK * KVSTR * 4);

    // prologue: K tile 0 (cp.async), V tile 0 (LDG to regs)
    cp16(ks0,      &Kg[(size_t)lr * EMBED + lcb]);
    cp16(ks0 + 16, &Kg[(size_t)lr * EMBED + lcb + 4]);
    asm volatile("cp.async.commit_group;");
    uint2 va = *(const uint2*)&Vg[(size_t)(2 * vr) * EMBED + vdc];
    uint2 vb = *(const uint2*)&Vg[(size_t)(2 * vr + 1) * EMBED + vdc];

    // Q fragments, single tf32 rounding
    uint32_t qa[4][4];
    #pragma unroll
    for (int kc = 0; kc < 4; kc++) {
        qa[kc][0] = f2tf32(Qg[(size_t)g * EMBED + kc * 8 + t4]);
        qa[kc][1] = f2tf32(Qg[(size_t)(g + 8) * EMBED + kc * 8 + t4]);
        qa[kc][2] = f2tf32(Qg[(size_t)g * EMBED + kc * 8 + t4 + 4]);
        qa[kc][3] = f2tf32(Qg[(size_t)(g + 8) * EMBED + kc * 8 + t4 + 4]);
    }

    float m0r = -1e30f, m1r = -1e30f, l0r = 0.f, l1r = 0.f;
    float acc[4][4] = {};

    for (int it = 0; it < NKT; it++) {
        const int cur = it & 1;
        asm volatile("cp.async.wait_group 0;");

        // interleave + store V(it) as key-paired half2
        {
            uint32_t h0, h1, h2, h3;
            asm("prmt.b32 %0, %1, %2, 0x5410;" : "=r"(h0) : "r"(va.x), "r"(vb.x));
            asm("prmt.b32 %0, %1, %2, 0x7632;" : "=r"(h1) : "r"(va.x), "r"(vb.x));
            asm("prmt.b32 %0, %1, %2, 0x5410;" : "=r"(h2) : "r"(va.y), "r"(vb.y));
            asm("prmt.b32 %0, %1, %2, 0x7632;" : "=r"(h3) : "r"(va.y), "r"(vb.y));
            *(uint4*)&vh_s[cur][vr * VHS + vdc] = make_uint4(h0, h1, h2, h3);
        }
        __syncthreads();   // K(it) + V(it) visible; old buffers free

        if (it + 1 < NKT) {
            const size_t go = (size_t)((it + 1) * TK + lr) * EMBED + lcb;
            const uint32_t ks = ks0 + (cur ^ 1) * kbufstep;
            cp16(ks,      &Kg[go]);
            cp16(ks + 16, &Kg[go + 4]);
            asm volatile("cp.async.commit_group;");
            va = *(const uint2*)&Vg[(size_t)((it + 1) * TK + 2 * vr) * EMBED + vdc];
            vb = *(const uint2*)&Vg[(size_t)((it + 1) * TK + 2 * vr + 1) * EMBED + vdc];
        } else {
            asm volatile("cp.async.commit_group;");
        }

        const int k0 = it * TK;

        float2 mA[8], mB[8];
        #pragma unroll
        for (int n0 = 0; n0 < 8; n0++) {
            const float* mrow = Mg + (size_t)g * NTOK + k0 + n0 * 8 + 2 * t4;
            mA[n0] = *(const float2*)mrow;
            mB[n0] = *(const float2*)(mrow + 8 * NTOK);
        }

        float c[8][4] = {};
        const uint32_t* ks = k_s[cur];
        #pragma unroll
        for (int kc = 0; kc < 4; kc++) {
            #pragma unroll
            for (int n0 = 0; n0 < 8; n0++) {
                const int krow = n0 * 8 + g;
                uint32_t bh0 = ks[krow * KVSTR + kc * 8 + t4];
                uint32_t bh1 = ks[krow * KVSTR + kc * 8 + t4 + 4];
                mma_tf32(c[n0][0], c[n0][1], c[n0][2], c[n0][3],
                         qa[kc][0], qa[kc][1], qa[kc][2], qa[kc][3],
                         bh0, bh1);
            }
        }
        #pragma unroll
        for (int n0 = 0; n0 < 8; n0++) {
            c[n0][0] += mA[n0].x; c[n0][1] += mA[n0].y;
            c[n0][2] += mB[n0].x; c[n0][3] += mB[n0].y;
        }

        float mx0 = -1e30f, mx1 = -1e30f;
        #pragma unroll
        for (int n0 = 0; n0 < 8; n0++) {
            mx0 = fmaxf(mx0, fmaxf(c[n0][0], c[n0][1]));
            mx1 = fmaxf(mx1, fmaxf(c[n0][2], c[n0][3]));
        }
        mx0 = fmaxf(mx0, __shfl_xor_sync(0xffffffffu, mx0, 1));
        mx0 = fmaxf(mx0, __shfl_xor_sync(0xffffffffu, mx0, 2));
        mx1 = fmaxf(mx1, __shfl_xor_sync(0xffffffffu, mx1, 1));
        mx1 = fmaxf(mx1, __shfl_xor_sync(0xffffffffu, mx1, 2));

        const float mn0 = fmaxf(m0r, mx0);
        const float mn1 = fmaxf(m1r, mx1);
        const float al0 = __expf(m0r - mn0);
        const float al1 = __expf(m1r - mn1);
        m0r = mn0; m1r = mn1;

        float s0 = 0.f, s1 = 0.f;
        #pragma unroll
        for (int n0 = 0; n0 < 8; n0++) {
            c[n0][0] = __expf(c[n0][0] - mn0);
            c[n0][1] = __expf(c[n0][1] - mn0);
            c[n0][2] = __expf(c[n0][2] - mn1);
            c[n0][3] = __expf(c[n0][3] - mn1);
            s0 += c[n0][0] + c[n0][1];
            s1 += c[n0][2] + c[n0][3];
        }
        s0 += __shfl_xor_sync(0xffffffffu, s0, 1);
        s0 += __shfl_xor_sync(0xffffffffu, s0, 2);
        s1 += __shfl_xor_sync(0xffffffffu, s1, 1);
        s1 += __shfl_xor_sync(0xffffffffu, s1, 2);
        l0r = l0r * al0 + s0;
        l1r = l1r * al1 + s1;

        #pragma unroll
        for (int n = 0; n < 4; n++) {
            acc[n][0] *= al0; acc[n][1] *= al0;
            acc[n][2] *= al1; acc[n][3] *= al1;
        }

        // ---- PV fp16: C-frag -> A-frag direct pack, V pairs from smem ----
        const uint32_t* vs = vh_s[cur];
        #pragma unroll
        for (int kc = 0; kc < 4; kc++) {
            uint32_t pa0 = pack_h2(c[2 * kc][0],     c[2 * kc][1]);
            uint32_t pa1 = pack_h2(c[2 * kc][2],     c[2 * kc][3]);
            uint32_t pa2 = pack_h2(c[2 * kc + 1][0], c[2 * kc + 1][1]);
            uint32_t pa3 = pack_h2(c[2 * kc + 1][2], c[2 * kc + 1][3]);
            const int p0 = (8 * kc + t4) * VHS;
            const int p1 = (8 * kc + t4 + 4) * VHS;
            #pragma unroll
            for (int n = 0; n < 4; n++) {
                uint32_t b0 = vs[p0 + n * 8 + g];
                uint32_t b1 = vs[p1 + n * 8 + g];
                mma_f16(acc[n][0], acc[n][1], acc[n][2], acc[n][3],
                        pa0, pa1, pa2, pa3, b0, b1);
            }
        }
    }

    // ---- epilogue: /l, +lepe, tf32 round, write g_ao ----
    const float inv0 = 1.0f / l0r;
    const float inv1 = 1.0f / l1r;
    const float* Lg = g_lepe + (size_t)(b * NTOK + qw) * EMBED + h * HD;
    float* Og = g_ao + (size_t)(b * NTOK + qw) * EMBED + h * HD;
    #pragma unroll
    for (int n = 0; n < 4; n++) {
        const int off = n * 8 + 2 * t4;
        float2 lp0 = *(const float2*)&Lg[(size_t)g * EMBED + off];
        float2 lp1 = *(const float2*)&Lg[(size_t)(g + 8) * EMBED + off];
        float2 o0, o1;
        o0.x = __uint_as_float(f2tf32(acc[n][0] * inv0 + lp0.x));
        o0.y = __uint_as_float(f2tf32(acc[n][1] * inv0 + lp0.y));
        o1.x = __uint_as_float(f2tf32(acc[n][2] * inv1 + lp1.x));
        o1.y = __uint_as_float(f2tf32(acc[n][3] * inv1 + lp1.y));
        *(float2*)&Og[(size_t)g * EMBED + off] = o0;
        *(float2*)&Og[(size_t)(g + 8) * EMBED + off] = o1;
    }
}

// ---------------------------------------------------------------------------
extern "C" void kernel_launch(void* const* d_in, const int* in_sizes, int n_in,
                              void* d_out, int out_size)
{
    const float* x      = (const float*)d_in[0];
    const float* sin_t  = (const float*)d_in[1];
    const float* cos_t  = (const float*)d_in[2];
    const float* mask   = (const float*)d_in[3];
    const float* bq     = (const float*)d_in[5];
    const float* bk     = (const float*)d_in[7];
    const float* bv     = (const float*)d_in[9];
    const float* lepe_w = (const float*)d_in[10];
    const float* lepe_b = (const float*)d_in[11];
    const float* bout   = (const float*)d_in[13];
    float* out = (float*)d_out;

    const int M = BATCH * NTOK;   // 9216

    round_x<<<(M * EMBED / 4) / 256, 256>>>(x);
    round_w<<<dim3((EMBED * EMBED / 4) / 256, 4), 256>>>(
        (const float*)d_in[4], (const float*)d_in[6],
        (const float*)d_in[8], (const float*)d_in[12]);
    qkv_gemm_t<<<dim3(12, M / GBM), 256>>>(bq, bk, bv, sin_t, cos_t);
    lepe_kernel<<<dim3(HH, BATCH, 4), 256>>>(lepe_w, lepe_b);
    attn_kernel<<<dim3(BATCH, NTOK / TQ, HEADS), 256>>>(mask);
    out_gemm_t<<<dim3(4, M / GBM), 256>>>(bout, out);
}

// round 9
// speedup vs baseline: 20.9444x; 1.0914x over previous
#include <cuda_runtime.h>
#include <cuda_fp16.h>
#include <cstdint>

#define EMBED 256
#define HEADS 8
#define HD    32
#define NTOK  2304
#define BATCH 4
#define HH    48
#define WW    48
#define KSCALE 0.17677669529663687f  /* 32^-0.5 */

// Tensor GEMM tiling
#define GBM 128
#define GBN 64
#define GBK 32
#define ASTR 36          // 32 + 4 pad
#define WSTR 72          // 64 + 8 pad
#define GEMM_SMEM ((2 * GBM * ASTR + 2 * GBK * WSTR) * 4)

// Attention tiling
#define TQ 128
#define TK 64
#define KVSTR 36
#define VHS   40
#define NKT (NTOK / TK)

// Scratch buffers (allocation-free rule: __device__ globals)
__device__ float  g_xt[BATCH * NTOK * EMBED];
__device__ float  g_wt[4 * EMBED * EMBED];
__device__ float  g_q[BATCH * NTOK * EMBED];
__device__ float  g_k[BATCH * NTOK * EMBED];
__device__ float  g_v[BATCH * NTOK * EMBED];
__device__ __half g_vh[BATCH * NTOK * EMBED];
__device__ float  g_lepe[BATCH * NTOK * EMBED];
__device__ float  g_ao[BATCH * NTOK * EMBED];

// ---------------------------------------------------------------------------
// Helpers
// ---------------------------------------------------------------------------
__device__ __forceinline__ uint32_t f2tf32(float x) {
    uint32_t r;
    asm("cvt.rna.tf32.f32 %0, %1;" : "=r"(r) : "f"(x));
    return r;
}

__device__ __forceinline__ uint32_t pack_h2(float lo, float hi) {
    uint32_t r;
    asm("cvt.rn.f16x2.f32 %0, %1, %2;" : "=r"(r) : "f"(hi), "f"(lo));
    return r;
}

__device__ __forceinline__ void mma_tf32(
    float& c0, float& c1, float& c2, float& c3,
    uint32_t a0, uint32_t a1, uint32_t a2, uint32_t a3,
    uint32_t b0, uint32_t b1)
{
    asm("mma.sync.aligned.m16n8k8.row.col.f32.tf32.tf32.f32 "
        "{%0,%1,%2,%3}, {%4,%5,%6,%7}, {%8,%9}, {%0,%1,%2,%3};"
        : "+f"(c0), "+f"(c1), "+f"(c2), "+f"(c3)
        : "r"(a0), "r"(a1), "r"(a2), "r"(a3), "r"(b0), "r"(b1));
}

__device__ __forceinline__ void mma_f16(
    float& c0, float& c1, float& c2, float& c3,
    uint32_t a0, uint32_t a1, uint32_t a2, uint32_t a3,
    uint32_t b0, uint32_t b1)
{
    asm("mma.sync.aligned.m16n8k16.row.col.f32.f16.f16.f32 "
        "{%0,%1,%2,%3}, {%4,%5,%6,%7}, {%8,%9}, {%0,%1,%2,%3};"
        : "+f"(c0), "+f"(c1), "+f"(c2), "+f"(c3)
        : "r"(a0), "r"(a1), "r"(a2), "r"(a3), "r"(b0), "r"(b1));
}

__device__ __forceinline__ void cp16(uint32_t s_addr, const void* g_ptr) {
    asm volatile("cp.async.ca.shared.global [%0], [%1], 16;"
                 :: "r"(s_addr), "l"(g_ptr));
}

// ---------------------------------------------------------------------------
// Rounding kernels
// ---------------------------------------------------------------------------
__global__ void __launch_bounds__(256)
round_x(const float* __restrict__ x)
{
    const int i = blockIdx.x * blockDim.x + threadIdx.x;
    float4 v = ((const float4*)x)[i];
    float4 o;
    o.x = __uint_as_float(f2tf32(v.x));
    o.y = __uint_as_float(f2tf32(v.y));
    o.z = __uint_as_float(f2tf32(v.z));
    o.w = __uint_as_float(f2tf32(v.w));
    ((float4*)g_xt)[i] = o;
}

__global__ void __launch_bounds__(256)
round_w(const float* __restrict__ wq, const float* __restrict__ wk,
        const float* __restrict__ wv, const float* __restrict__ wo)
{
    const int mat = blockIdx.y;
    const float* src = (mat == 0) ? wq : (mat == 1) ? wk : (mat == 2) ? wv : wo;
    const int i = blockIdx.x * blockDim.x + threadIdx.x;
    float4 v = ((const float4*)src)[i];
    float4 o;
    o.x = __uint_as_float(f2tf32(v.x));
    o.y = __uint_as_float(f2tf32(v.y));
    o.z = __uint_as_float(f2tf32(v.z));
    o.w = __uint_as_float(f2tf32(v.w));
    ((float4*)(g_wt + (size_t)mat * EMBED * EMBED))[i] = o;
}

// ---------------------------------------------------------------------------
// TF32 tensor GEMM (GBK=32, dynamic smem, 8 mainloop iters).
// mode 0: bias add; 1: q rope; 2: k rope+scale+tf32; 3: v + fp16 copy.
// ---------------------------------------------------------------------------
__device__ __forceinline__ void gemm_t_body(
    const float* __restrict__ A, const float* __restrict__ W,
    const float* __restrict__ bias, float* __restrict__ C,
    int m0, int n0, int mode,
    const float* __restrict__ sin_t, const float* __restrict__ cos_t,
    __half* __restrict__ Ch)
{
    extern __shared__ __align__(16) uint32_t dynsmem[];
    uint32_t* a_s = dynsmem;                   // [2][GBM*ASTR]
    uint32_t* w_s = dynsmem + 2 * GBM * ASTR;  // [2][GBK*WSTR]

    const int tid  = threadIdx.x;
    const int warp = tid >> 5;
    const int lane = tid & 31;
    const int g    = lane >> 2;
    const int t4   = lane & 3;
    const int wrow = warp * 16;

    float acc[8][4] = {};

    #define GEMM_ISSUE(kt, buf)                                               \
    {                                                                         \
        _Pragma("unroll")                                                     \
        for (int j = 0; j < 4; j++) {                                         \
            const int idx = j * 256 + tid;                                    \
            const int r = idx >> 3, c4 = (idx & 7) << 2;                      \
            cp16((uint32_t)__cvta_generic_to_shared(                          \
                     &a_s[(buf) * (GBM * ASTR) + r * ASTR + c4]),             \
                 &A[(size_t)(m0 + r) * EMBED + (kt) * GBK + c4]);             \
        }                                                                     \
        _Pragma("unroll")                                                     \
        for (int j = 0; j < 2; j++) {                                         \
            const int idx = j * 256 + tid;                                    \
            const int r = idx >> 4, c4 = (idx & 15) << 2;                     \
            cp16((uint32_t)__cvta_generic_to_shared(                          \
                     &w_s[(buf) * (GBK * WSTR) + r * WSTR + c4]),             \
                 &W[(size_t)((kt) * GBK + r) * EMBED + n0 + c4]);             \
        }                                                                     \
        asm volatile("cp.async.commit_group;");                               \
    }

    GEMM_ISSUE(0, 0)

    #pragma unroll 1
    for (int kt = 0; kt < EMBED / GBK; kt++) {
        const int cur = kt & 1;
        asm volatile("cp.async.wait_group 0;");
        __syncthreads();
        if (kt + 1 < EMBED / GBK) GEMM_ISSUE(kt + 1, cur ^ 1)

        const uint32_t* ab = a_s + cur * (GBM * ASTR);
        const uint32_t* wb = w_s + cur * (GBK * WSTR);
        #pragma unroll
        for (int kc = 0; kc < 4; kc++) {
            uint32_t qa[4];
            qa[0] = ab[(wrow + g) * ASTR + kc * 8 + t4];
            qa[1] = ab[(wrow + g + 8) * ASTR + kc * 8 + t4];
            qa[2] = ab[(wrow + g) * ASTR + kc * 8 + t4 + 4];
            qa[3] = ab[(wrow + g + 8) * ASTR + kc * 8 + t4 + 4];
            #pragma unroll
            for (int n = 0; n < 8; n++) {
                uint32_t b0 = wb[(kc * 8 + t4) * WSTR + n * 8 + g];
                uint32_t b1 = wb[(kc * 8 + t4 + 4) * WSTR + n * 8 + g];
                mma_tf32(acc[n][0], acc[n][1], acc[n][2], acc[n][3],
                         qa[0], qa[1], qa[2], qa[3], b0, b1);
            }
        }
    }
    #undef GEMM_ISSUE

    const int row0 = m0 + wrow + g;
    const int row1 = row0 + 8;
    const int pos0 = row0 % NTOK;
    const int pos1 = row1 % NTOK;

    #pragma unroll
    for (int n = 0; n < 8; n++) {
        const int col = n0 + n * 8 + 2 * t4;
        const float b0 = bias[col], b1 = bias[col + 1];
        float e0 = acc[n][0] + b0, o0 = acc[n][1] + b1;
        float e1 = acc[n][2] + b0, o1 = acc[n][3] + b1;

        if (mode == 1 || mode == 2) {
            const int dd = col & (HD - 1);
            float2 cs0 = *(const float2*)&cos_t[pos0 * HD + dd];
            float2 sn0 = *(const float2*)&sin_t[pos0 * HD + dd];
            float2 cs1 = *(const float2*)&cos_t[pos1 * HD + dd];
            float2 sn1 = *(const float2*)&sin_t[pos1 * HD + dd];
            float r0e = e0 * cs0.x - o0 * sn0.x;
            float r0o = o0 * cs0.y + e0 * sn0.y;
            float r1e = e1 * cs1.x - o1 * sn1.x;
            float r1o = o1 * cs1.y + e1 * sn1.y;
            if (mode == 2) {
                r0e = __uint_as_float(f2tf32(r0e * KSCALE));
                r0o = __uint_as_float(f2tf32(r0o * KSCALE));
                r1e = __uint_as_float(f2tf32(r1e * KSCALE));
                r1o = __uint_as_float(f2tf32(r1o * KSCALE));
            }
            e0 = r0e; o0 = r0o; e1 = r1e; o1 = r1o;
        }

        *(float2*)&C[(size_t)row0 * EMBED + col] = make_float2(e0, o0);
        *(float2*)&C[(size_t)row1 * EMBED + col] = make_float2(e1, o1);
        if (mode == 3) {
            *(uint32_t*)&Ch[(size_t)row0 * EMBED + col] = pack_h2(e0, o0);
            *(uint32_t*)&Ch[(size_t)row1 * EMBED + col] = pack_h2(e1, o1);
        }
    }
}

__global__ void __launch_bounds__(256, 2)
qkv_gemm_t(const float* __restrict__ bq, const float* __restrict__ bk,
           const float* __restrict__ bv,
           const float* __restrict__ sin_t, const float* __restrict__ cos_t)
{
    const int m0  = blockIdx.y * GBM;
    const int nb  = blockIdx.x;
    const int mat = nb >> 2;
    const int n0  = (nb & 3) * GBN;

    if (mat == 0)
        gemm_t_body(g_xt, g_wt, bq, g_q, m0, n0, 1, sin_t, cos_t, nullptr);
    else if (mat == 1)
        gemm_t_body(g_xt, g_wt + (size_t)EMBED * EMBED, bk, g_k,
                    m0, n0, 2, sin_t, cos_t, nullptr);
    else
        gemm_t_body(g_xt, g_wt + (size_t)2 * EMBED * EMBED, bv, g_v,
                    m0, n0, 3, nullptr, nullptr, g_vh);
}

__global__ void __launch_bounds__(256, 2)
out_gemm_t(const float* __restrict__ bout, float* __restrict__ out)
{
    gemm_t_body(g_ao, g_wt + (size_t)3 * EMBED * EMBED, bout, out,
                blockIdx.y * GBM, blockIdx.x * GBN, 0,
                nullptr, nullptr, nullptr);
}

// ---------------------------------------------------------------------------
// LePE: 5x5 depthwise conv, register sliding window.
// ---------------------------------------------------------------------------
__global__ void __launch_bounds__(256)
lepe_kernel(const float* __restrict__ w, const float* __restrict__ bias)
{
    const int c  = threadIdx.x;
    const int y  = blockIdx.x;
    const int b  = blockIdx.y;
    const int x0 = blockIdx.z * 12;

    float wr[25];
    #pragma unroll
    for (int t = 0; t < 25; t++) wr[t] = w[t * EMBED + c];
    const float bv = bias[c];

    const float* vb = g_v + (size_t)b * NTOK * EMBED;
    float* ob = g_lepe + (size_t)(b * NTOK + y * WW) * EMBED;

    float win[5][5];
    #pragma unroll
    for (int j = 0; j < 4; j++) {
        const int xx = x0 - 2 + j;
        #pragma unroll
        for (int dy = 0; dy < 5; dy++) {
            const int yy = y + dy - 2;
            win[dy][j] = (xx >= 0 && xx < WW && yy >= 0 && yy < HH)
                       ? vb[(size_t)(yy * WW + xx) * EMBED + c] : 0.f;
        }
    }

    #pragma unroll
    for (int i = 0; i < 12; i++) {
        const int x  = x0 + i;
        const int xx = x + 2;
        #pragma unroll
        for (int dy = 0; dy < 5; dy++) {
            const int yy = y + dy - 2;
            win[dy][4] = (xx < WW && yy >= 0 && yy < HH)
                       ? vb[(size_t)(yy * WW + xx) * EMBED + c] : 0.f;
        }
        float sum = bv;
        #pragma unroll
        for (int dy = 0; dy < 5; dy++)
            #pragma unroll
            for (int j = 0; j < 5; j++)
                sum = fmaf(win[dy][j], wr[dy * 5 + j], sum);
        ob[(size_t)x * EMBED + c] = sum;
        #pragma unroll
        for (int dy = 0; dy < 5; dy++)
            #pragma unroll
            for (int j = 0; j < 4; j++)
                win[dy][j] = win[dy][j + 1];
    }
}

// ---------------------------------------------------------------------------
// Attention v7: no-max softmax (scores bounded ~|4|: exp safe in fp32/fp16),
// deferred l reduction, 1xTF32 QK + fp16 PV with direct fragment pack.
// ---------------------------------------------------------------------------
__global__ void __launch_bounds__(256, 2)
attn_kernel(const float* __restrict__ mask)
{
    __shared__ __align__(16) uint32_t k_s[2][TK * KVSTR];
    __shared__ __align__(16) uint32_t vh_s[2][32 * VHS];

    const int tid  = threadIdx.x;
    const int warp = tid >> 5;
    const int lane = tid & 31;
    const int g    = lane >> 2;
    const int t4   = lane & 3;

    const int b  = blockIdx.x;
    const int q0 = blockIdx.y * TQ;
    const int h  = blockIdx.z;
    const int qw = q0 + warp * 16;

    const float*  Qg = g_q + (size_t)(b * NTOK + qw) * EMBED + h * HD;
    const float*  Kg = g_k + (size_t)b * NTOK * EMBED + h * HD;
    const __half* Vg = g_vh + (size_t)b * NTOK * EMBED + h * HD;
    const float*  Mg = mask + ((size_t)h * NTOK + qw) * NTOK;

    const int lr  = tid >> 2;
    const int lcb = (tid & 3) * 8;
    const int vr  = tid >> 3;
    const int vdc = (tid & 7) * 4;

    const uint32_t ks0 = (uint32_t)__cvta_generic_to_shared(&k_s[0][lr * KVSTR + lcb]);
    const uint32_t kbufstep = (uint32_t)(TK * KVSTR * 4);

    cp16(ks0,      &Kg[(size_t)lr * EMBED + lcb]);
    cp16(ks0 + 16, &Kg[(size_t)lr * EMBED + lcb + 4]);
    asm volatile("cp.async.commit_group;");
    uint2 va = *(const uint2*)&Vg[(size_t)(2 * vr) * EMBED + vdc];
    uint2 vb = *(const uint2*)&Vg[(size_t)(2 * vr + 1) * EMBED + vdc];

    uint32_t qa[4][4];
    #pragma unroll
    for (int kc = 0; kc < 4; kc++) {
        qa[kc][0] = f2tf32(Qg[(size_t)g * EMBED + kc * 8 + t4]);
        qa[kc][1] = f2tf32(Qg[(size_t)(g + 8) * EMBED + kc * 8 + t4]);
        qa[kc][2] = f2tf32(Qg[(size_t)g * EMBED + kc * 8 + t4 + 4]);
        qa[kc][3] = f2tf32(Qg[(size_t)(g + 8) * EMBED + kc * 8 + t4 + 4]);
    }

    float l0r = 0.f, l1r = 0.f;
    float acc[4][4] = {};

    for (int it = 0; it < NKT; it++) {
        const int cur = it & 1;
        asm volatile("cp.async.wait_group 0;");

        {
            uint32_t h0, h1, h2, h3;
            asm("prmt.b32 %0, %1, %2, 0x5410;" : "=r"(h0) : "r"(va.x), "r"(vb.x));
            asm("prmt.b32 %0, %1, %2, 0x7632;" : "=r"(h1) : "r"(va.x), "r"(vb.x));
            asm("prmt.b32 %0, %1, %2, 0x5410;" : "=r"(h2) : "r"(va.y), "r"(vb.y));
            asm("prmt.b32 %0, %1, %2, 0x7632;" : "=r"(h3) : "r"(va.y), "r"(vb.y));
            *(uint4*)&vh_s[cur][vr * VHS + vdc] = make_uint4(h0, h1, h2, h3);
        }
        __syncthreads();

        if (it + 1 < NKT) {
            const size_t go = (size_t)((it + 1) * TK + lr) * EMBED + lcb;
            const uint32_t ks = ks0 + (cur ^ 1) * kbufstep;
            cp16(ks,      &Kg[go]);
            cp16(ks + 16, &Kg[go + 4]);
            asm volatile("cp.async.commit_group;");
            va = *(const uint2*)&Vg[(size_t)((it + 1) * TK + 2 * vr) * EMBED + vdc];
            vb = *(const uint2*)&Vg[(size_t)((it + 1) * TK + 2 * vr + 1) * EMBED + vdc];
        } else {
            asm volatile("cp.async.commit_group;");
        }

        const int k0 = it * TK;

        float2 mA[8], mB[8];
        #pragma unroll
        for (int n0 = 0; n0 < 8; n0++) {
            const float* mrow = Mg + (size_t)g * NTOK + k0 + n0 * 8 + 2 * t4;
            mA[n0] = *(const float2*)mrow;
            mB[n0] = *(const float2*)(mrow + 8 * NTOK);
        }

        float c[8][4] = {};
        const uint32_t* ks = k_s[cur];
        #pragma unroll
        for (int kc = 0; kc < 4; kc++) {
            #pragma unroll
            for (int n0 = 0; n0 < 8; n0++) {
                const int krow = n0 * 8 + g;
                uint32_t bh0 = ks[krow * KVSTR + kc * 8 + t4];
                uint32_t bh1 = ks[krow * KVSTR + kc * 8 + t4 + 4];
                mma_tf32(c[n0][0], c[n0][1], c[n0][2], c[n0][3],
                         qa[kc][0], qa[kc][1], qa[kc][2], qa[kc][3],
                         bh0, bh1);
            }
        }

        // exp(score + mask), no max subtraction; accumulate l locally
        #pragma unroll
        for (int n0 = 0; n0 < 8; n0++) {
            c[n0][0] = __expf(c[n0][0] + mA[n0].x);
            c[n0][1] = __expf(c[n0][1] + mA[n0].y);
            c[n0][2] = __expf(c[n0][2] + mB[n0].x);
            c[n0][3] = __expf(c[n0][3] + mB[n0].y);
            l0r += c[n0][0] + c[n0][1];
            l1r += c[n0][2] + c[n0][3];
        }

        // PV fp16: direct C-frag -> A-frag pack
        const uint32_t* vs = vh_s[cur];
        #pragma unroll
        for (int kc = 0; kc < 4; kc++) {
            uint32_t pa0 = pack_h2(c[2 * kc][0],     c[2 * kc][1]);
            uint32_t pa1 = pack_h2(c[2 * kc][2],     c[2 * kc][3]);
            uint32_t pa2 = pack_h2(c[2 * kc + 1][0], c[2 * kc + 1][1]);
            uint32_t pa3 = pack_h2(c[2 * kc + 1][2], c[2 * kc + 1][3]);
            const int p0 = (8 * kc + t4) * VHS;
            const int p1 = (8 * kc + t4 + 4) * VHS;
            #pragma unroll
            for (int n = 0; n < 4; n++) {
                uint32_t b0 = vs[p0 + n * 8 + g];
                uint32_t b1 = vs[p1 + n * 8 + g];
                mma_f16(acc[n][0], acc[n][1], acc[n][2], acc[n][3],
                        pa0, pa1, pa2, pa3, b0, b1);
            }
        }
    }

    // one-time l reduction across the quad
    l0r += __shfl_xor_sync(0xffffffffu, l0r, 1);
    l0r += __shfl_xor_sync(0xffffffffu, l0r, 2);
    l1r += __shfl_xor_sync(0xffffffffu, l1r, 1);
    l1r += __shfl_xor_sync(0xffffffffu, l1r, 2);

    const float inv0 = 1.0f / l0r;
    const float inv1 = 1.0f / l1r;
    const float* Lg = g_lepe + (size_t)(b * NTOK + qw) * EMBED + h * HD;
    float* Og = g_ao + (size_t)(b * NTOK + qw) * EMBED + h * HD;
    #pragma unroll
    for (int n = 0; n < 4; n++) {
        const int off = n * 8 + 2 * t4;
        float2 lp0 = *(const float2*)&Lg[(size_t)g * EMBED + off];
        float2 lp1 = *(const float2*)&Lg[(size_t)(g + 8) * EMBED + off];
        float2 o0, o1;
        o0.x = __uint_as_float(f2tf32(acc[n][0] * inv0 + lp0.x));
        o0.y = __uint_as_float(f2tf32(acc[n][1] * inv0 + lp0.y));
        o1.x = __uint_as_float(f2tf32(acc[n][2] * inv1 + lp1.x));
        o1.y = __uint_as_float(f2tf32(acc[n][3] * inv1 + lp1.y));
        *(float2*)&Og[(size_t)g * EMBED + off] = o0;
        *(float2*)&Og[(size_t)(g + 8) * EMBED + off] = o1;
    }
}

// ---------------------------------------------------------------------------
extern "C" void kernel_launch(void* const* d_in, const int* in_sizes, int n_in,
                              void* d_out, int out_size)
{
    const float* x      = (const float*)d_in[0];
    const float* sin_t  = (const float*)d_in[1];
    const float* cos_t  = (const float*)d_in[2];
    const float* mask   = (const float*)d_in[3];
    const float* bq     = (const float*)d_in[5];
    const float* bk     = (const float*)d_in[7];
    const float* bv     = (const float*)d_in[9];
    const float* lepe_w = (const float*)d_in[10];
    const float* lepe_b = (const float*)d_in[11];
    const float* bout   = (const float*)d_in[13];
    float* out = (float*)d_out;

    const int M = BATCH * NTOK;   // 9216

    static int smem_set = 0;
    if (!smem_set) {
        cudaFuncSetAttribute(qkv_gemm_t,
            cudaFuncAttributeMaxDynamicSharedMemorySize, GEMM_SMEM);
        cudaFuncSetAttribute(out_gemm_t,
            cudaFuncAttributeMaxDynamicSharedMemorySize, GEMM_SMEM);
        smem_set = 1;
    }

    round_x<<<(M * EMBED / 4) / 256, 256>>>(x);
    round_w<<<dim3((EMBED * EMBED / 4) / 256, 4), 256>>>(
        (const float*)d_in[4], (const float*)d_in[6],
        (const float*)d_in[8], (const float*)d_in[12]);
    qkv_gemm_t<<<dim3(12, M / GBM), 256, GEMM_SMEM>>>(bq, bk, bv, sin_t, cos_t);
    lepe_kernel<<<dim3(HH, BATCH, 4), 256>>>(lepe_w, lepe_b);
    attn_kernel<<<dim3(BATCH, NTOK / TQ, HEADS), 256>>>(mask);
    out_gemm_t<<<dim3(4, M / GBM), 256, GEMM_SMEM>>>(bout, out);
}

// round 10
// speedup vs baseline: 20.9467x; 1.0001x over previous
#include <cuda_runtime.h>
#include <cuda_fp16.h>
#include <cstdint>

#define EMBED 256
#define HEADS 8
#define HD    32
#define NTOK  2304
#define BATCH 4
#define HH    48
#define WW    48
#define KSCALE 0.17677669529663687f  /* 32^-0.5 */

// Tensor GEMM tiling
#define GBM 128
#define GBN 64
#define GBK 32
#define ASTR 36          // A row stride (words): 32 + 4 pad, conflict-free
#define WTSTR 36         // transposed-W row stride (words)
#define GEMM_SMEM ((2 * GBM * ASTR + 2 * GBN * WTSTR) * 4)

// Attention tiling
#define TQ 128
#define TK 64
#define KVSTR 36
#define VHS   40
#define NKT (NTOK / TK)

// round_all partition
#define NXB 2304         // x blocks (float4 path)
#define NWB 1024         // w blocks (transpose path)

// Scratch buffers (allocation-free rule: __device__ globals)
__device__ float  g_xt[BATCH * NTOK * EMBED];
__device__ float  g_wt[4 * EMBED * EMBED];     // tf32-rounded, TRANSPOSED [n][k]
__device__ float  g_q[BATCH * NTOK * EMBED];
__device__ float  g_k[BATCH * NTOK * EMBED];
__device__ float  g_v[BATCH * NTOK * EMBED];
__device__ __half g_vh[BATCH * NTOK * EMBED];
__device__ float  g_lepe[BATCH * NTOK * EMBED];
__device__ float  g_ao[BATCH * NTOK * EMBED];

// ---------------------------------------------------------------------------
// Helpers
// ---------------------------------------------------------------------------
__device__ __forceinline__ uint32_t f2tf32(float x) {
    uint32_t r;
    asm("cvt.rna.tf32.f32 %0, %1;" : "=r"(r) : "f"(x));
    return r;
}

__device__ __forceinline__ uint32_t pack_h2(float lo, float hi) {
    uint32_t r;
    asm("cvt.rn.f16x2.f32 %0, %1, %2;" : "=r"(r) : "f"(hi), "f"(lo));
    return r;
}

__device__ __forceinline__ void mma_tf32(
    float& c0, float& c1, float& c2, float& c3,
    uint32_t a0, uint32_t a1, uint32_t a2, uint32_t a3,
    uint32_t b0, uint32_t b1)
{
    asm("mma.sync.aligned.m16n8k8.row.col.f32.tf32.tf32.f32 "
        "{%0,%1,%2,%3}, {%4,%5,%6,%7}, {%8,%9}, {%0,%1,%2,%3};"
        : "+f"(c0), "+f"(c1), "+f"(c2), "+f"(c3)
        : "r"(a0), "r"(a1), "r"(a2), "r"(a3), "r"(b0), "r"(b1));
}

__device__ __forceinline__ void mma_f16(
    float& c0, float& c1, float& c2, float& c3,
    uint32_t a0, uint32_t a1, uint32_t a2, uint32_t a3,
    uint32_t b0, uint32_t b1)
{
    asm("mma.sync.aligned.m16n8k16.row.col.f32.f16.f16.f32 "
        "{%0,%1,%2,%3}, {%4,%5,%6,%7}, {%8,%9}, {%0,%1,%2,%3};"
        : "+f"(c0), "+f"(c1), "+f"(c2), "+f"(c3)
        : "r"(a0), "r"(a1), "r"(a2), "r"(a3), "r"(b0), "r"(b1));
}

__device__ __forceinline__ void cp16(uint32_t s_addr, const void* g_ptr) {
    asm volatile("cp.async.ca.shared.global [%0], [%1], 16;"
                 :: "r"(s_addr), "l"(g_ptr));
}

__device__ __forceinline__ void ldsm4(
    uint32_t& r0, uint32_t& r1, uint32_t& r2, uint32_t& r3, uint32_t addr)
{
    asm volatile("ldmatrix.sync.aligned.m8n8.x4.shared.b16 {%0,%1,%2,%3}, [%4];"
        : "=r"(r0), "=r"(r1), "=r"(r2), "=r"(r3) : "r"(addr));
}

// ---------------------------------------------------------------------------
// round_all: tf32-round x (float4 path) + tf32-round AND TRANSPOSE weights
// into g_wt[mat][n][k]. One launch.
// ---------------------------------------------------------------------------
__global__ void __launch_bounds__(256)
round_all(const float* __restrict__ x,
          const float* __restrict__ wq, const float* __restrict__ wk,
          const float* __restrict__ wv, const float* __restrict__ wo)
{
    const int bid = blockIdx.x;
    if (bid < NXB) {
        const int i = bid * 256 + threadIdx.x;
        float4 v = ((const float4*)x)[i];
        float4 o;
        o.x = __uint_as_float(f2tf32(v.x));
        o.y = __uint_as_float(f2tf32(v.y));
        o.z = __uint_as_float(f2tf32(v.z));
        o.w = __uint_as_float(f2tf32(v.w));
        ((float4*)g_xt)[i] = o;
    } else {
        const int idx = (bid - NXB) * 256 + threadIdx.x;   // 0..262143
        const int mat = idx >> 16;
        const int rem = idx & 65535;
        const int n   = rem >> 8;
        const int k   = rem & 255;      // consecutive tid -> coalesced store
        const float* src = (mat == 0) ? wq : (mat == 1) ? wk
                         : (mat == 2) ? wv : wo;
        g_wt[(size_t)mat * 65536 + n * 256 + k] =
            __uint_as_float(f2tf32(src[k * 256 + n]));
    }
}

// ---------------------------------------------------------------------------
// TF32 tensor GEMM, ldmatrix fragment loads.
// A [M,256] row-major in smem [128][36]; W transposed [n][k] in smem [64][36].
// Per iter per warp: 4 A-ldmatrix.x4 + 16 B-ldmatrix.x4 + 32 mma.
// mode 0: bias add; 1: q rope; 2: k rope+scale+tf32; 3: v + fp16 copy.
// ---------------------------------------------------------------------------
__device__ __forceinline__ void gemm_t_body(
    const float* __restrict__ A, const float* __restrict__ WT,
    const float* __restrict__ bias, float* __restrict__ C,
    int m0, int n0, int mode,
    const float* __restrict__ sin_t, const float* __restrict__ cos_t,
    __half* __restrict__ Ch)
{
    extern __shared__ __align__(16) uint32_t dynsmem[];
    uint32_t* a_s = dynsmem;                    // [2][GBM*ASTR]
    uint32_t* w_s = dynsmem + 2 * GBM * ASTR;   // [2][GBN*WTSTR]

    const int tid  = threadIdx.x;
    const int warp = tid >> 5;
    const int lane = tid & 31;
    const int g    = lane >> 2;
    const int t4   = lane & 3;
    const int li   = lane & 7;
    const int sub  = lane >> 3;
    const int wrow = warp * 16;

    // ldmatrix lane base addresses (bytes, within buffer 0)
    const uint32_t a_smem0 = (uint32_t)__cvta_generic_to_shared(a_s);
    const uint32_t w_smem0 = (uint32_t)__cvta_generic_to_shared(w_s);
    const uint32_t a_lane = a_smem0 +
        (((wrow + li + (sub & 1) * 8) * ASTR + (sub >> 1) * 4) << 2);
    const uint32_t w_lane = w_smem0 + ((li * WTSTR + sub * 4) << 2);
    const uint32_t ABUF = GBM * ASTR * 4;
    const uint32_t WBUF = GBN * WTSTR * 4;

    float acc[8][4] = {};

    #define GEMM_ISSUE(kt, buf)                                               \
    {                                                                         \
        _Pragma("unroll")                                                     \
        for (int j = 0; j < 4; j++) {                                         \
            const int idx = j * 256 + tid;                                    \
            const int r = idx >> 3, c4 = (idx & 7) << 2;                      \
            cp16(a_smem0 + (buf) * ABUF + ((r * ASTR + c4) << 2),             \
                 &A[(size_t)(m0 + r) * EMBED + (kt) * GBK + c4]);             \
        }                                                                     \
        _Pragma("unroll")                                                     \
        for (int j = 0; j < 2; j++) {                                         \
            const int idx = j * 256 + tid;                                    \
            const int r = idx >> 3, c4 = (idx & 7) << 2;                      \
            cp16(w_smem0 + (buf) * WBUF + ((r * WTSTR + c4) << 2),            \
                 &WT[(size_t)(n0 + r) * EMBED + (kt) * GBK + c4]);            \
        }                                                                     \
        asm volatile("cp.async.commit_group;");                               \
    }

    GEMM_ISSUE(0, 0)

    #pragma unroll 1
    for (int kt = 0; kt < EMBED / GBK; kt++) {
        const int cur = kt & 1;
        asm volatile("cp.async.wait_group 0;");
        __syncthreads();
        if (kt + 1 < EMBED / GBK) GEMM_ISSUE(kt + 1, cur ^ 1)

        const uint32_t ap = a_lane + cur * ABUF;
        const uint32_t wp = w_lane + cur * WBUF;
        #pragma unroll
        for (int kcp = 0; kcp < 2; kcp++) {
            uint32_t aA[4], aB[4];
            ldsm4(aA[0], aA[1], aA[2], aA[3], ap + kcp * 64);
            ldsm4(aB[0], aB[1], aB[2], aB[3], ap + kcp * 64 + 32);
            #pragma unroll
            for (int n = 0; n < 8; n++) {
                uint32_t b[4];
                ldsm4(b[0], b[1], b[2], b[3],
                      wp + n * (8 * WTSTR * 4) + kcp * 64);
                mma_tf32(acc[n][0], acc[n][1], acc[n][2], acc[n][3],
                         aA[0], aA[1], aA[2], aA[3], b[0], b[1]);
                mma_tf32(acc[n][0], acc[n][1], acc[n][2], acc[n][3],
                         aB[0], aB[1], aB[2], aB[3], b[2], b[3]);
            }
        }
    }
    #undef GEMM_ISSUE

    const int row0 = m0 + wrow + g;
    const int row1 = row0 + 8;
    const int pos0 = row0 % NTOK;
    const int pos1 = row1 % NTOK;

    #pragma unroll
    for (int n = 0; n < 8; n++) {
        const int col = n0 + n * 8 + 2 * t4;
        const float b0 = bias[col], b1 = bias[col + 1];
        float e0 = acc[n][0] + b0, o0 = acc[n][1] + b1;
        float e1 = acc[n][2] + b0, o1 = acc[n][3] + b1;

        if (mode == 1 || mode == 2) {
            const int dd = col & (HD - 1);
            float2 cs0 = *(const float2*)&cos_t[pos0 * HD + dd];
            float2 sn0 = *(const float2*)&sin_t[pos0 * HD + dd];
            float2 cs1 = *(const float2*)&cos_t[pos1 * HD + dd];
            float2 sn1 = *(const float2*)&sin_t[pos1 * HD + dd];
            float r0e = e0 * cs0.x - o0 * sn0.x;
            float r0o = o0 * cs0.y + e0 * sn0.y;
            float r1e = e1 * cs1.x - o1 * sn1.x;
            float r1o = o1 * cs1.y + e1 * sn1.y;
            if (mode == 2) {
                r0e = __uint_as_float(f2tf32(r0e * KSCALE));
                r0o = __uint_as_float(f2tf32(r0o * KSCALE));
                r1e = __uint_as_float(f2tf32(r1e * KSCALE));
                r1o = __uint_as_float(f2tf32(r1o * KSCALE));
            }
            e0 = r0e; o0 = r0o; e1 = r1e; o1 = r1o;
        }

        *(float2*)&C[(size_t)row0 * EMBED + col] = make_float2(e0, o0);
        *(float2*)&C[(size_t)row1 * EMBED + col] = make_float2(e1, o1);
        if (mode == 3) {
            *(uint32_t*)&Ch[(size_t)row0 * EMBED + col] = pack_h2(e0, o0);
            *(uint32_t*)&Ch[(size_t)row1 * EMBED + col] = pack_h2(e1, o1);
        }
    }
}

__global__ void __launch_bounds__(256, 2)
qkv_gemm_t(const float* __restrict__ bq, const float* __restrict__ bk,
           const float* __restrict__ bv,
           const float* __restrict__ sin_t, const float* __restrict__ cos_t)
{
    const int m0  = blockIdx.y * GBM;
    const int nb  = blockIdx.x;
    const int mat = nb >> 2;
    const int n0  = (nb & 3) * GBN;

    if (mat == 0)
        gemm_t_body(g_xt, g_wt, bq, g_q, m0, n0, 1, sin_t, cos_t, nullptr);
    else if (mat == 1)
        gemm_t_body(g_xt, g_wt + (size_t)EMBED * EMBED, bk, g_k,
                    m0, n0, 2, sin_t, cos_t, nullptr);
    else
        gemm_t_body(g_xt, g_wt + (size_t)2 * EMBED * EMBED, bv, g_v,
                    m0, n0, 3, nullptr, nullptr, g_vh);
}

__global__ void __launch_bounds__(256, 2)
out_gemm_t(const float* __restrict__ bout, float* __restrict__ out)
{
    gemm_t_body(g_ao, g_wt + (size_t)3 * EMBED * EMBED, bout, out,
                blockIdx.y * GBM, blockIdx.x * GBN, 0,
                nullptr, nullptr, nullptr);
}

// ---------------------------------------------------------------------------
// LePE: 5x5 depthwise conv, register sliding window; 6 x-steps per block.
// ---------------------------------------------------------------------------
__global__ void __launch_bounds__(256)
lepe_kernel(const float* __restrict__ w, const float* __restrict__ bias)
{
    const int c  = threadIdx.x;
    const int y  = blockIdx.x;
    const int b  = blockIdx.y;
    const int x0 = blockIdx.z * 6;

    float wr[25];
    #pragma unroll
    for (int t = 0; t < 25; t++) wr[t] = w[t * EMBED + c];
    const float bv = bias[c];

    const float* vb = g_v + (size_t)b * NTOK * EMBED;
    float* ob = g_lepe + (size_t)(b * NTOK + y * WW) * EMBED;

    float win[5][5];
    #pragma unroll
    for (int j = 0; j < 4; j++) {
        const int xx = x0 - 2 + j;
        #pragma unroll
        for (int dy = 0; dy < 5; dy++) {
            const int yy = y + dy - 2;
            win[dy][j] = (xx >= 0 && xx < WW && yy >= 0 && yy < HH)
                       ? vb[(size_t)(yy * WW + xx) * EMBED + c] : 0.f;
        }
    }

    #pragma unroll
    for (int i = 0; i < 6; i++) {
        const int x  = x0 + i;
        const int xx = x + 2;
        #pragma unroll
        for (int dy = 0; dy < 5; dy++) {
            const int yy = y + dy - 2;
            win[dy][4] = (xx < WW && yy >= 0 && yy < HH)
                       ? vb[(size_t)(yy * WW + xx) * EMBED + c] : 0.f;
        }
        float sum = bv;
        #pragma unroll
        for (int dy = 0; dy < 5; dy++)
            #pragma unroll
            for (int j = 0; j < 5; j++)
                sum = fmaf(win[dy][j], wr[dy * 5 + j], sum);
        ob[(size_t)x * EMBED + c] = sum;
        #pragma unroll
        for (int dy = 0; dy < 5; dy++)
            #pragma unroll
            for (int j = 0; j < 4; j++)
                win[dy][j] = win[dy][j + 1];
    }
}

// ---------------------------------------------------------------------------
// Attention (unchanged from R9): no-max softmax, 1xTF32 QK, fp16 PV.
// ---------------------------------------------------------------------------
__global__ void __launch_bounds__(256, 2)
attn_kernel(const float* __restrict__ mask)
{
    __shared__ __align__(16) uint32_t k_s[2][TK * KVSTR];
    __shared__ __align__(16) uint32_t vh_s[2][32 * VHS];

    const int tid  = threadIdx.x;
    const int warp = tid >> 5;
    const int lane = tid & 31;
    const int g    = lane >> 2;
    const int t4   = lane & 3;

    const int b  = blockIdx.x;
    const int q0 = blockIdx.y * TQ;
    const int h  = blockIdx.z;
    const int qw = q0 + warp * 16;

    const float*  Qg = g_q + (size_t)(b * NTOK + qw) * EMBED + h * HD;
    const float*  Kg = g_k + (size_t)b * NTOK * EMBED + h * HD;
    const __half* Vg = g_vh + (size_t)b * NTOK * EMBED + h * HD;
    const float*  Mg = mask + ((size_t)h * NTOK + qw) * NTOK;

    const int lr  = tid >> 2;
    const int lcb = (tid & 3) * 8;
    const int vr  = tid >> 3;
    const int vdc = (tid & 7) * 4;

    const uint32_t ks0 = (uint32_t)__cvta_generic_to_shared(&k_s[0][lr * KVSTR + lcb]);
    const uint32_t kbufstep = (uint32_t)(TK * KVSTR * 4);

    cp16(ks0,      &Kg[(size_t)lr * EMBED + lcb]);
    cp16(ks0 + 16, &Kg[(size_t)lr * EMBED + lcb + 4]);
    asm volatile("cp.async.commit_group;");
    uint2 va = *(const uint2*)&Vg[(size_t)(2 * vr) * EMBED + vdc];
    uint2 vb = *(const uint2*)&Vg[(size_t)(2 * vr + 1) * EMBED + vdc];

    uint32_t qa[4][4];
    #pragma unroll
    for (int kc = 0; kc < 4; kc++) {
        qa[kc][0] = f2tf32(Qg[(size_t)g * EMBED + kc * 8 + t4]);
        qa[kc][1] = f2tf32(Qg[(size_t)(g + 8) * EMBED + kc * 8 + t4]);
        qa[kc][2] = f2tf32(Qg[(size_t)g * EMBED + kc * 8 + t4 + 4]);
        qa[kc][3] = f2tf32(Qg[(size_t)(g + 8) * EMBED + kc * 8 + t4 + 4]);
    }

    float l0r = 0.f, l1r = 0.f;
    float acc[4][4] = {};

    for (int it = 0; it < NKT; it++) {
        const int cur = it & 1;
        asm volatile("cp.async.wait_group 0;");

        {
            uint32_t h0, h1, h2, h3;
            asm("prmt.b32 %0, %1, %2, 0x5410;" : "=r"(h0) : "r"(va.x), "r"(vb.x));
            asm("prmt.b32 %0, %1, %2, 0x7632;" : "=r"(h1) : "r"(va.x), "r"(vb.x));
            asm("prmt.b32 %0, %1, %2, 0x5410;" : "=r"(h2) : "r"(va.y), "r"(vb.y));
            asm("prmt.b32 %0, %1, %2, 0x7632;" : "=r"(h3) : "r"(va.y), "r"(vb.y));
            *(uint4*)&vh_s[cur][vr * VHS + vdc] = make_uint4(h0, h1, h2, h3);
        }
        __syncthreads();

        if (it + 1 < NKT) {
            const size_t go = (size_t)((it + 1) * TK + lr) * EMBED + lcb;
            const uint32_t ks = ks0 + (cur ^ 1) * kbufstep;
            cp16(ks,      &Kg[go]);
            cp16(ks + 16, &Kg[go + 4]);
            asm volatile("cp.async.commit_group;");
            va = *(const uint2*)&Vg[(size_t)((it + 1) * TK + 2 * vr) * EMBED + vdc];
            vb = *(const uint2*)&Vg[(size_t)((it + 1) * TK + 2 * vr + 1) * EMBED + vdc];
        } else {
            asm volatile("cp.async.commit_group;");
        }

        const int k0 = it * TK;

        float2 mA[8], mB[8];
        #pragma unroll
        for (int n0 = 0; n0 < 8; n0++) {
            const float* mrow = Mg + (size_t)g * NTOK + k0 + n0 * 8 + 2 * t4;
            mA[n0] = *(const float2*)mrow;
            mB[n0] = *(const float2*)(mrow + 8 * NTOK);
        }

        float c[8][4] = {};
        const uint32_t* ks = k_s[cur];
        #pragma unroll
        for (int kc = 0; kc < 4; kc++) {
            #pragma unroll
            for (int n0 = 0; n0 < 8; n0++) {
                const int krow = n0 * 8 + g;
                uint32_t bh0 = ks[krow * KVSTR + kc * 8 + t4];
                uint32_t bh1 = ks[krow * KVSTR + kc * 8 + t4 + 4];
                mma_tf32(c[n0][0], c[n0][1], c[n0][2], c[n0][3],
                         qa[kc][0], qa[kc][1], qa[kc][2], qa[kc][3],
                         bh0, bh1);
            }
        }

        #pragma unroll
        for (int n0 = 0; n0 < 8; n0++) {
            c[n0][0] = __expf(c[n0][0] + mA[n0].x);
            c[n0][1] = __expf(c[n0][1] + mA[n0].y);
            c[n0][2] = __expf(c[n0][2] + mB[n0].x);
            c[n0][3] = __expf(c[n0][3] + mB[n0].y);
            l0r += c[n0][0] + c[n0][1];
            l1r += c[n0][2] + c[n0][3];
        }

        const uint32_t* vs = vh_s[cur];
        #pragma unroll
        for (int kc = 0; kc < 4; kc++) {
            uint32_t pa0 = pack_h2(c[2 * kc][0],     c[2 * kc][1]);
            uint32_t pa1 = pack_h2(c[2 * kc][2],     c[2 * kc][3]);
            uint32_t pa2 = pack_h2(c[2 * kc + 1][0], c[2 * kc + 1][1]);
            uint32_t pa3 = pack_h2(c[2 * kc + 1][2], c[2 * kc + 1][3]);
            const int p0 = (8 * kc + t4) * VHS;
            const int p1 = (8 * kc + t4 + 4) * VHS;
            #pragma unroll
            for (int n = 0; n < 4; n++) {
                uint32_t b0 = vs[p0 + n * 8 + g];
                uint32_t b1 = vs[p1 + n * 8 + g];
                mma_f16(acc[n][0], acc[n][1], acc[n][2], acc[n][3],
                        pa0, pa1, pa2, pa3, b0, b1);
            }
        }
    }

    l0r += __shfl_xor_sync(0xffffffffu, l0r, 1);
    l0r += __shfl_xor_sync(0xffffffffu, l0r, 2);
    l1r += __shfl_xor_sync(0xffffffffu, l1r, 1);
    l1r += __shfl_xor_sync(0xffffffffu, l1r, 2);

    const float inv0 = 1.0f / l0r;
    const float inv1 = 1.0f / l1r;
    const float* Lg = g_lepe + (size_t)(b * NTOK + qw) * EMBED + h * HD;
    float* Og = g_ao + (size_t)(b * NTOK + qw) * EMBED + h * HD;
    #pragma unroll
    for (int n = 0; n < 4; n++) {
        const int off = n * 8 + 2 * t4;
        float2 lp0 = *(const float2*)&Lg[(size_t)g * EMBED + off];
        float2 lp1 = *(const float2*)&Lg[(size_t)(g + 8) * EMBED + off];
        float2 o0, o1;
        o0.x = __uint_as_float(f2tf32(acc[n][0] * inv0 + lp0.x));
        o0.y = __uint_as_float(f2tf32(acc[n][1] * inv0 + lp0.y));
        o1.x = __uint_as_float(f2tf32(acc[n][2] * inv1 + lp1.x));
        o1.y = __uint_as_float(f2tf32(acc[n][3] * inv1 + lp1.y));
        *(float2*)&Og[(size_t)g * EMBED + off] = o0;
        *(float2*)&Og[(size_t)(g + 8) * EMBED + off] = o1;
    }
}

// ---------------------------------------------------------------------------
extern "C" void kernel_launch(void* const* d_in, const int* in_sizes, int n_in,
                              void* d_out, int out_size)
{
    const float* x      = (const float*)d_in[0];
    const float* sin_t  = (const float*)d_in[1];
    const float* cos_t  = (const float*)d_in[2];
    const float* mask   = (const float*)d_in[3];
    const float* bq     = (const float*)d_in[5];
    const float* bk     = (const float*)d_in[7];
    const float* bv     = (const float*)d_in[9];
    const float* lepe_w = (const float*)d_in[10];
    const float* lepe_b = (const float*)d_in[11];
    const float* bout   = (const float*)d_in[13];
    float* out = (float*)d_out;

    const int M = BATCH * NTOK;   // 9216

    static int smem_set = 0;
    if (!smem_set) {
        cudaFuncSetAttribute(qkv_gemm_t,
            cudaFuncAttributeMaxDynamicSharedMemorySize, GEMM_SMEM);
        cudaFuncSetAttribute(out_gemm_t,
            cudaFuncAttributeMaxDynamicSharedMemorySize, GEMM_SMEM);
        smem_set = 1;
    }

    round_all<<<NXB + NWB, 256>>>(x, (const float*)d_in[4],
        (const float*)d_in[6], (const float*)d_in[8], (const float*)d_in[12]);
    qkv_gemm_t<<<dim3(12, M / GBM), 256, GEMM_SMEM>>>(bq, bk, bv, sin_t, cos_t);
    lepe_kernel<<<dim3(HH, BATCH, 8), 256>>>(lepe_w, lepe_b);
    attn_kernel<<<dim3(BATCH, NTOK / TQ, HEADS), 256>>>(mask);
    out_gemm_t<<<dim3(4, M / GBM), 256, GEMM_SMEM>>>(bout, out);
}

// round 12
// speedup vs baseline: 22.5205x; 1.0751x over previous
#include <cuda_runtime.h>
#include <cuda_fp16.h>
#include <cstdint>

#define EMBED 256
#define HEADS 8
#define HD    32
#define NTOK  2304
#define BATCH 4
#define HH    48
#define WW    48
#define KSCALE 0.17677669529663687f  /* 32^-0.5 */

// Tensor GEMM tiling
#define GBM 128
#define GBN 64
#define GBK 32
#define ASTR 36
#define WTSTR 36
#define GEMM_SMEM ((2 * GBM * ASTR + 2 * GBN * WTSTR) * 4)

// Attention tiling
#define TQ 128
#define TK 64
#define KVSTR 36          // K row stride (u32); 36 mod 32 == 4 -> ldmatrix-clean
#define VSTRW 20          // V row stride (u32); 20*r mod 32 covers all banks
#define NST 3             // cp.async ring depth
#define NKT (NTOK / TK)

// round_all partition
#define NXB 2304
#define NWB 1024

// Scratch buffers (allocation-free rule: __device__ globals)
__device__ float  g_xt[BATCH * NTOK * EMBED];
__device__ float  g_wt[4 * EMBED * EMBED];     // tf32-rounded, TRANSPOSED [n][k]
__device__ float  g_q[BATCH * NTOK * EMBED];
__device__ float  g_k[BATCH * NTOK * EMBED];
__device__ float  g_v[BATCH * NTOK * EMBED];
__device__ __half g_vh[BATCH * NTOK * EMBED];
__device__ float  g_lepe[BATCH * NTOK * EMBED];
__device__ float  g_ao[BATCH * NTOK * EMBED];

// ---------------------------------------------------------------------------
// Helpers
// ---------------------------------------------------------------------------
__device__ __forceinline__ uint32_t f2tf32(float x) {
    uint32_t r;
    asm("cvt.rna.tf32.f32 %0, %1;" : "=r"(r) : "f"(x));
    return r;
}

__device__ __forceinline__ uint32_t pack_h2(float lo, float hi) {
    uint32_t r;
    asm("cvt.rn.f16x2.f32 %0, %1, %2;" : "=r"(r) : "f"(hi), "f"(lo));
    return r;
}

__device__ __forceinline__ void mma_tf32(
    float& c0, float& c1, float& c2, float& c3,
    uint32_t a0, uint32_t a1, uint32_t a2, uint32_t a3,
    uint32_t b0, uint32_t b1)
{
    asm("mma.sync.aligned.m16n8k8.row.col.f32.tf32.tf32.f32 "
        "{%0,%1,%2,%3}, {%4,%5,%6,%7}, {%8,%9}, {%0,%1,%2,%3};"
        : "+f"(c0), "+f"(c1), "+f"(c2), "+f"(c3)
        : "r"(a0), "r"(a1), "r"(a2), "r"(a3), "r"(b0), "r"(b1));
}

__device__ __forceinline__ void mma_f16(
    float& c0, float& c1, float& c2, float& c3,
    uint32_t a0, uint32_t a1, uint32_t a2, uint32_t a3,
    uint32_t b0, uint32_t b1)
{
    asm("mma.sync.aligned.m16n8k16.row.col.f32.f16.f16.f32 "
        "{%0,%1,%2,%3}, {%4,%5,%6,%7}, {%8,%9}, {%0,%1,%2,%3};"
        : "+f"(c0), "+f"(c1), "+f"(c2), "+f"(c3)
        : "r"(a0), "r"(a1), "r"(a2), "r"(a3), "r"(b0), "r"(b1));
}

__device__ __forceinline__ void cp16(uint32_t s_addr, const void* g_ptr) {
    asm volatile("cp.async.ca.shared.global [%0], [%1], 16;"
                 :: "r"(s_addr), "l"(g_ptr));
}

__device__ __forceinline__ void ldsm4(
    uint32_t& r0, uint32_t& r1, uint32_t& r2, uint32_t& r3, uint32_t addr)
{
    asm volatile("ldmatrix.sync.aligned.m8n8.x4.shared.b16 {%0,%1,%2,%3}, [%4];"
        : "=r"(r0), "=r"(r1), "=r"(r2), "=r"(r3) : "r"(addr));
}

__device__ __forceinline__ void ldsm4t(
    uint32_t& r0, uint32_t& r1, uint32_t& r2, uint32_t& r3, uint32_t addr)
{
    asm volatile("ldmatrix.sync.aligned.m8n8.x4.trans.shared.b16 {%0,%1,%2,%3}, [%4];"
        : "=r"(r0), "=r"(r1), "=r"(r2), "=r"(r3) : "r"(addr));
}

// ---------------------------------------------------------------------------
// round_all: tf32-round x + tf32-round AND TRANSPOSE weights.
// ---------------------------------------------------------------------------
__global__ void __launch_bounds__(256)
round_all(const float* __restrict__ x,
          const float* __restrict__ wq, const float* __restrict__ wk,
          const float* __restrict__ wv, const float* __restrict__ wo)
{
    const int bid = blockIdx.x;
    if (bid < NXB) {
        const int i = bid * 256 + threadIdx.x;
        float4 v = ((const float4*)x)[i];
        float4 o;
        o.x = __uint_as_float(f2tf32(v.x));
        o.y = __uint_as_float(f2tf32(v.y));
        o.z = __uint_as_float(f2tf32(v.z));
        o.w = __uint_as_float(f2tf32(v.w));
        ((float4*)g_xt)[i] = o;
    } else {
        const int idx = (bid - NXB) * 256 + threadIdx.x;
        const int mat = idx >> 16;
        const int rem = idx & 65535;
        const int n   = rem >> 8;
        const int k   = rem & 255;
        const float* src = (mat == 0) ? wq : (mat == 1) ? wk
                         : (mat == 2) ? wv : wo;
        g_wt[(size_t)mat * 65536 + n * 256 + k] =
            __uint_as_float(f2tf32(src[k * 256 + n]));
    }
}

// ---------------------------------------------------------------------------
// TF32 tensor GEMM (unchanged, passing): ldmatrix fragments.
// ---------------------------------------------------------------------------
__device__ __forceinline__ void gemm_t_body(
    const float* __restrict__ A, const float* __restrict__ WT,
    const float* __restrict__ bias, float* __restrict__ C,
    int m0, int n0, int mode,
    const float* __restrict__ sin_t, const float* __restrict__ cos_t,
    __half* __restrict__ Ch)
{
    extern __shared__ __align__(16) uint32_t dynsmem[];
    uint32_t* a_s = dynsmem;
    uint32_t* w_s = dynsmem + 2 * GBM * ASTR;

    const int tid  = threadIdx.x;
    const int warp = tid >> 5;
    const int lane = tid & 31;
    const int g    = lane >> 2;
    const int t4   = lane & 3;
    const int li   = lane & 7;
    const int sub  = lane >> 3;
    const int wrow = warp * 16;

    const uint32_t a_smem0 = (uint32_t)__cvta_generic_to_shared(a_s);
    const uint32_t w_smem0 = (uint32_t)__cvta_generic_to_shared(w_s);
    const uint32_t a_lane = a_smem0 +
        (((wrow + li + (sub & 1) * 8) * ASTR + (sub >> 1) * 4) << 2);
    const uint32_t w_lane = w_smem0 + ((li * WTSTR + sub * 4) << 2);
    const uint32_t ABUF = GBM * ASTR * 4;
    const uint32_t WBUF = GBN * WTSTR * 4;

    float acc[8][4] = {};

    #define GEMM_ISSUE(kt, buf)                                               \
    {                                                                         \
        _Pragma("unroll")                                                     \
        for (int j = 0; j < 4; j++) {                                         \
            const int idx = j * 256 + tid;                                    \
            const int r = idx >> 3, c4 = (idx & 7) << 2;                      \
            cp16(a_smem0 + (buf) * ABUF + ((r * ASTR + c4) << 2),             \
                 &A[(size_t)(m0 + r) * EMBED + (kt) * GBK + c4]);             \
        }                                                                     \
        _Pragma("unroll")                                                     \
        for (int j = 0; j < 2; j++) {                                         \
            const int idx = j * 256 + tid;                                    \
            const int r = idx >> 3, c4 = (idx & 7) << 2;                      \
            cp16(w_smem0 + (buf) * WBUF + ((r * WTSTR + c4) << 2),            \
                 &WT[(size_t)(n0 + r) * EMBED + (kt) * GBK + c4]);            \
        }                                                                     \
        asm volatile("cp.async.commit_group;");                               \
    }

    GEMM_ISSUE(0, 0)

    #pragma unroll 1
    for (int kt = 0; kt < EMBED / GBK; kt++) {
        const int cur = kt & 1;
        asm volatile("cp.async.wait_group 0;");
        __syncthreads();
        if (kt + 1 < EMBED / GBK) GEMM_ISSUE(kt + 1, cur ^ 1)

        const uint32_t ap = a_lane + cur * ABUF;
        const uint32_t wp = w_lane + cur * WBUF;
        #pragma unroll
        for (int kcp = 0; kcp < 2; kcp++) {
            uint32_t aA[4], aB[4];
            ldsm4(aA[0], aA[1], aA[2], aA[3], ap + kcp * 64);
            ldsm4(aB[0], aB[1], aB[2], aB[3], ap + kcp * 64 + 32);
            #pragma unroll
            for (int n = 0; n < 8; n++) {
                uint32_t b[4];
                ldsm4(b[0], b[1], b[2], b[3],
                      wp + n * (8 * WTSTR * 4) + kcp * 64);
                mma_tf32(acc[n][0], acc[n][1], acc[n][2], acc[n][3],
                         aA[0], aA[1], aA[2], aA[3], b[0], b[1]);
                mma_tf32(acc[n][0], acc[n][1], acc[n][2], acc[n][3],
                         aB[0], aB[1], aB[2], aB[3], b[2], b[3]);
            }
        }
    }
    #undef GEMM_ISSUE

    const int row0 = m0 + wrow + g;
    const int row1 = row0 + 8;
    const int pos0 = row0 % NTOK;
    const int pos1 = row1 % NTOK;

    #pragma unroll
    for (int n = 0; n < 8; n++) {
        const int col = n0 + n * 8 + 2 * t4;
        const float b0 = bias[col], b1 = bias[col + 1];
        float e0 = acc[n][0] + b0, o0 = acc[n][1] + b1;
        float e1 = acc[n][2] + b0, o1 = acc[n][3] + b1;

        if (mode == 1 || mode == 2) {
            const int dd = col & (HD - 1);
            float2 cs0 = *(const float2*)&cos_t[pos0 * HD + dd];
            float2 sn0 = *(const float2*)&sin_t[pos0 * HD + dd];
            float2 cs1 = *(const float2*)&cos_t[pos1 * HD + dd];
            float2 sn1 = *(const float2*)&sin_t[pos1 * HD + dd];
            float r0e = e0 * cs0.x - o0 * sn0.x;
            float r0o = o0 * cs0.y + e0 * sn0.y;
            float r1e = e1 * cs1.x - o1 * sn1.x;
            float r1o = o1 * cs1.y + e1 * sn1.y;
            if (mode == 2) {
                r0e = __uint_as_float(f2tf32(r0e * KSCALE));
                r0o = __uint_as_float(f2tf32(r0o * KSCALE));
                r1e = __uint_as_float(f2tf32(r1e * KSCALE));
                r1o = __uint_as_float(f2tf32(r1o * KSCALE));
            }
            e0 = r0e; o0 = r0o; e1 = r1e; o1 = r1o;
        }

        *(float2*)&C[(size_t)row0 * EMBED + col] = make_float2(e0, o0);
        *(float2*)&C[(size_t)row1 * EMBED + col] = make_float2(e1, o1);
        if (mode == 3) {
            *(uint32_t*)&Ch[(size_t)row0 * EMBED + col] = pack_h2(e0, o0);
            *(uint32_t*)&Ch[(size_t)row1 * EMBED + col] = pack_h2(e1, o1);
        }
    }
}

__global__ void __launch_bounds__(256, 2)
qkv_gemm_t(const float* __restrict__ bq, const float* __restrict__ bk,
           const float* __restrict__ bv,
           const float* __restrict__ sin_t, const float* __restrict__ cos_t)
{
    const int m0  = blockIdx.y * GBM;
    const int nb  = blockIdx.x;
    const int mat = nb >> 2;
    const int n0  = (nb & 3) * GBN;

    if (mat == 0)
        gemm_t_body(g_xt, g_wt, bq, g_q, m0, n0, 1, sin_t, cos_t, nullptr);
    else if (mat == 1)
        gemm_t_body(g_xt, g_wt + (size_t)EMBED * EMBED, bk, g_k,
                    m0, n0, 2, sin_t, cos_t, nullptr);
    else
        gemm_t_body(g_xt, g_wt + (size_t)2 * EMBED * EMBED, bv, g_v,
                    m0, n0, 3, nullptr, nullptr, g_vh);
}

__global__ void __launch_bounds__(256, 2)
out_gemm_t(const float* __restrict__ bout, float* __restrict__ out)
{
    gemm_t_body(g_ao, g_wt + (size_t)3 * EMBED * EMBED, bout, out,
                blockIdx.y * GBM, blockIdx.x * GBN, 0,
                nullptr, nullptr, nullptr);
}

// ---------------------------------------------------------------------------
// LePE: 5x5 depthwise conv, register sliding window.
// ---------------------------------------------------------------------------
__global__ void __launch_bounds__(256)
lepe_kernel(const float* __restrict__ w, const float* __restrict__ bias)
{
    const int c  = threadIdx.x;
    const int y  = blockIdx.x;
    const int b  = blockIdx.y;
    const int x0 = blockIdx.z * 6;

    float wr[25];
    #pragma unroll
    for (int t = 0; t < 25; t++) wr[t] = w[t * EMBED + c];
    const float bv = bias[c];

    const float* vb = g_v + (size_t)b * NTOK * EMBED;
    float* ob = g_lepe + (size_t)(b * NTOK + y * WW) * EMBED;

    float win[5][5];
    #pragma unroll
    for (int j = 0; j < 4; j++) {
        const int xx = x0 - 2 + j;
        #pragma unroll
        for (int dy = 0; dy < 5; dy++) {
            const int yy = y + dy - 2;
            win[dy][j] = (xx >= 0 && xx < WW && yy >= 0 && yy < HH)
                       ? vb[(size_t)(yy * WW + xx) * EMBED + c] : 0.f;
        }
    }

    #pragma unroll
    for (int i = 0; i < 6; i++) {
        const int x  = x0 + i;
        const int xx = x + 2;
        #pragma unroll
        for (int dy = 0; dy < 5; dy++) {
            const int yy = y + dy - 2;
            win[dy][4] = (xx < WW && yy >= 0 && yy < HH)
                       ? vb[(size_t)(yy * WW + xx) * EMBED + c] : 0.f;
        }
        float sum = bv;
        #pragma unroll
        for (int dy = 0; dy < 5; dy++)
            #pragma unroll
            for (int j = 0; j < 5; j++)
                sum = fmaf(win[dy][j], wr[dy * 5 + j], sum);
        ob[(size_t)x * EMBED + c] = sum;
        #pragma unroll
        for (int dy = 0; dy < 5; dy++)
            #pragma unroll
            for (int j = 0; j < 4; j++)
                win[dy][j] = win[dy][j + 1];
    }
}

// ---------------------------------------------------------------------------
// Attention v8: 3-stage cp.async ring (K fp32-tf32 + V fp16 copied verbatim),
// K QK-frags via ldmatrix.x4, V PV-frags via ldmatrix.x4.trans.
// No-max softmax, fp16 PV with direct C->A fragment pack.
// ---------------------------------------------------------------------------
__global__ void __launch_bounds__(256, 2)
attn_kernel(const float* __restrict__ mask)
{
    __shared__ __align__(16) uint32_t k_s[NST][TK * KVSTR];   // 27,648 B
    __shared__ __align__(16) uint32_t v_s[NST][TK * VSTRW];   // 15,360 B

    const int tid  = threadIdx.x;
    const int warp = tid >> 5;
    const int lane = tid & 31;
    const int g    = lane >> 2;
    const int t4   = lane & 3;
    const int li   = lane & 7;
    const int sub  = lane >> 3;

    const int b  = blockIdx.x;
    const int q0 = blockIdx.y * TQ;
    const int h  = blockIdx.z;
    const int qw = q0 + warp * 16;

    const float*  Qg = g_q + (size_t)(b * NTOK + qw) * EMBED + h * HD;
    const float*  Kg = g_k + (size_t)b * NTOK * EMBED + h * HD;
    const __half* Vg = g_vh + (size_t)b * NTOK * EMBED + h * HD;
    const float*  Mg = mask + ((size_t)h * NTOK + qw) * NTOK;

    const int klr  = tid >> 2;
    const int klcb = (tid & 3) * 8;
    const int vlr  = tid >> 2;
    const int vlc8 = (tid & 3) * 8;

    const uint32_t ksm = (uint32_t)__cvta_generic_to_shared(k_s);
    const uint32_t vsm = (uint32_t)__cvta_generic_to_shared(v_s);
    const uint32_t KB = TK * KVSTR * 4;
    const uint32_t VB = TK * VSTRW * 4;

    const uint32_t aK0 = ksm + ((sub >> 1) * 8 + li) * (KVSTR * 4) + (sub & 1) * 16;
    const uint32_t aV0 = vsm + ((sub & 1) * 8 + li) * (VSTRW * 4) + (sub >> 1) * 16;

    #define ATTN_ISSUE(t)                                                     \
    {                                                                         \
        const int _buf = (t) % NST;                                           \
        const size_t kro = (size_t)((t) * TK + klr) * EMBED;                  \
        cp16(ksm + _buf * KB + ((klr * KVSTR + klcb) << 2), &Kg[kro + klcb]); \
        cp16(ksm + _buf * KB + ((klr * KVSTR + klcb) << 2) + 16,              \
             &Kg[kro + klcb + 4]);                                            \
        cp16(vsm + _buf * VB + vlr * (VSTRW * 4) + vlc8 * 2,                  \
             &Vg[(size_t)((t) * TK + vlr) * EMBED + vlc8]);                   \
        asm volatile("cp.async.commit_group;");                               \
    }

    ATTN_ISSUE(0)
    ATTN_ISSUE(1)

    uint32_t qa[4][4];
    #pragma unroll
    for (int kc = 0; kc < 4; kc++) {
        qa[kc][0] = f2tf32(Qg[(size_t)g * EMBED + kc * 8 + t4]);
        qa[kc][1] = f2tf32(Qg[(size_t)(g + 8) * EMBED + kc * 8 + t4]);
        qa[kc][2] = f2tf32(Qg[(size_t)g * EMBED + kc * 8 + t4 + 4]);
        qa[kc][3] = f2tf32(Qg[(size_t)(g + 8) * EMBED + kc * 8 + t4 + 4]);
    }

    float l0r = 0.f, l1r = 0.f;
    float acc[4][4] = {};

    #pragma unroll 1
    for (int it = 0; it < NKT; it++) {
        const int buf = it % NST;
        asm volatile("cp.async.wait_group 1;");
        __syncthreads();

        if (it + 2 < NKT) ATTN_ISSUE(it + 2)
        else asm volatile("cp.async.commit_group;");

        const int k0 = it * TK;

        float2 mA[8], mB[8];
        #pragma unroll
        for (int n0 = 0; n0 < 8; n0++) {
            const float* mrow = Mg + (size_t)g * NTOK + k0 + n0 * 8 + 2 * t4;
            mA[n0] = *(const float2*)mrow;
            mB[n0] = *(const float2*)(mrow + 8 * NTOK);
        }

        float c[8][4] = {};
        const uint32_t aK = aK0 + buf * KB;
        #pragma unroll
        for (int kc = 0; kc < 4; kc++) {
            #pragma unroll
            for (int p = 0; p < 4; p++) {
                uint32_t r0, r1, r2, r3;
                ldsm4(r0, r1, r2, r3, aK + p * (16 * KVSTR * 4) + kc * 32);
                mma_tf32(c[2 * p][0], c[2 * p][1], c[2 * p][2], c[2 * p][3],
                         qa[kc][0], qa[kc][1], qa[kc][2], qa[kc][3], r0, r1);
                mma_tf32(c[2 * p + 1][0], c[2 * p + 1][1],
                         c[2 * p + 1][2], c[2 * p + 1][3],
                         qa[kc][0], qa[kc][1], qa[kc][2], qa[kc][3], r2, r3);
            }
        }

        #pragma unroll
        for (int n0 = 0; n0 < 8; n0++) {
            c[n0][0] = __expf(c[n0][0] + mA[n0].x);
            c[n0][1] = __expf(c[n0][1] + mA[n0].y);
            c[n0][2] = __expf(c[n0][2] + mB[n0].x);
            c[n0][3] = __expf(c[n0][3] + mB[n0].y);
            l0r += c[n0][0] + c[n0][1];
            l1r += c[n0][2] + c[n0][3];
        }

        const uint32_t aV = aV0 + buf * VB;
        #pragma unroll
        for (int kc = 0; kc < 4; kc++) {
            uint32_t pa0 = pack_h2(c[2 * kc][0],     c[2 * kc][1]);
            uint32_t pa1 = pack_h2(c[2 * kc][2],     c[2 * kc][3]);
            uint32_t pa2 = pack_h2(c[2 * kc + 1][0], c[2 * kc + 1][1]);
            uint32_t pa3 = pack_h2(c[2 * kc + 1][2], c[2 * kc + 1][3]);
            #pragma unroll
            for (int ha = 0; ha < 2; ha++) {
                uint32_t r0, r1, r2, r3;
                ldsm4t(r0, r1, r2, r3,
                       aV + kc * (16 * VSTRW * 4) + ha * 32);
                mma_f16(acc[2 * ha][0], acc[2 * ha][1],
                        acc[2 * ha][2], acc[2 * ha][3],
                        pa0, pa1, pa2, pa3, r0, r1);
                mma_f16(acc[2 * ha + 1][0], acc[2 * ha + 1][1],
                        acc[2 * ha + 1][2], acc[2 * ha + 1][3],
                        pa0, pa1, pa2, pa3, r2, r3);
            }
        }
    }
    #undef ATTN_ISSUE

    l0r += __shfl_xor_sync(0xffffffffu, l0r, 1);
    l0r += __shfl_xor_sync(0xffffffffu, l0r, 2);
    l1r += __shfl_xor_sync(0xffffffffu, l1r, 1);
    l1r += __shfl_xor_sync(0xffffffffu, l1r, 2);

    const float inv0 = 1.0f / l0r;
    const float inv1 = 1.0f / l1r;
    const float* Lg = g_lepe + (size_t)(b * NTOK + qw) * EMBED + h * HD;
    float* Og = g_ao + (size_t)(b * NTOK + qw) * EMBED + h * HD;
    #pragma unroll
    for (int n = 0; n < 4; n++) {
        const int off = n * 8 + 2 * t4;
        float2 lp0 = *(const float2*)&Lg[(size_t)g * EMBED + off];
        float2 lp1 = *(const float2*)&Lg[(size_t)(g + 8) * EMBED + off];
        float2 o0, o1;
        o0.x = __uint_as_float(f2tf32(acc[n][0] * inv0 + lp0.x));
        o0.y = __uint_as_float(f2tf32(acc[n][1] * inv0 + lp0.y));
        o1.x = __uint_as_float(f2tf32(acc[n][2] * inv1 + lp1.x));
        o1.y = __uint_as_float(f2tf32(acc[n][3] * inv1 + lp1.y));
        *(float2*)&Og[(size_t)g * EMBED + off] = o0;
        *(float2*)&Og[(size_t)(g + 8) * EMBED + off] = o1;
    }
}

// ---------------------------------------------------------------------------
extern "C" void kernel_launch(void* const* d_in, const int* in_sizes, int n_in,
                              void* d_out, int out_size)
{
    const float* x      = (const float*)d_in[0];
    const float* sin_t  = (const float*)d_in[1];
    const float* cos_t  = (const float*)d_in[2];
    const float* mask   = (const float*)d_in[3];
    const float* bq     = (const float*)d_in[5];
    const float* bk     = (const float*)d_in[7];
    const float* bv     = (const float*)d_in[9];
    const float* lepe_w = (const float*)d_in[10];
    const float* lepe_b = (const float*)d_in[11];
    const float* bout   = (const float*)d_in[13];
    float* out = (float*)d_out;

    const int M = BATCH * NTOK;   // 9216

    static int smem_set = 0;
    if (!smem_set) {
        cudaFuncSetAttribute(qkv_gemm_t,
            cudaFuncAttributeMaxDynamicSharedMemorySize, GEMM_SMEM);
        cudaFuncSetAttribute(out_gemm_t,
            cudaFuncAttributeMaxDynamicSharedMemorySize, GEMM_SMEM);
        smem_set = 1;
    }

    round_all<<<NXB + NWB, 256>>>(x, (const float*)d_in[4],
        (const float*)d_in[6], (const float*)d_in[8], (const float*)d_in[12]);
    qkv_gemm_t<<<dim3(12, M / GBM), 256, GEMM_SMEM>>>(bq, bk, bv, sin_t, cos_t);
    lepe_kernel<<<dim3(HH, BATCH, 8), 256>>>(lepe_w, lepe_b);
    attn_kernel<<<dim3(BATCH, NTOK / TQ, HEADS), 256>>>(mask);
    out_gemm_t<<<dim3(4, M / GBM), 256, GEMM_SMEM>>>(bout, out);
}

// round 13
// speedup vs baseline: 23.9848x; 1.0650x over previous
#include <cuda_runtime.h>
#include <cuda_fp16.h>
#include <cstdint>

#define EMBED 256
#define HEADS 8
#define HD    32
#define NTOK  2304
#define BATCH 4
#define HH    48
#define WW    48
#define KSCALE 0.17677669529663687f  /* 32^-0.5 */
#define LOG2E  1.4426950408889634f

// Tensor GEMM tiling
#define GBM 128
#define GBN 64
#define GBK 32
#define ASTR 36
#define WTSTR 36
#define GEMM_SMEM ((2 * GBM * ASTR + 2 * GBN * WTSTR) * 4)

// Attention tiling
#define TQ 128
#define TK 64
#define KVSTR 36          // K row stride (u32); 36 mod 32 == 4 -> ldmatrix-clean
#define VSTRW 20          // V row stride (u32); 20*r mod 32 covers all banks
#define NST 3             // cp.async ring depth
#define NKT (NTOK / TK)
#define H2_ONES 0x3C003C00u

// round_all partition
#define NXB 2304
#define NWB 1024

// Scratch buffers (allocation-free rule: __device__ globals)
__device__ float  g_xt[BATCH * NTOK * EMBED];
__device__ float  g_wt[4 * EMBED * EMBED];     // tf32-rounded, TRANSPOSED [n][k]
__device__ float  g_q[BATCH * NTOK * EMBED];
__device__ float  g_k[BATCH * NTOK * EMBED];
__device__ float  g_v[BATCH * NTOK * EMBED];
__device__ __half g_vh[BATCH * NTOK * EMBED];
__device__ float  g_lepe[BATCH * NTOK * EMBED];
__device__ float  g_ao[BATCH * NTOK * EMBED];

// ---------------------------------------------------------------------------
// Helpers
// ---------------------------------------------------------------------------
__device__ __forceinline__ uint32_t f2tf32(float x) {
    uint32_t r;
    asm("cvt.rna.tf32.f32 %0, %1;" : "=r"(r) : "f"(x));
    return r;
}

__device__ __forceinline__ uint32_t pack_h2(float lo, float hi) {
    uint32_t r;
    asm("cvt.rn.f16x2.f32 %0, %1, %2;" : "=r"(r) : "f"(hi), "f"(lo));
    return r;
}

__device__ __forceinline__ uint32_t ex2_h2(uint32_t h2) {
    uint32_t r;
    asm("ex2.approx.f16x2 %0, %1;" : "=r"(r) : "r"(h2));
    return r;
}

__device__ __forceinline__ void mma_tf32(
    float& c0, float& c1, float& c2, float& c3,
    uint32_t a0, uint32_t a1, uint32_t a2, uint32_t a3,
    uint32_t b0, uint32_t b1)
{
    asm("mma.sync.aligned.m16n8k8.row.col.f32.tf32.tf32.f32 "
        "{%0,%1,%2,%3}, {%4,%5,%6,%7}, {%8,%9}, {%0,%1,%2,%3};"
        : "+f"(c0), "+f"(c1), "+f"(c2), "+f"(c3)
        : "r"(a0), "r"(a1), "r"(a2), "r"(a3), "r"(b0), "r"(b1));
}

__device__ __forceinline__ void mma_f16(
    float& c0, float& c1, float& c2, float& c3,
    uint32_t a0, uint32_t a1, uint32_t a2, uint32_t a3,
    uint32_t b0, uint32_t b1)
{
    asm("mma.sync.aligned.m16n8k16.row.col.f32.f16.f16.f32 "
        "{%0,%1,%2,%3}, {%4,%5,%6,%7}, {%8,%9}, {%0,%1,%2,%3};"
        : "+f"(c0), "+f"(c1), "+f"(c2), "+f"(c3)
        : "r"(a0), "r"(a1), "r"(a2), "r"(a3), "r"(b0), "r"(b1));
}

__device__ __forceinline__ void cp16(uint32_t s_addr, const void* g_ptr) {
    asm volatile("cp.async.ca.shared.global [%0], [%1], 16;"
                 :: "r"(s_addr), "l"(g_ptr));
}

__device__ __forceinline__ void ldsm4(
    uint32_t& r0, uint32_t& r1, uint32_t& r2, uint32_t& r3, uint32_t addr)
{
    asm volatile("ldmatrix.sync.aligned.m8n8.x4.shared.b16 {%0,%1,%2,%3}, [%4];"
        : "=r"(r0), "=r"(r1), "=r"(r2), "=r"(r3) : "r"(addr));
}

__device__ __forceinline__ void ldsm4t(
    uint32_t& r0, uint32_t& r1, uint32_t& r2, uint32_t& r3, uint32_t addr)
{
    asm volatile("ldmatrix.sync.aligned.m8n8.x4.trans.shared.b16 {%0,%1,%2,%3}, [%4];"
        : "=r"(r0), "=r"(r1), "=r"(r2), "=r"(r3) : "r"(addr));
}

// ---------------------------------------------------------------------------
// round_all: tf32-round x + tf32-round AND TRANSPOSE weights.
// ---------------------------------------------------------------------------
__global__ void __launch_bounds__(256)
round_all(const float* __restrict__ x,
          const float* __restrict__ wq, const float* __restrict__ wk,
          const float* __restrict__ wv, const float* __restrict__ wo)
{
    const int bid = blockIdx.x;
    if (bid < NXB) {
        const int i = bid * 256 + threadIdx.x;
        float4 v = ((const float4*)x)[i];
        float4 o;
        o.x = __uint_as_float(f2tf32(v.x));
        o.y = __uint_as_float(f2tf32(v.y));
        o.z = __uint_as_float(f2tf32(v.z));
        o.w = __uint_as_float(f2tf32(v.w));
        ((float4*)g_xt)[i] = o;
    } else {
        const int idx = (bid - NXB) * 256 + threadIdx.x;
        const int mat = idx >> 16;
        const int rem = idx & 65535;
        const int n   = rem >> 8;
        const int k   = rem & 255;
        const float* src = (mat == 0) ? wq : (mat == 1) ? wk
                         : (mat == 2) ? wv : wo;
        g_wt[(size_t)mat * 65536 + n * 256 + k] =
            __uint_as_float(f2tf32(src[k * 256 + n]));
    }
}

// ---------------------------------------------------------------------------
// TF32 tensor GEMM (unchanged, passing): ldmatrix fragments.
// ---------------------------------------------------------------------------
__device__ __forceinline__ void gemm_t_body(
    const float* __restrict__ A, const float* __restrict__ WT,
    const float* __restrict__ bias, float* __restrict__ C,
    int m0, int n0, int mode,
    const float* __restrict__ sin_t, const float* __restrict__ cos_t,
    __half* __restrict__ Ch)
{
    extern __shared__ __align__(16) uint32_t dynsmem[];
    uint32_t* a_s = dynsmem;
    uint32_t* w_s = dynsmem + 2 * GBM * ASTR;

    const int tid  = threadIdx.x;
    const int warp = tid >> 5;
    const int lane = tid & 31;
    const int g    = lane >> 2;
    const int t4   = lane & 3;
    const int li   = lane & 7;
    const int sub  = lane >> 3;
    const int wrow = warp * 16;

    const uint32_t a_smem0 = (uint32_t)__cvta_generic_to_shared(a_s);
    const uint32_t w_smem0 = (uint32_t)__cvta_generic_to_shared(w_s);
    const uint32_t a_lane = a_smem0 +
        (((wrow + li + (sub & 1) * 8) * ASTR + (sub >> 1) * 4) << 2);
    const uint32_t w_lane = w_smem0 + ((li * WTSTR + sub * 4) << 2);
    const uint32_t ABUF = GBM * ASTR * 4;
    const uint32_t WBUF = GBN * WTSTR * 4;

    float acc[8][4] = {};

    #define GEMM_ISSUE(kt, buf)                                               \
    {                                                                         \
        _Pragma("unroll")                                                     \
        for (int j = 0; j < 4; j++) {                                         \
            const int idx = j * 256 + tid;                                    \
            const int r = idx >> 3, c4 = (idx & 7) << 2;                      \
            cp16(a_smem0 + (buf) * ABUF + ((r * ASTR + c4) << 2),             \
                 &A[(size_t)(m0 + r) * EMBED + (kt) * GBK + c4]);             \
        }                                                                     \
        _Pragma("unroll")                                                     \
        for (int j = 0; j < 2; j++) {                                         \
            const int idx = j * 256 + tid;                                    \
            const int r = idx >> 3, c4 = (idx & 7) << 2;                      \
            cp16(w_smem0 + (buf) * WBUF + ((r * WTSTR + c4) << 2),            \
                 &WT[(size_t)(n0 + r) * EMBED + (kt) * GBK + c4]);            \
        }                                                                     \
        asm volatile("cp.async.commit_group;");                               \
    }

    GEMM_ISSUE(0, 0)

    #pragma unroll 1
    for (int kt = 0; kt < EMBED / GBK; kt++) {
        const int cur = kt & 1;
        asm volatile("cp.async.wait_group 0;");
        __syncthreads();
        if (kt + 1 < EMBED / GBK) GEMM_ISSUE(kt + 1, cur ^ 1)

        const uint32_t ap = a_lane + cur * ABUF;
        const uint32_t wp = w_lane + cur * WBUF;
        #pragma unroll
        for (int kcp = 0; kcp < 2; kcp++) {
            uint32_t aA[4], aB[4];
            ldsm4(aA[0], aA[1], aA[2], aA[3], ap + kcp * 64);
            ldsm4(aB[0], aB[1], aB[2], aB[3], ap + kcp * 64 + 32);
            #pragma unroll
            for (int n = 0; n < 8; n++) {
                uint32_t b[4];
                ldsm4(b[0], b[1], b[2], b[3],
                      wp + n * (8 * WTSTR * 4) + kcp * 64);
                mma_tf32(acc[n][0], acc[n][1], acc[n][2], acc[n][3],
                         aA[0], aA[1], aA[2], aA[3], b[0], b[1]);
                mma_tf32(acc[n][0], acc[n][1], acc[n][2], acc[n][3],
                         aB[0], aB[1], aB[2], aB[3], b[2], b[3]);
            }
        }
    }
    #undef GEMM_ISSUE

    const int row0 = m0 + wrow + g;
    const int row1 = row0 + 8;
    const int pos0 = row0 % NTOK;
    const int pos1 = row1 % NTOK;

    #pragma unroll
    for (int n = 0; n < 8; n++) {
        const int col = n0 + n * 8 + 2 * t4;
        const float b0 = bias[col], b1 = bias[col + 1];
        float e0 = acc[n][0] + b0, o0 = acc[n][1] + b1;
        float e1 = acc[n][2] + b0, o1 = acc[n][3] + b1;

        if (mode == 1 || mode == 2) {
            const int dd = col & (HD - 1);
            float2 cs0 = *(const float2*)&cos_t[pos0 * HD + dd];
            float2 sn0 = *(const float2*)&sin_t[pos0 * HD + dd];
            float2 cs1 = *(const float2*)&cos_t[pos1 * HD + dd];
            float2 sn1 = *(const float2*)&sin_t[pos1 * HD + dd];
            float r0e = e0 * cs0.x - o0 * sn0.x;
            float r0o = o0 * cs0.y + e0 * sn0.y;
            float r1e = e1 * cs1.x - o1 * sn1.x;
            float r1o = o1 * cs1.y + e1 * sn1.y;
            if (mode == 2) {
                r0e = __uint_as_float(f2tf32(r0e * KSCALE));
                r0o = __uint_as_float(f2tf32(r0o * KSCALE));
                r1e = __uint_as_float(f2tf32(r1e * KSCALE));
                r1o = __uint_as_float(f2tf32(r1o * KSCALE));
            }
            e0 = r0e; o0 = r0o; e1 = r1e; o1 = r1o;
        }

        *(float2*)&C[(size_t)row0 * EMBED + col] = make_float2(e0, o0);
        *(float2*)&C[(size_t)row1 * EMBED + col] = make_float2(e1, o1);
        if (mode == 3) {
            *(uint32_t*)&Ch[(size_t)row0 * EMBED + col] = pack_h2(e0, o0);
            *(uint32_t*)&Ch[(size_t)row1 * EMBED + col] = pack_h2(e1, o1);
        }
    }
}

__global__ void __launch_bounds__(256, 2)
qkv_gemm_t(const float* __restrict__ bq, const float* __restrict__ bk,
           const float* __restrict__ bv,
           const float* __restrict__ sin_t, const float* __restrict__ cos_t)
{
    const int m0  = blockIdx.y * GBM;
    const int nb  = blockIdx.x;
    const int mat = nb >> 2;
    const int n0  = (nb & 3) * GBN;

    if (mat == 0)
        gemm_t_body(g_xt, g_wt, bq, g_q, m0, n0, 1, sin_t, cos_t, nullptr);
    else if (mat == 1)
        gemm_t_body(g_xt, g_wt + (size_t)EMBED * EMBED, bk, g_k,
                    m0, n0, 2, sin_t, cos_t, nullptr);
    else
        gemm_t_body(g_xt, g_wt + (size_t)2 * EMBED * EMBED, bv, g_v,
                    m0, n0, 3, nullptr, nullptr, g_vh);
}

__global__ void __launch_bounds__(256, 2)
out_gemm_t(const float* __restrict__ bout, float* __restrict__ out)
{
    gemm_t_body(g_ao, g_wt + (size_t)3 * EMBED * EMBED, bout, out,
                blockIdx.y * GBM, blockIdx.x * GBN, 0,
                nullptr, nullptr, nullptr);
}

// ---------------------------------------------------------------------------
// LePE: 5x5 depthwise conv, register sliding window.
// ---------------------------------------------------------------------------
__global__ void __launch_bounds__(256)
lepe_kernel(const float* __restrict__ w, const float* __restrict__ bias)
{
    const int c  = threadIdx.x;
    const int y  = blockIdx.x;
    const int b  = blockIdx.y;
    const int x0 = blockIdx.z * 6;

    float wr[25];
    #pragma unroll
    for (int t = 0; t < 25; t++) wr[t] = w[t * EMBED + c];
    const float bv = bias[c];

    const float* vb = g_v + (size_t)b * NTOK * EMBED;
    float* ob = g_lepe + (size_t)(b * NTOK + y * WW) * EMBED;

    float win[5][5];
    #pragma unroll
    for (int j = 0; j < 4; j++) {
        const int xx = x0 - 2 + j;
        #pragma unroll
        for (int dy = 0; dy < 5; dy++) {
            const int yy = y + dy - 2;
            win[dy][j] = (xx >= 0 && xx < WW && yy >= 0 && yy < HH)
                       ? vb[(size_t)(yy * WW + xx) * EMBED + c] : 0.f;
        }
    }

    #pragma unroll
    for (int i = 0; i < 6; i++) {
        const int x  = x0 + i;
        const int xx = x + 2;
        #pragma unroll
        for (int dy = 0; dy < 5; dy++) {
            const int yy = y + dy - 2;
            win[dy][4] = (xx < WW && yy >= 0 && yy < HH)
                       ? vb[(size_t)(yy * WW + xx) * EMBED + c] : 0.f;
        }
        float sum = bv;
        #pragma unroll
        for (int dy = 0; dy < 5; dy++)
            #pragma unroll
            for (int j = 0; j < 5; j++)
                sum = fmaf(win[dy][j], wr[dy * 5 + j], sum);
        ob[(size_t)x * EMBED + c] = sum;
        #pragma unroll
        for (int dy = 0; dy < 5; dy++)
            #pragma unroll
            for (int j = 0; j < 4; j++)
                win[dy][j] = win[dy][j + 1];
    }
}

// ---------------------------------------------------------------------------
// Attention v9: base-2 softmax on fp16x2 (Q pre-scaled by log2e; mask folded
// via FFMA; ex2.approx.f16x2 -> P frags directly), l accumulated on the
// tensor pipe via a ones-column mma (no scalar l chain, no end shuffles).
// 3-stage cp.async ring; K ldmatrix; V ldmatrix.trans.
// ---------------------------------------------------------------------------
__global__ void __launch_bounds__(256, 2)
attn_kernel(const float* __restrict__ mask)
{
    __shared__ __align__(16) uint32_t k_s[NST][TK * KVSTR];
    __shared__ __align__(16) uint32_t v_s[NST][TK * VSTRW];

    const int tid  = threadIdx.x;
    const int warp = tid >> 5;
    const int lane = tid & 31;
    const int g    = lane >> 2;
    const int t4   = lane & 3;
    const int li   = lane & 7;
    const int sub  = lane >> 3;

    const int b  = blockIdx.x;
    const int q0 = blockIdx.y * TQ;
    const int h  = blockIdx.z;
    const int qw = q0 + warp * 16;

    const float*  Qg = g_q + (size_t)(b * NTOK + qw) * EMBED + h * HD;
    const float*  Kg = g_k + (size_t)b * NTOK * EMBED + h * HD;
    const __half* Vg = g_vh + (size_t)b * NTOK * EMBED + h * HD;
    const float*  Mg = mask + ((size_t)h * NTOK + qw) * NTOK;

    const int klr  = tid >> 2;
    const int klcb = (tid & 3) * 8;
    const int vlr  = tid >> 2;
    const int vlc8 = (tid & 3) * 8;

    const uint32_t ksm = (uint32_t)__cvta_generic_to_shared(k_s);
    const uint32_t vsm = (uint32_t)__cvta_generic_to_shared(v_s);
    const uint32_t KB = TK * KVSTR * 4;
    const uint32_t VB = TK * VSTRW * 4;

    const uint32_t aK0 = ksm + ((sub >> 1) * 8 + li) * (KVSTR * 4) + (sub & 1) * 16;
    const uint32_t aV0 = vsm + ((sub & 1) * 8 + li) * (VSTRW * 4) + (sub >> 1) * 16;

    #define ATTN_ISSUE(t)                                                     \
    {                                                                         \
        const int _buf = (t) % NST;                                           \
        const size_t kro = (size_t)((t) * TK + klr) * EMBED;                  \
        cp16(ksm + _buf * KB + ((klr * KVSTR + klcb) << 2), &Kg[kro + klcb]); \
        cp16(ksm + _buf * KB + ((klr * KVSTR + klcb) << 2) + 16,              \
             &Kg[kro + klcb + 4]);                                            \
        cp16(vsm + _buf * VB + vlr * (VSTRW * 4) + vlc8 * 2,                  \
             &Vg[(size_t)((t) * TK + vlr) * EMBED + vlc8]);                   \
        asm volatile("cp.async.commit_group;");                               \
    }

    ATTN_ISSUE(0)
    ATTN_ISSUE(1)

    // Q fragments pre-scaled by log2(e): QK outputs are base-2 exponents
    uint32_t qa[4][4];
    #pragma unroll
    for (int kc = 0; kc < 4; kc++) {
        qa[kc][0] = f2tf32(LOG2E * Qg[(size_t)g * EMBED + kc * 8 + t4]);
        qa[kc][1] = f2tf32(LOG2E * Qg[(size_t)(g + 8) * EMBED + kc * 8 + t4]);
        qa[kc][2] = f2tf32(LOG2E * Qg[(size_t)g * EMBED + kc * 8 + t4 + 4]);
        qa[kc][3] = f2tf32(LOG2E * Qg[(size_t)(g + 8) * EMBED + kc * 8 + t4 + 4]);
    }

    float acc[4][4] = {};
    float lacc[4] = {};   // ones-column mma accumulator: [0]=l(row g), [2]=l(row g+8)

    #pragma unroll 1
    for (int it = 0; it < NKT; it++) {
        const int buf = it % NST;
        asm volatile("cp.async.wait_group 1;");
        __syncthreads();

        if (it + 2 < NKT) ATTN_ISSUE(it + 2)
        else asm volatile("cp.async.commit_group;");

        const int k0 = it * TK;

        float2 mA[8], mB[8];
        #pragma unroll
        for (int n0 = 0; n0 < 8; n0++) {
            const float* mrow = Mg + (size_t)g * NTOK + k0 + n0 * 8 + 2 * t4;
            mA[n0] = *(const float2*)mrow;
            mB[n0] = *(const float2*)(mrow + 8 * NTOK);
        }

        // ---- QK^T (outputs already x log2e) ----
        float c[8][4] = {};
        const uint32_t aK = aK0 + buf * KB;
        #pragma unroll
        for (int kc = 0; kc < 4; kc++) {
            #pragma unroll
            for (int p = 0; p < 4; p++) {
                uint32_t r0, r1, r2, r3;
                ldsm4(r0, r1, r2, r3, aK + p * (16 * KVSTR * 4) + kc * 32);
                mma_tf32(c[2 * p][0], c[2 * p][1], c[2 * p][2], c[2 * p][3],
                         qa[kc][0], qa[kc][1], qa[kc][2], qa[kc][3], r0, r1);
                mma_tf32(c[2 * p + 1][0], c[2 * p + 1][1],
                         c[2 * p + 1][2], c[2 * p + 1][3],
                         qa[kc][0], qa[kc][1], qa[kc][2], qa[kc][3], r2, r3);
            }
        }

        // ---- P = 2^(c + mask*log2e), computed in fp16x2 ----
        uint32_t ph[8][2];
        #pragma unroll
        for (int n0 = 0; n0 < 8; n0++) {
            float t0 = fmaf(mA[n0].x, LOG2E, c[n0][0]);
            float t1 = fmaf(mA[n0].y, LOG2E, c[n0][1]);
            float t2 = fmaf(mB[n0].x, LOG2E, c[n0][2]);
            float t3 = fmaf(mB[n0].y, LOG2E, c[n0][3]);
            ph[n0][0] = ex2_h2(pack_h2(t0, t1));   // row g,   keys 2t4,2t4+1
            ph[n0][1] = ex2_h2(pack_h2(t2, t3));   // row g+8
        }

        // ---- PV fp16 + ones-column l mma ----
        const uint32_t aV = aV0 + buf * VB;
        #pragma unroll
        for (int kc = 0; kc < 4; kc++) {
            const uint32_t pa0 = ph[2 * kc][0];
            const uint32_t pa1 = ph[2 * kc][1];
            const uint32_t pa2 = ph[2 * kc + 1][0];
            const uint32_t pa3 = ph[2 * kc + 1][1];
            #pragma unroll
            for (int ha = 0; ha < 2; ha++) {
                uint32_t r0, r1, r2, r3;
                ldsm4t(r0, r1, r2, r3,
                       aV + kc * (16 * VSTRW * 4) + ha * 32);
                mma_f16(acc[2 * ha][0], acc[2 * ha][1],
                        acc[2 * ha][2], acc[2 * ha][3],
                        pa0, pa1, pa2, pa3, r0, r1);
                mma_f16(acc[2 * ha + 1][0], acc[2 * ha + 1][1],
                        acc[2 * ha + 1][2], acc[2 * ha + 1][3],
                        pa0, pa1, pa2, pa3, r2, r3);
            }
            mma_f16(lacc[0], lacc[1], lacc[2], lacc[3],
                    pa0, pa1, pa2, pa3, H2_ONES, H2_ONES);
        }
    }
    #undef ATTN_ISSUE

    const float inv0 = 1.0f / lacc[0];
    const float inv1 = 1.0f / lacc[2];
    const float* Lg = g_lepe + (size_t)(b * NTOK + qw) * EMBED + h * HD;
    float* Og = g_ao + (size_t)(b * NTOK + qw) * EMBED + h * HD;
    #pragma unroll
    for (int n = 0; n < 4; n++) {
        const int off = n * 8 + 2 * t4;
        float2 lp0 = *(const float2*)&Lg[(size_t)g * EMBED + off];
        float2 lp1 = *(const float2*)&Lg[(size_t)(g + 8) * EMBED + off];
        float2 o0, o1;
        o0.x = __uint_as_float(f2tf32(acc[n][0] * inv0 + lp0.x));
        o0.y = __uint_as_float(f2tf32(acc[n][1] * inv0 + lp0.y));
        o1.x = __uint_as_float(f2tf32(acc[n][2] * inv1 + lp1.x));
        o1.y = __uint_as_float(f2tf32(acc[n][3] * inv1 + lp1.y));
        *(float2*)&Og[(size_t)g * EMBED + off] = o0;
        *(float2*)&Og[(size_t)(g + 8) * EMBED + off] = o1;
    }
}

// ---------------------------------------------------------------------------
extern "C" void kernel_launch(void* const* d_in, const int* in_sizes, int n_in,
                              void* d_out, int out_size)
{
    const float* x      = (const float*)d_in[0];
    const float* sin_t  = (const float*)d_in[1];
    const float* cos_t  = (const float*)d_in[2];
    const float* mask   = (const float*)d_in[3];
    const float* bq     = (const float*)d_in[5];
    const float* bk     = (const float*)d_in[7];
    const float* bv     = (const float*)d_in[9];
    const float* lepe_w = (const float*)d_in[10];
    const float* lepe_b = (const float*)d_in[11];
    const float* bout   = (const float*)d_in[13];
    float* out = (float*)d_out;

    const int M = BATCH * NTOK;   // 9216

    static int smem_set = 0;
    if (!smem_set) {
        cudaFuncSetAttribute(qkv_gemm_t,
            cudaFuncAttributeMaxDynamicSharedMemorySize, GEMM_SMEM);
        cudaFuncSetAttribute(out_gemm_t,
            cudaFuncAttributeMaxDynamicSharedMemorySize, GEMM_SMEM);
        smem_set = 1;
    }

    round_all<<<NXB + NWB, 256>>>(x, (const float*)d_in[4],
        (const float*)d_in[6], (const float*)d_in[8], (const float*)d_in[12]);
    qkv_gemm_t<<<dim3(12, M / GBM), 256, GEMM_SMEM>>>(bq, bk, bv, sin_t, cos_t);
    lepe_kernel<<<dim3(HH, BATCH, 8), 256>>>(lepe_w, lepe_b);
    attn_kernel<<<dim3(BATCH, NTOK / TQ, HEADS), 256>>>(mask);
    out_gemm_t<<<dim3(4, M / GBM), 256, GEMM_SMEM>>>(bout, out);
}

// round 14
// speedup vs baseline: 25.8653x; 1.0784x over previous
#include <cuda_runtime.h>
#include <cuda_fp16.h>
#include <cstdint>

#define EMBED 256
#define HEADS 8
#define HD    32
#define NTOK  2304
#define BATCH 4
#define HH    48
#define WW    48
#define KSCALE 0.17677669529663687f  /* 32^-0.5 */
#define LOG2E  1.4426950408889634f

// Tensor GEMM tiling
#define GBM 128
#define GBN 64
#define GBK 32
#define ASTR 36
#define WTSTR 36
#define GEMM_SMEM ((2 * GBM * ASTR + 2 * GBN * WTSTR) * 4)

// Attention tiling
#define TQ 128
#define TK 64
#define KVH 20            // K/V fp16 tile row stride in u32 (32 halfs + 8 pad)
#define NST 3             // cp.async ring depth
#define NKT (NTOK / TK)
#define H2_ONES 0x3C003C00u

// round_all partition
#define NXB 2304
#define NWB 1024

// Scratch buffers (allocation-free rule: __device__ globals)
__device__ float  g_xt[BATCH * NTOK * EMBED];
__device__ float  g_wt[4 * EMBED * EMBED];     // tf32-rounded, TRANSPOSED [n][k]
__device__ __half g_qh[BATCH * NTOK * EMBED];  // fp16 rope(q)*log2e
__device__ __half g_kh[BATCH * NTOK * EMBED];  // fp16 rope(k)*KSCALE
__device__ float  g_v[BATCH * NTOK * EMBED];   // exact v (for lepe)
__device__ __half g_vh[BATCH * NTOK * EMBED];  // fp16 v (for attn PV)
__device__ float  g_lepe[BATCH * NTOK * EMBED];
__device__ float  g_ao[BATCH * NTOK * EMBED];

// ---------------------------------------------------------------------------
// Helpers
// ---------------------------------------------------------------------------
__device__ __forceinline__ uint32_t f2tf32(float x) {
    uint32_t r;
    asm("cvt.rna.tf32.f32 %0, %1;" : "=r"(r) : "f"(x));
    return r;
}

__device__ __forceinline__ uint32_t pack_h2(float lo, float hi) {
    uint32_t r;
    asm("cvt.rn.f16x2.f32 %0, %1, %2;" : "=r"(r) : "f"(hi), "f"(lo));
    return r;
}

__device__ __forceinline__ uint32_t ex2_h2(uint32_t h2) {
    uint32_t r;
    asm("ex2.approx.f16x2 %0, %1;" : "=r"(r) : "r"(h2));
    return r;
}

__device__ __forceinline__ void mma_tf32(
    float& c0, float& c1, float& c2, float& c3,
    uint32_t a0, uint32_t a1, uint32_t a2, uint32_t a3,
    uint32_t b0, uint32_t b1)
{
    asm("mma.sync.aligned.m16n8k8.row.col.f32.tf32.tf32.f32 "
        "{%0,%1,%2,%3}, {%4,%5,%6,%7}, {%8,%9}, {%0,%1,%2,%3};"
        : "+f"(c0), "+f"(c1), "+f"(c2), "+f"(c3)
        : "r"(a0), "r"(a1), "r"(a2), "r"(a3), "r"(b0), "r"(b1));
}

__device__ __forceinline__ void mma_f16(
    float& c0, float& c1, float& c2, float& c3,
    uint32_t a0, uint32_t a1, uint32_t a2, uint32_t a3,
    uint32_t b0, uint32_t b1)
{
    asm("mma.sync.aligned.m16n8k16.row.col.f32.f16.f16.f32 "
        "{%0,%1,%2,%3}, {%4,%5,%6,%7}, {%8,%9}, {%0,%1,%2,%3};"
        : "+f"(c0), "+f"(c1), "+f"(c2), "+f"(c3)
        : "r"(a0), "r"(a1), "r"(a2), "r"(a3), "r"(b0), "r"(b1));
}

__device__ __forceinline__ void cp16(uint32_t s_addr, const void* g_ptr) {
    asm volatile("cp.async.ca.shared.global [%0], [%1], 16;"
                 :: "r"(s_addr), "l"(g_ptr));
}

__device__ __forceinline__ void ldsm4(
    uint32_t& r0, uint32_t& r1, uint32_t& r2, uint32_t& r3, uint32_t addr)
{
    asm volatile("ldmatrix.sync.aligned.m8n8.x4.shared.b16 {%0,%1,%2,%3}, [%4];"
        : "=r"(r0), "=r"(r1), "=r"(r2), "=r"(r3) : "r"(addr));
}

__device__ __forceinline__ void ldsm4t(
    uint32_t& r0, uint32_t& r1, uint32_t& r2, uint32_t& r3, uint32_t addr)
{
    asm volatile("ldmatrix.sync.aligned.m8n8.x4.trans.shared.b16 {%0,%1,%2,%3}, [%4];"
        : "=r"(r0), "=r"(r1), "=r"(r2), "=r"(r3) : "r"(addr));
}

// ---------------------------------------------------------------------------
// round_all: tf32-round x + tf32-round AND TRANSPOSE weights.
// ---------------------------------------------------------------------------
__global__ void __launch_bounds__(256)
round_all(const float* __restrict__ x,
          const float* __restrict__ wq, const float* __restrict__ wk,
          const float* __restrict__ wv, const float* __restrict__ wo)
{
    const int bid = blockIdx.x;
    if (bid < NXB) {
        const int i = bid * 256 + threadIdx.x;
        float4 v = ((const float4*)x)[i];
        float4 o;
        o.x = __uint_as_float(f2tf32(v.x));
        o.y = __uint_as_float(f2tf32(v.y));
        o.z = __uint_as_float(f2tf32(v.z));
        o.w = __uint_as_float(f2tf32(v.w));
        ((float4*)g_xt)[i] = o;
    } else {
        const int idx = (bid - NXB) * 256 + threadIdx.x;
        const int mat = idx >> 16;
        const int rem = idx & 65535;
        const int n   = rem >> 8;
        const int k   = rem & 255;
        const float* src = (mat == 0) ? wq : (mat == 1) ? wk
                         : (mat == 2) ? wv : wo;
        g_wt[(size_t)mat * 65536 + n * 256 + k] =
            __uint_as_float(f2tf32(src[k * 256 + n]));
    }
}

// ---------------------------------------------------------------------------
// TF32 tensor GEMM, ldmatrix fragments.
// mode 0: bias -> fp32 C.     mode 1: q rope * log2e -> fp16 Ch only.
// mode 2: k rope * KSCALE -> fp16 Ch only.   mode 3: v -> fp32 C + fp16 Ch.
// ---------------------------------------------------------------------------
__device__ __forceinline__ void gemm_t_body(
    const float* __restrict__ A, const float* __restrict__ WT,
    const float* __restrict__ bias, float* __restrict__ C,
    int m0, int n0, int mode,
    const float* __restrict__ sin_t, const float* __restrict__ cos_t,
    __half* __restrict__ Ch)
{
    extern __shared__ __align__(16) uint32_t dynsmem[];
    uint32_t* a_s = dynsmem;
    uint32_t* w_s = dynsmem + 2 * GBM * ASTR;

    const int tid  = threadIdx.x;
    const int warp = tid >> 5;
    const int lane = tid & 31;
    const int g    = lane >> 2;
    const int t4   = lane & 3;
    const int li   = lane & 7;
    const int sub  = lane >> 3;
    const int wrow = warp * 16;

    const uint32_t a_smem0 = (uint32_t)__cvta_generic_to_shared(a_s);
    const uint32_t w_smem0 = (uint32_t)__cvta_generic_to_shared(w_s);
    const uint32_t a_lane = a_smem0 +
        (((wrow + li + (sub & 1) * 8) * ASTR + (sub >> 1) * 4) << 2);
    const uint32_t w_lane = w_smem0 + ((li * WTSTR + sub * 4) << 2);
    const uint32_t ABUF = GBM * ASTR * 4;
    const uint32_t WBUF = GBN * WTSTR * 4;

    float acc[8][4] = {};

    #define GEMM_ISSUE(kt, buf)                                               \
    {                                                                         \
        _Pragma("unroll")                                                     \
        for (int j = 0; j < 4; j++) {                                         \
            const int idx = j * 256 + tid;                                    \
            const int r = idx >> 3, c4 = (idx & 7) << 2;                      \
            cp16(a_smem0 + (buf) * ABUF + ((r * ASTR + c4) << 2),             \
                 &A[(size_t)(m0 + r) * EMBED + (kt) * GBK + c4]);             \
        }                                                                     \
        _Pragma("unroll")                                                     \
        for (int j = 0; j < 2; j++) {                                         \
            const int idx = j * 256 + tid;                                    \
            const int r = idx >> 3, c4 = (idx & 7) << 2;                      \
            cp16(w_smem0 + (buf) * WBUF + ((r * WTSTR + c4) << 2),            \
                 &WT[(size_t)(n0 + r) * EMBED + (kt) * GBK + c4]);            \
        }                                                                     \
        asm volatile("cp.async.commit_group;");                               \
    }

    GEMM_ISSUE(0, 0)

    #pragma unroll 1
    for (int kt = 0; kt < EMBED / GBK; kt++) {
        const int cur = kt & 1;
        asm volatile("cp.async.wait_group 0;");
        __syncthreads();
        if (kt + 1 < EMBED / GBK) GEMM_ISSUE(kt + 1, cur ^ 1)

        const uint32_t ap = a_lane + cur * ABUF;
        const uint32_t wp = w_lane + cur * WBUF;
        #pragma unroll
        for (int kcp = 0; kcp < 2; kcp++) {
            uint32_t aA[4], aB[4];
            ldsm4(aA[0], aA[1], aA[2], aA[3], ap + kcp * 64);
            ldsm4(aB[0], aB[1], aB[2], aB[3], ap + kcp * 64 + 32);
            #pragma unroll
            for (int n = 0; n < 8; n++) {
                uint32_t b[4];
                ldsm4(b[0], b[1], b[2], b[3],
                      wp + n * (8 * WTSTR * 4) + kcp * 64);
                mma_tf32(acc[n][0], acc[n][1], acc[n][2], acc[n][3],
                         aA[0], aA[1], aA[2], aA[3], b[0], b[1]);
                mma_tf32(acc[n][0], acc[n][1], acc[n][2], acc[n][3],
                         aB[0], aB[1], aB[2], aB[3], b[2], b[3]);
            }
        }
    }
    #undef GEMM_ISSUE

    const int row0 = m0 + wrow + g;
    const int row1 = row0 + 8;
    const int pos0 = row0 % NTOK;
    const int pos1 = row1 % NTOK;

    #pragma unroll
    for (int n = 0; n < 8; n++) {
        const int col = n0 + n * 8 + 2 * t4;
        const float b0 = bias[col], b1 = bias[col + 1];
        float e0 = acc[n][0] + b0, o0 = acc[n][1] + b1;
        float e1 = acc[n][2] + b0, o1 = acc[n][3] + b1;

        if (mode == 1 || mode == 2) {
            const int dd = col & (HD - 1);
            float2 cs0 = *(const float2*)&cos_t[pos0 * HD + dd];
            float2 sn0 = *(const float2*)&sin_t[pos0 * HD + dd];
            float2 cs1 = *(const float2*)&cos_t[pos1 * HD + dd];
            float2 sn1 = *(const float2*)&sin_t[pos1 * HD + dd];
            const float sc = (mode == 1) ? LOG2E : KSCALE;
            float r0e = (e0 * cs0.x - o0 * sn0.x) * sc;
            float r0o = (o0 * cs0.y + e0 * sn0.y) * sc;
            float r1e = (e1 * cs1.x - o1 * sn1.x) * sc;
            float r1o = (o1 * cs1.y + e1 * sn1.y) * sc;
            *(uint32_t*)&Ch[(size_t)row0 * EMBED + col] = pack_h2(r0e, r0o);
            *(uint32_t*)&Ch[(size_t)row1 * EMBED + col] = pack_h2(r1e, r1o);
        } else {
            *(float2*)&C[(size_t)row0 * EMBED + col] = make_float2(e0, o0);
            *(float2*)&C[(size_t)row1 * EMBED + col] = make_float2(e1, o1);
            if (mode == 3) {
                *(uint32_t*)&Ch[(size_t)row0 * EMBED + col] = pack_h2(e0, o0);
                *(uint32_t*)&Ch[(size_t)row1 * EMBED + col] = pack_h2(e1, o1);
            }
        }
    }
}

__global__ void __launch_bounds__(256, 2)
qkv_gemm_t(const float* __restrict__ bq, const float* __restrict__ bk,
           const float* __restrict__ bv,
           const float* __restrict__ sin_t, const float* __restrict__ cos_t)
{
    const int m0  = blockIdx.y * GBM;
    const int nb  = blockIdx.x;
    const int mat = nb >> 2;
    const int n0  = (nb & 3) * GBN;

    if (mat == 0)
        gemm_t_body(g_xt, g_wt, bq, nullptr, m0, n0, 1, sin_t, cos_t, g_qh);
    else if (mat == 1)
        gemm_t_body(g_xt, g_wt + (size_t)EMBED * EMBED, bk, nullptr,
                    m0, n0, 2, sin_t, cos_t, g_kh);
    else
        gemm_t_body(g_xt, g_wt + (size_t)2 * EMBED * EMBED, bv, g_v,
                    m0, n0, 3, nullptr, nullptr, g_vh);
}

__global__ void __launch_bounds__(256, 2)
out_gemm_t(const float* __restrict__ bout, float* __restrict__ out)
{
    gemm_t_body(g_ao, g_wt + (size_t)3 * EMBED * EMBED, bout, out,
                blockIdx.y * GBM, blockIdx.x * GBN, 0,
                nullptr, nullptr, nullptr);
}

// ---------------------------------------------------------------------------
// LePE: 5x5 depthwise conv, register sliding window.
// ---------------------------------------------------------------------------
__global__ void __launch_bounds__(256)
lepe_kernel(const float* __restrict__ w, const float* __restrict__ bias)
{
    const int c  = threadIdx.x;
    const int y  = blockIdx.x;
    const int b  = blockIdx.y;
    const int x0 = blockIdx.z * 6;

    float wr[25];
    #pragma unroll
    for (int t = 0; t < 25; t++) wr[t] = w[t * EMBED + c];
    const float bv = bias[c];

    const float* vb = g_v + (size_t)b * NTOK * EMBED;
    float* ob = g_lepe + (size_t)(b * NTOK + y * WW) * EMBED;

    float win[5][5];
    #pragma unroll
    for (int j = 0; j < 4; j++) {
        const int xx = x0 - 2 + j;
        #pragma unroll
        for (int dy = 0; dy < 5; dy++) {
            const int yy = y + dy - 2;
            win[dy][j] = (xx >= 0 && xx < WW && yy >= 0 && yy < HH)
                       ? vb[(size_t)(yy * WW + xx) * EMBED + c] : 0.f;
        }
    }

    #pragma unroll
    for (int i = 0; i < 6; i++) {
        const int x  = x0 + i;
        const int xx = x + 2;
        #pragma unroll
        for (int dy = 0; dy < 5; dy++) {
            const int yy = y + dy - 2;
            win[dy][4] = (xx < WW && yy >= 0 && yy < HH)
                       ? vb[(size_t)(yy * WW + xx) * EMBED + c] : 0.f;
        }
        float sum = bv;
        #pragma unroll
        for (int dy = 0; dy < 5; dy++)
            #pragma unroll
            for (int j = 0; j < 5; j++)
                sum = fmaf(win[dy][j], wr[dy * 5 + j], sum);
        ob[(size_t)x * EMBED + c] = sum;
        #pragma unroll
        for (int dy = 0; dy < 5; dy++)
            #pragma unroll
            for (int j = 0; j < 4; j++)
                win[dy][j] = win[dy][j + 1];
    }
}

// ---------------------------------------------------------------------------
// Attention v10: all-fp16 operands. QK in m16n8k16 fp16 (Q pre-scaled by
// log2e in GEMM epilogue; K pre-scaled by KSCALE). K/V tiles share one fp16
// format (64x32, stride 20 words); K frags via ldmatrix.x4 (B-layout match),
// V frags via ldmatrix.x4.trans. Base-2 softmax on fp16x2, l via ones-mma.
// ---------------------------------------------------------------------------
__global__ void __launch_bounds__(256, 2)
attn_kernel(const float* __restrict__ mask)
{
    __shared__ __align__(16) uint32_t k_s[NST][TK * KVH];   // 15,360 B
    __shared__ __align__(16) uint32_t v_s[NST][TK * KVH];   // 15,360 B

    const int tid  = threadIdx.x;
    const int warp = tid >> 5;
    const int lane = tid & 31;
    const int g    = lane >> 2;
    const int t4   = lane & 3;
    const int li   = lane & 7;
    const int sub  = lane >> 3;

    const int b  = blockIdx.x;
    const int q0 = blockIdx.y * TQ;
    const int h  = blockIdx.z;
    const int qw = q0 + warp * 16;

    const __half* Qg = g_qh + (size_t)(b * NTOK + qw) * EMBED + h * HD;
    const __half* Kg = g_kh + (size_t)b * NTOK * EMBED + h * HD;
    const __half* Vg = g_vh + (size_t)b * NTOK * EMBED + h * HD;
    const float*  Mg = mask + ((size_t)h * NTOK + qw) * NTOK;

    const int lr  = tid >> 2;            // tile row 0..63
    const int lc8 = (tid & 3) * 8;       // half chunk (8 halfs = 16B)

    const uint32_t ksm = (uint32_t)__cvta_generic_to_shared(k_s);
    const uint32_t vsm = (uint32_t)__cvta_generic_to_shared(v_s);
    const uint32_t TB = TK * KVH * 4;    // 5120 per buffer

    // K (non-trans, B-frag): matrix rows = keys; m0/m1 = keys p16+0..7 dims
    // lo/hi, m2/m3 = keys p16+8..15 lo/hi.
    const uint32_t aK0 = ksm + ((sub >> 1) * 8 + li) * (KVH * 4) + (sub & 1) * 16;
    // V (trans): rows = tokens; m0/m1 = token halves, m2/m3 next dim block.
    const uint32_t aV0 = vsm + ((sub & 1) * 8 + li) * (KVH * 4) + (sub >> 1) * 16;

    #define ATTN_ISSUE(t)                                                     \
    {                                                                         \
        const int _buf = (t) % NST;                                           \
        const size_t ro = (size_t)((t) * TK + lr) * EMBED + lc8;              \
        cp16(ksm + _buf * TB + lr * (KVH * 4) + lc8 * 2, &Kg[ro]);            \
        cp16(vsm + _buf * TB + lr * (KVH * 4) + lc8 * 2, &Vg[ro]);            \
        asm volatile("cp.async.commit_group;");                               \
    }

    ATTN_ISSUE(0)
    ATTN_ISSUE(1)

    // Q fragments (fp16, pre-scaled by log2e): 2 k-chunks x 4 regs
    uint32_t qa[2][4];
    #pragma unroll
    for (int kc = 0; kc < 2; kc++) {
        qa[kc][0] = *(const uint32_t*)&Qg[(size_t)g * EMBED + kc * 16 + 2 * t4];
        qa[kc][1] = *(const uint32_t*)&Qg[(size_t)(g + 8) * EMBED + kc * 16 + 2 * t4];
        qa[kc][2] = *(const uint32_t*)&Qg[(size_t)g * EMBED + kc * 16 + 2 * t4 + 8];
        qa[kc][3] = *(const uint32_t*)&Qg[(size_t)(g + 8) * EMBED + kc * 16 + 2 * t4 + 8];
    }

    float acc[4][4] = {};
    float lacc[4] = {};

    #pragma unroll 1
    for (int it = 0; it < NKT; it++) {
        const int buf = it % NST;
        asm volatile("cp.async.wait_group 1;");
        __syncthreads();

        if (it + 2 < NKT) ATTN_ISSUE(it + 2)
        else asm volatile("cp.async.commit_group;");

        const int k0 = it * TK;

        float2 mA[8], mB[8];
        #pragma unroll
        for (int n0 = 0; n0 < 8; n0++) {
            const float* mrow = Mg + (size_t)g * NTOK + k0 + n0 * 8 + 2 * t4;
            mA[n0] = *(const float2*)mrow;
            mB[n0] = *(const float2*)(mrow + 8 * NTOK);
        }

        // ---- QK^T fp16 (outputs base-2 exponents) ----
        float c[8][4] = {};
        const uint32_t aK = aK0 + buf * TB;
        #pragma unroll
        for (int kc = 0; kc < 2; kc++) {
            #pragma unroll
            for (int p = 0; p < 4; p++) {
                uint32_t r0, r1, r2, r3;
                ldsm4(r0, r1, r2, r3, aK + p * (16 * KVH * 4) + kc * 32);
                mma_f16(c[2 * p][0], c[2 * p][1], c[2 * p][2], c[2 * p][3],
                        qa[kc][0], qa[kc][1], qa[kc][2], qa[kc][3], r0, r1);
                mma_f16(c[2 * p + 1][0], c[2 * p + 1][1],
                        c[2 * p + 1][2], c[2 * p + 1][3],
                        qa[kc][0], qa[kc][1], qa[kc][2], qa[kc][3], r2, r3);
            }
        }

        // ---- P = 2^(c + mask*log2e) in fp16x2 ----
        uint32_t ph[8][2];
        #pragma unroll
        for (int n0 = 0; n0 < 8; n0++) {
            float t0 = fmaf(mA[n0].x, LOG2E, c[n0][0]);
            float t1 = fmaf(mA[n0].y, LOG2E, c[n0][1]);
            float t2 = fmaf(mB[n0].x, LOG2E, c[n0][2]);
            float t3 = fmaf(mB[n0].y, LOG2E, c[n0][3]);
            ph[n0][0] = ex2_h2(pack_h2(t0, t1));
            ph[n0][1] = ex2_h2(pack_h2(t2, t3));
        }

        // ---- PV fp16 + ones-column l mma ----
        const uint32_t aV = aV0 + buf * TB;
        #pragma unroll
        for (int kc = 0; kc < 4; kc++) {
            const uint32_t pa0 = ph[2 * kc][0];
            const uint32_t pa1 = ph[2 * kc][1];
            const uint32_t pa2 = ph[2 * kc + 1][0];
            const uint32_t pa3 = ph[2 * kc + 1][1];
            #pragma unroll
            for (int ha = 0; ha < 2; ha++) {
                uint32_t r0, r1, r2, r3;
                ldsm4t(r0, r1, r2, r3,
                       aV + kc * (16 * KVH * 4) + ha * 32);
                mma_f16(acc[2 * ha][0], acc[2 * ha][1],
                        acc[2 * ha][2], acc[2 * ha][3],
                        pa0, pa1, pa2, pa3, r0, r1);
                mma_f16(acc[2 * ha + 1][0], acc[2 * ha + 1][1],
                        acc[2 * ha + 1][2], acc[2 * ha + 1][3],
                        pa0, pa1, pa2, pa3, r2, r3);
            }
            mma_f16(lacc[0], lacc[1], lacc[2], lacc[3],
                    pa0, pa1, pa2, pa3, H2_ONES, H2_ONES);
        }
    }
    #undef ATTN_ISSUE

    const float inv0 = 1.0f / lacc[0];
    const float inv1 = 1.0f / lacc[2];
    const float* Lg = g_lepe + (size_t)(b * NTOK + qw) * EMBED + h * HD;
    float* Og = g_ao + (size_t)(b * NTOK + qw) * EMBED + h * HD;
    #pragma unroll
    for (int n = 0; n < 4; n++) {
        const int off = n * 8 + 2 * t4;
        float2 lp0 = *(const float2*)&Lg[(size_t)g * EMBED + off];
        float2 lp1 = *(const float2*)&Lg[(size_t)(g + 8) * EMBED + off];
        float2 o0, o1;
        o0.x = __uint_as_float(f2tf32(acc[n][0] * inv0 + lp0.x));
        o0.y = __uint_as_float(f2tf32(acc[n][1] * inv0 + lp0.y));
        o1.x = __uint_as_float(f2tf32(acc[n][2] * inv1 + lp1.x));
        o1.y = __uint_as_float(f2tf32(acc[n][3] * inv1 + lp1.y));
        *(float2*)&Og[(size_t)g * EMBED + off] = o0;
        *(float2*)&Og[(size_t)(g + 8) * EMBED + off] = o1;
    }
}

// ---------------------------------------------------------------------------
extern "C" void kernel_launch(void* const* d_in, const int* in_sizes, int n_in,
                              void* d_out, int out_size)
{
    const float* x      = (const float*)d_in[0];
    const float* sin_t  = (const float*)d_in[1];
    const float* cos_t  = (const float*)d_in[2];
    const float* mask   = (const float*)d_in[3];
    const float* bq     = (const float*)d_in[5];
    const float* bk     = (const float*)d_in[7];
    const float* bv     = (const float*)d_in[9];
    const float* lepe_w = (const float*)d_in[10];
    const float* lepe_b = (const float*)d_in[11];
    const float* bout   = (const float*)d_in[13];
    float* out = (float*)d_out;

    const int M = BATCH * NTOK;   // 9216

    static int smem_set = 0;
    if (!smem_set) {
        cudaFuncSetAttribute(qkv_gemm_t,
            cudaFuncAttributeMaxDynamicSharedMemorySize, GEMM_SMEM);
        cudaFuncSetAttribute(out_gemm_t,
            cudaFuncAttributeMaxDynamicSharedMemorySize, GEMM_SMEM);
        smem_set = 1;
    }

    round_all<<<NXB + NWB, 256>>>(x, (const float*)d_in[4],
        (const float*)d_in[6], (const float*)d_in[8], (const float*)d_in[12]);
    qkv_gemm_t<<<dim3(12, M / GBM), 256, GEMM_SMEM>>>(bq, bk, bv, sin_t, cos_t);
    lepe_kernel<<<dim3(HH, BATCH, 8), 256>>>(lepe_w, lepe_b);
    attn_kernel<<<dim3(BATCH, NTOK / TQ, HEADS), 256>>>(mask);
    out_gemm_t<<<dim3(4, M / GBM), 256, GEMM_SMEM>>>(bout, out);
}